// round 8
// baseline (speedup 1.0000x reference)
#include <cuda_runtime.h>
#include <cuda_bf16.h>
#include <math.h>
#include <stdint.h>

#define BB 4
#define SS 8192
#define EE 1024
#define HH 16
#define DD 64
#define LL 64
#define NCAND 96
#define MROWS (BB * SS)
#define MSZ   ((size_t)MROWS * EE)

// scales: seg0 = Amid(x4096) * Whi(x512); seg1 = Ahi(x16) * Wmid(x131072)
// both products scale 2^21 -> single s32 accumulator, descale 2^-21.
#define SCALE_OUT (1.0f / 2097152.0f)

// ===================== scratch ==============================================
__device__ float g_Q[MSZ];
__device__ float g_K[MSZ];
__device__ float g_ctx[MSZ];
__device__ __nv_bfloat16 g_Ahi[MSZ];          // Q/O activation hi (reused)
__device__ char          g_A8[MSZ * 2];       // Q/O activation int8 segs (reused)
__device__ __nv_bfloat16 g_Akhi[MSZ];         // K activation hi
__device__ __nv_bfloat16 g_Wqhi[EE * EE];
__device__ char          g_Wq8[EE * EE * 2];
__device__ __nv_bfloat16 g_Wkhi[EE * EE];
__device__ __nv_bfloat16 g_Wohi[EE * EE];
__device__ char          g_Wo8[EE * EE * 2];
__device__ float g_scores[BB * SS];
__device__ int   g_idx96[BB * NCAND];
__device__ float g_kex[BB * NCAND * EE];
__device__ float g_vex[BB * NCAND * EE];
__device__ float g_scex[BB * NCAND];
__device__ int   g_idxf[BB * LL];
__device__ int   g_candf[BB * LL];
__device__ float g_Ksp[BB * HH * LL * DD];
__device__ float g_Vsp[BB * HH * LL * DD];

// ===================== small PTX helpers ====================================
__device__ __forceinline__ uint32_t smem_u32(const void* p) {
    uint32_t a;
    asm("{ .reg .u64 t; cvta.to.shared.u64 t, %1; cvt.u32.u64 %0, t; }" : "=r"(a) : "l"(p));
    return a;
}
__device__ __forceinline__ void cp16(uint32_t dst, const void* src) {
    asm volatile("cp.async.cg.shared.global [%0], [%1], 16;" :: "r"(dst), "l"(src));
}
#define CP_COMMIT() asm volatile("cp.async.commit_group;" ::: "memory")
#define CP_WAIT1()  asm volatile("cp.async.wait_group 1;" ::: "memory")
__device__ __forceinline__ void ldm_x4(uint32_t* r, uint32_t addr) {
    asm volatile("ldmatrix.sync.aligned.m8n8.x4.shared.b16 {%0,%1,%2,%3}, [%4];"
                 : "=r"(r[0]), "=r"(r[1]), "=r"(r[2]), "=r"(r[3]) : "r"(addr));
}
#define MMA16816(d, a, b0, b1) \
    asm volatile("mma.sync.aligned.m16n8k16.row.col.f32.bf16.bf16.f32 " \
        "{%0,%1,%2,%3}, {%4,%5,%6,%7}, {%8,%9}, {%0,%1,%2,%3};" \
        : "+f"((d)[0]), "+f"((d)[1]), "+f"((d)[2]), "+f"((d)[3]) \
        : "r"((a)[0]), "r"((a)[1]), "r"((a)[2]), "r"((a)[3]), \
          "r"(b0), "r"(b1))
#define MMAS8(d, a, b0, b1) \
    asm volatile("mma.sync.aligned.m16n8k32.row.col.s32.s8.s8.s32 " \
        "{%0,%1,%2,%3}, {%4,%5,%6,%7}, {%8,%9}, {%0,%1,%2,%3};" \
        : "+r"((d)[0]), "+r"((d)[1]), "+r"((d)[2]), "+r"((d)[3]) \
        : "r"((a)[0]), "r"((a)[1]), "r"((a)[2]), "r"((a)[3]), \
          "r"(b0), "r"(b1))

__device__ __forceinline__ char q8(float v) {
    int t = __float2int_rn(v);
    t = t > 127 ? 127 : (t < -127 ? -127 : t);
    return (char)t;
}

// ===================== quantization kernels =================================
// activations: hi = bf16(x); seg0 = round((x-hi)*4096); seg1 = round(hi*16)
__global__ __launch_bounds__(256) void quant_a(
    const float* __restrict__ x, __nv_bfloat16* __restrict__ hi,
    char* __restrict__ a8, int n4)
{
    int i = blockIdx.x * 256 + threadIdx.x;
    if (i >= n4) return;
    float4 v = ((const float4*)x)[i];
    float vv[4] = {v.x, v.y, v.z, v.w};
    uint32_t hb[4];
    char m8[4], h8[4];
    #pragma unroll
    for (int q = 0; q < 4; q++) {
        __nv_bfloat16 h = __float2bfloat16(vv[q]);
        float hf = __bfloat162float(h);
        hb[q] = (uint32_t)__bfloat16_as_ushort(h);
        m8[q] = q8((vv[q] - hf) * 4096.f);
        h8[q] = q8(hf * 16.f);
    }
    uint2 hp;
    hp.x = hb[0] | (hb[1] << 16); hp.y = hb[2] | (hb[3] << 16);
    ((uint2*)hi)[i] = hp;
    size_t e = (size_t)i * 4;
    size_t row = e >> 10, k = e & 1023;
    *(char4*)(a8 + row * 2048 + k)        = make_char4(m8[0], m8[1], m8[2], m8[3]);
    *(char4*)(a8 + row * 2048 + 1024 + k) = make_char4(h8[0], h8[1], h8[2], h8[3]);
}

// weights: hi = bf16(w); seg0 = round(hi*512); seg1 = round((w-hi)*131072)
__global__ __launch_bounds__(256) void quant_w(
    const float* __restrict__ x, __nv_bfloat16* __restrict__ hi,
    char* __restrict__ w8, int n4)
{
    int i = blockIdx.x * 256 + threadIdx.x;
    if (i >= n4) return;
    float4 v = ((const float4*)x)[i];
    float vv[4] = {v.x, v.y, v.z, v.w};
    uint32_t hb[4];
    char s0[4], s1[4];
    #pragma unroll
    for (int q = 0; q < 4; q++) {
        __nv_bfloat16 h = __float2bfloat16(vv[q]);
        float hf = __bfloat162float(h);
        hb[q] = (uint32_t)__bfloat16_as_ushort(h);
        s0[q] = q8(hf * 512.f);
        s1[q] = q8((vv[q] - hf) * 131072.f);
    }
    uint2 hp;
    hp.x = hb[0] | (hb[1] << 16); hp.y = hb[2] | (hb[3] << 16);
    ((uint2*)hi)[i] = hp;
    size_t e = (size_t)i * 4;
    size_t row = e >> 10, k = e & 1023;
    *(char4*)(w8 + row * 2048 + k)        = make_char4(s0[0], s0[1], s0[2], s0[3]);
    *(char4*)(w8 + row * 2048 + 1024 + k) = make_char4(s1[0], s1[1], s1[2], s1[3]);
}

// hi-only conversion (for key path)
__global__ __launch_bounds__(256) void hi_only(
    const float* __restrict__ x, __nv_bfloat16* __restrict__ hi, int n4)
{
    int i = blockIdx.x * 256 + threadIdx.x;
    if (i >= n4) return;
    float4 v = ((const float4*)x)[i];
    uint32_t h0 = (uint32_t)__bfloat16_as_ushort(__float2bfloat16(v.x));
    uint32_t h1 = (uint32_t)__bfloat16_as_ushort(__float2bfloat16(v.y));
    uint32_t h2 = (uint32_t)__bfloat16_as_ushort(__float2bfloat16(v.z));
    uint32_t h3 = (uint32_t)__bfloat16_as_ushort(__float2bfloat16(v.w));
    uint2 hp; hp.x = h0 | (h1 << 16); hp.y = h2 | (h3 << 16);
    ((uint2*)hi)[i] = hp;
}

// ===================== bf16 GEMM (single product, K=1024) ===================
// BM=128, BN=256, BK=64, 256 thr, warp grid 2x4, warp tile 64x64, 3 stages.
#define GSTAGE 49152u
#define GEMM_SMEM (3 * 49152)

__global__ __launch_bounds__(256) void gemm_bf16(
    const __nv_bfloat16* __restrict__ A, const __nv_bfloat16* __restrict__ W,
    const float* __restrict__ bias, float* __restrict__ C)
{
    extern __shared__ __align__(128) char dsm[];
    const uint32_t sbase = smem_u32(dsm);
    const int tid  = threadIdx.x;
    const int lane = tid & 31;
    const int wid  = tid >> 5;
    const int bm = blockIdx.y * 128;
    const int bn = blockIdx.x * 256;
    const int m0 = (wid & 1) * 64;
    const int n0 = (wid >> 1) * 64;
    const int qrow = lane >> 2;
    const int qk   = (lane & 3) * 2;
    const int lrow  = lane & 7;
    const int phase = lane >> 3;
    const int g_c  = tid & 7;
    const int g_r0 = tid >> 3;

    float c[4][8][4];
    #pragma unroll
    for (int mt = 0; mt < 4; mt++)
        #pragma unroll
        for (int nt = 0; nt < 8; nt++)
            #pragma unroll
            for (int q = 0; q < 4; q++) c[mt][nt][q] = 0.f;

    auto load_tile = [&](int kt) {
        if (kt < 16) {
            const uint32_t sA = sbase + (uint32_t)(kt % 3) * GSTAGE;
            const uint32_t sB = sA + 16384u;
            const int kk = kt << 6;
            #pragma unroll
            for (int i = 0; i < 4; i++) {
                int row = g_r0 + i * 32;
                uint32_t off = (uint32_t)(row * 128 + ((g_c ^ (row & 7)) << 4));
                cp16(sA + off, A + (size_t)(bm + row) * 1024 + kk + g_c * 8);
            }
            #pragma unroll
            for (int i = 0; i < 8; i++) {
                int row = g_r0 + i * 32;
                uint32_t off = (uint32_t)(row * 128 + ((g_c ^ (row & 7)) << 4));
                cp16(sB + off, W + (size_t)(bn + row) * 1024 + kk + g_c * 8);
            }
        }
        CP_COMMIT();
    };

    load_tile(0);
    load_tile(1);

    for (int kt = 0; kt < 16; kt++) {
        CP_WAIT1();
        __syncthreads();
        load_tile(kt + 2);
        const uint32_t aB = sbase + (uint32_t)(kt % 3) * GSTAGE;
        const uint32_t bB = aB + 16384u;
        #pragma unroll
        for (int ks = 0; ks < 4; ks++) {
            const int c0 = ks * 2;
            uint32_t a[4][4];
            #pragma unroll
            for (int mt = 0; mt < 4; mt++) {
                int row = m0 + mt * 16 + (phase & 1) * 8 + lrow;
                int ch  = c0 + (phase >> 1);
                ldm_x4(a[mt], aB + (uint32_t)(row * 128 + ((ch ^ (row & 7)) << 4)));
            }
            uint32_t bf[4][4];
            #pragma unroll
            for (int ng = 0; ng < 4; ng++) {
                int row = n0 + ng * 16 + (phase >> 1) * 8 + lrow;
                int ch  = c0 + (phase & 1);
                ldm_x4(bf[ng], bB + (uint32_t)(row * 128 + ((ch ^ (row & 7)) << 4)));
            }
            #pragma unroll
            for (int nt = 0; nt < 8; nt++) {
                uint32_t b0 = bf[nt >> 1][(nt & 1) * 2];
                uint32_t b1 = bf[nt >> 1][(nt & 1) * 2 + 1];
                #pragma unroll
                for (int mt = 0; mt < 4; mt++)
                    MMA16816(c[mt][nt], a[mt], b0, b1);
            }
        }
        __syncthreads();
    }

    #pragma unroll
    for (int mt = 0; mt < 4; mt++) {
        #pragma unroll
        for (int nt = 0; nt < 8; nt++) {
            int r0  = bm + m0 + mt * 16 + qrow;
            int col = bn + n0 + nt * 8 + qk;
            float2 bv = *(const float2*)(bias + col);
            float2 o0, o1;
            o0.x = c[mt][nt][0] + bv.x; o0.y = c[mt][nt][1] + bv.y;
            o1.x = c[mt][nt][2] + bv.x; o1.y = c[mt][nt][3] + bv.y;
            *(float2*)(C + (size_t)r0 * 1024 + col) = o0;
            *(float2*)(C + (size_t)(r0 + 8) * 1024 + col) = o1;
        }
    }
}

// ===================== int8 cross-term GEMM (K=2048, C += 2^-21 * acc) ======
__global__ __launch_bounds__(256) void gemm_s8(
    const char* __restrict__ A8, const char* __restrict__ W8,
    float* __restrict__ C)
{
    extern __shared__ __align__(128) char dsm[];
    const uint32_t sbase = smem_u32(dsm);
    const int tid  = threadIdx.x;
    const int lane = tid & 31;
    const int wid  = tid >> 5;
    const int bm = blockIdx.y * 128;
    const int bn = blockIdx.x * 256;
    const int m0 = (wid & 1) * 64;
    const int n0 = (wid >> 1) * 64;
    const int qrow = lane >> 2;
    const int qk   = (lane & 3) * 2;
    const int lrow  = lane & 7;
    const int phase = lane >> 3;
    const int g_c  = tid & 7;
    const int g_r0 = tid >> 3;

    int c[4][8][4];
    #pragma unroll
    for (int mt = 0; mt < 4; mt++)
        #pragma unroll
        for (int nt = 0; nt < 8; nt++)
            #pragma unroll
            for (int q = 0; q < 4; q++) c[mt][nt][q] = 0;

    auto load_tile = [&](int kt) {
        if (kt < 16) {
            const uint32_t sA = sbase + (uint32_t)(kt % 3) * GSTAGE;
            const uint32_t sB = sA + 16384u;
            const int kk = kt << 7;             // 128 int8 per tile
            #pragma unroll
            for (int i = 0; i < 4; i++) {
                int row = g_r0 + i * 32;
                uint32_t off = (uint32_t)(row * 128 + ((g_c ^ (row & 7)) << 4));
                cp16(sA + off, A8 + (size_t)(bm + row) * 2048 + kk + g_c * 16);
            }
            #pragma unroll
            for (int i = 0; i < 8; i++) {
                int row = g_r0 + i * 32;
                uint32_t off = (uint32_t)(row * 128 + ((g_c ^ (row & 7)) << 4));
                cp16(sB + off, W8 + (size_t)(bn + row) * 2048 + kk + g_c * 16);
            }
        }
        CP_COMMIT();
    };

    load_tile(0);
    load_tile(1);

    for (int kt = 0; kt < 16; kt++) {
        CP_WAIT1();
        __syncthreads();
        load_tile(kt + 2);
        const uint32_t aB = sbase + (uint32_t)(kt % 3) * GSTAGE;
        const uint32_t bB = aB + 16384u;
        #pragma unroll
        for (int ks = 0; ks < 4; ks++) {
            const int c0 = ks * 2;
            uint32_t a[4][4];
            #pragma unroll
            for (int mt = 0; mt < 4; mt++) {
                int row = m0 + mt * 16 + (phase & 1) * 8 + lrow;
                int ch  = c0 + (phase >> 1);
                ldm_x4(a[mt], aB + (uint32_t)(row * 128 + ((ch ^ (row & 7)) << 4)));
            }
            uint32_t bf[4][4];
            #pragma unroll
            for (int ng = 0; ng < 4; ng++) {
                int row = n0 + ng * 16 + (phase >> 1) * 8 + lrow;
                int ch  = c0 + (phase & 1);
                ldm_x4(bf[ng], bB + (uint32_t)(row * 128 + ((ch ^ (row & 7)) << 4)));
            }
            #pragma unroll
            for (int nt = 0; nt < 8; nt++) {
                uint32_t b0 = bf[nt >> 1][(nt & 1) * 2];
                uint32_t b1 = bf[nt >> 1][(nt & 1) * 2 + 1];
                #pragma unroll
                for (int mt = 0; mt < 4; mt++)
                    MMAS8(c[mt][nt], a[mt], b0, b1);
            }
        }
        __syncthreads();
    }

    #pragma unroll
    for (int mt = 0; mt < 4; mt++) {
        #pragma unroll
        for (int nt = 0; nt < 8; nt++) {
            int r0  = bm + m0 + mt * 16 + qrow;
            int col = bn + n0 + nt * 8 + qk;
            float* p0 = C + (size_t)r0 * 1024 + col;
            float* p1 = C + (size_t)(r0 + 8) * 1024 + col;
            float2 o0 = *(float2*)p0;
            float2 o1 = *(float2*)p1;
            o0.x += (float)c[mt][nt][0] * SCALE_OUT;
            o0.y += (float)c[mt][nt][1] * SCALE_OUT;
            o1.x += (float)c[mt][nt][2] * SCALE_OUT;
            o1.y += (float)c[mt][nt][3] * SCALE_OUT;
            *(float2*)p0 = o0;
            *(float2*)p1 = o1;
        }
    }
}

// ===================== scores[row] = mean_h ||X[row, h*64:+64]|| ============
__global__ __launch_bounds__(256) void scores_kernel(
    const float* __restrict__ Km, float* __restrict__ scores)
{
    int row  = blockIdx.x * 8 + (threadIdx.x >> 5);
    int lane = threadIdx.x & 31;
    const float* kr = Km + (size_t)row * EE;
    float acc = 0.f;
    #pragma unroll
    for (int h = 0; h < HH; h++) {
        float x0 = kr[h * 64 + lane];
        float x1 = kr[h * 64 + 32 + lane];
        float ss = x0 * x0 + x1 * x1;
        #pragma unroll
        for (int o = 16; o > 0; o >>= 1)
            ss += __shfl_xor_sync(0xffffffffu, ss, o);
        acc += sqrtf(ss);
    }
    if (lane == 0) scores[row] = acc * (1.f / 16.f);
}

// ===================== approx top-kk per batch ===============================
__global__ __launch_bounds__(1024) void topk_kernel(
    const float* __restrict__ scores, int* __restrict__ idxout, int kk)
{
    __shared__ float sv[SS];
    __shared__ float rv[1024];
    __shared__ int   ri[1024];
    const int b = blockIdx.x, t = threadIdx.x;
    for (int i = t; i < SS; i += 1024) sv[i] = scores[b * SS + i];
    __syncthreads();
    for (int l = 0; l < kk; l++) {
        float m = -INFINITY; int a = 0;
        #pragma unroll
        for (int u = 0; u < 8; u++) {
            int i = t + u * 1024;
            float v = sv[i];
            if (v > m) { m = v; a = i; }
        }
        rv[t] = m; ri[t] = a;
        __syncthreads();
        for (int s = 512; s > 0; s >>= 1) {
            if (t < s) {
                float v2 = rv[t + s]; int a2 = ri[t + s];
                if (v2 > rv[t] || (v2 == rv[t] && a2 < ri[t])) { rv[t] = v2; ri[t] = a2; }
            }
            __syncthreads();
        }
        if (t == 0) { idxout[b * kk + l] = ri[0]; sv[ri[0]] = -INFINITY; }
        __syncthreads();
    }
}

// ===================== exact fp32 projection of candidate rows ==============
template<int CPT>
__global__ __launch_bounds__(256) void project_rows(
    const float* __restrict__ X, const float* __restrict__ Wt,
    const float* __restrict__ bias, const int* __restrict__ idx,
    int ncand, float* __restrict__ outp)
{
    __shared__ float xs[NCAND * 32];
    __shared__ float ws[32 * 128];
    const int b = blockIdx.y;
    const int e0 = blockIdx.x * 128;
    const int t = threadIdx.x, tx = t & 31, ty = t >> 5;

    float acc[CPT][4];
    #pragma unroll
    for (int c = 0; c < CPT; c++)
        #pragma unroll
        for (int j = 0; j < 4; j++) acc[c][j] = 0.f;

    for (int kt = 0; kt < EE; kt += 32) {
        __syncthreads();
        for (int u = t; u < ncand * 8; u += 256) {
            int cand = u >> 3, c4 = u & 7;
            int s = idx[b * ncand + cand];
            float4 v = *(const float4*)(X + ((size_t)(b * SS + s)) * EE + kt + c4 * 4);
            *(float4*)(xs + cand * 32 + c4 * 4) = v;
        }
        for (int u = t; u < 1024; u += 256) {
            int e = u >> 3, c4 = u & 7;
            float4 v = *(const float4*)(Wt + (size_t)(e0 + e) * EE + kt + c4 * 4);
            ws[(c4 * 4 + 0) * 128 + e] = v.x;
            ws[(c4 * 4 + 1) * 128 + e] = v.y;
            ws[(c4 * 4 + 2) * 128 + e] = v.z;
            ws[(c4 * 4 + 3) * 128 + e] = v.w;
        }
        __syncthreads();
        #pragma unroll 8
        for (int k = 0; k < 32; k++) {
            float wv[4];
            #pragma unroll
            for (int j = 0; j < 4; j++) wv[j] = ws[k * 128 + tx * 4 + j];
            #pragma unroll
            for (int c = 0; c < CPT; c++) {
                float a = xs[(ty * CPT + c) * 32 + k];
                #pragma unroll
                for (int j = 0; j < 4; j++) acc[c][j] = fmaf(a, wv[j], acc[c][j]);
            }
        }
    }
    #pragma unroll
    for (int c = 0; c < CPT; c++) {
        int cand = ty * CPT + c;
        #pragma unroll
        for (int j = 0; j < 4; j++) {
            int e = e0 + tx * 4 + j;
            outp[((size_t)b * ncand + cand) * EE + e] = acc[c][j] + bias[e];
        }
    }
}

// ===================== exact top-64 among the 96 candidates =================
__global__ __launch_bounds__(128) void topk_refine_kernel(
    const float* __restrict__ scex, const int* __restrict__ idx96,
    int* __restrict__ idxfin, int* __restrict__ candfin)
{
    __shared__ float sv[NCAND];
    __shared__ int   si[NCAND];
    __shared__ float rv[128];
    __shared__ int   rc[128];
    __shared__ int   rs[128];
    const int b = blockIdx.x, t = threadIdx.x;
    if (t < NCAND) { sv[t] = scex[b * NCAND + t]; si[t] = idx96[b * NCAND + t]; }
    __syncthreads();
    for (int l = 0; l < LL; l++) {
        float m = -INFINITY; int c = 0; int sb = 0x7fffffff;
        if (t < NCAND) { m = sv[t]; c = t; sb = si[t]; }
        rv[t] = m; rc[t] = c; rs[t] = sb;
        __syncthreads();
        for (int s = 64; s > 0; s >>= 1) {
            if (t < s) {
                if (rv[t + s] > rv[t] || (rv[t + s] == rv[t] && rs[t + s] < rs[t])) {
                    rv[t] = rv[t + s]; rc[t] = rc[t + s]; rs[t] = rs[t + s];
                }
            }
            __syncthreads();
        }
        if (t == 0) {
            idxfin[b * LL + l] = rs[0];
            candfin[b * LL + l] = rc[0];
            sv[rc[0]] = -INFINITY;
        }
        __syncthreads();
    }
}

// ===================== permute exact rows into [B,H,L,D] ====================
__global__ __launch_bounds__(256) void gatherperm_kernel(
    const float* __restrict__ kex, const float* __restrict__ vex,
    const int* __restrict__ candf,
    float* __restrict__ Ksp, float* __restrict__ Vsp)
{
    int i = blockIdx.x * 256 + threadIdx.x;
    int d = i & 63;
    int l = (i >> 6) & 63;
    int h = (i >> 12) & 15;
    int b = i >> 16;
    int cp = candf[b * LL + l];
    size_t src = ((size_t)b * NCAND + cp) * EE + h * 64 + d;
    Ksp[i] = kex[src];
    Vsp[i] = vex[src];
}

// ===================== attention (float4 w stores) ==========================
__global__ __launch_bounds__(64) void attn_kernel(
    const float* __restrict__ Q, const float* __restrict__ Ksp,
    const float* __restrict__ Vsp, float* __restrict__ w_out,
    float* __restrict__ ctx)
{
    __shared__ float Kt[64 * 64];
    __shared__ float Vt[64 * 64];
    __shared__ float sc[64 * 64];

    const int b = blockIdx.z, h = blockIdx.y, chunk = blockIdx.x;
    const int i = threadIdx.x;

    const float* Kg = Ksp + ((size_t)(b * HH + h) << 12);
    const float* Vg = Vsp + ((size_t)(b * HH + h) << 12);
    for (int j = i; j < 1024; j += 64) {
        ((float4*)Kt)[j] = ((const float4*)Kg)[j];
        ((float4*)Vt)[j] = ((const float4*)Vg)[j];
    }
    __syncthreads();

    const int s = chunk * 64 + i;
    const float* qp = Q + ((size_t)(b * SS + s)) * EE + h * 64;
    float4 q4[16];
    #pragma unroll
    for (int j = 0; j < 16; j++) q4[j] = ((const float4*)qp)[j];

    float mx = -INFINITY;
    #pragma unroll 4
    for (int l = 0; l < 64; l++) {
        const float4* kl = (const float4*)(Kt + l * 64);
        float acc = 0.f;
        #pragma unroll
        for (int j = 0; j < 16; j++) {
            float4 kv = kl[j];
            acc = fmaf(q4[j].x, kv.x, acc);
            acc = fmaf(q4[j].y, kv.y, acc);
            acc = fmaf(q4[j].z, kv.z, acc);
            acc = fmaf(q4[j].w, kv.w, acc);
        }
        acc *= 0.125f;
        sc[l * 64 + i] = acc;
        mx = fmaxf(mx, acc);
    }

    float sum = 0.f;
    #pragma unroll 4
    for (int l = 0; l < 64; l++) {
        float e = expf(sc[l * 64 + i] - mx);
        sc[l * 64 + i] = e;
        sum += e;
    }
    const float inv = 1.f / sum;

    float4 c4[16];
    #pragma unroll
    for (int j = 0; j < 16; j++) c4[j] = make_float4(0.f, 0.f, 0.f, 0.f);

    float* wp = w_out + ((size_t)((b * HH + h) * SS + s)) * LL;
    #pragma unroll 2
    for (int l4 = 0; l4 < 16; l4++) {
        float wls[4];
        #pragma unroll
        for (int jj = 0; jj < 4; jj++) {
            int l = l4 * 4 + jj;
            float wl = sc[l * 64 + i] * inv;
            wls[jj] = wl;
            const float4* vl = (const float4*)(Vt + l * 64);
            #pragma unroll
            for (int j = 0; j < 16; j++) {
                float4 vv = vl[j];
                c4[j].x = fmaf(wl, vv.x, c4[j].x);
                c4[j].y = fmaf(wl, vv.y, c4[j].y);
                c4[j].z = fmaf(wl, vv.z, c4[j].z);
                c4[j].w = fmaf(wl, vv.w, c4[j].w);
            }
        }
        *(float4*)(wp + l4 * 4) = make_float4(wls[0], wls[1], wls[2], wls[3]);
    }

    float* cp = ctx + ((size_t)(b * SS + s)) * EE + h * 64;
    #pragma unroll
    for (int j = 0; j < 16; j++) ((float4*)cp)[j] = c4[j];
}

// ===================== launch ===============================================
extern "C" void kernel_launch(void* const* d_in, const int* in_sizes, int n_in,
                              void* d_out, int out_size)
{
    const float* query = (const float*)d_in[0];
    const float* key   = (const float*)d_in[1];
    const float* value = (const float*)d_in[2];
    const float* Wq = (const float*)d_in[3];
    const float* bq = (const float*)d_in[4];
    const float* Wk = (const float*)d_in[5];
    const float* bk = (const float*)d_in[6];
    const float* Wv = (const float*)d_in[7];
    const float* bv = (const float*)d_in[8];
    const float* Wo = (const float*)d_in[9];
    const float* bo = (const float*)d_in[10];

    float* out  = (float*)d_out;
    float* wout = out + MSZ;

    float *pQ, *pK, *pC, *pScores, *pKex, *pVex, *pScex, *pKsp, *pVsp;
    __nv_bfloat16 *pAhi, *pAkhi, *pWqhi, *pWkhi, *pWohi;
    char *pA8, *pWq8, *pWo8;
    int *pIdx96, *pIdxf, *pCandf;
    cudaGetSymbolAddress((void**)&pQ, g_Q);
    cudaGetSymbolAddress((void**)&pK, g_K);
    cudaGetSymbolAddress((void**)&pC, g_ctx);
    cudaGetSymbolAddress((void**)&pAhi, g_Ahi);
    cudaGetSymbolAddress((void**)&pA8, g_A8);
    cudaGetSymbolAddress((void**)&pAkhi, g_Akhi);
    cudaGetSymbolAddress((void**)&pWqhi, g_Wqhi);
    cudaGetSymbolAddress((void**)&pWq8, g_Wq8);
    cudaGetSymbolAddress((void**)&pWkhi, g_Wkhi);
    cudaGetSymbolAddress((void**)&pWohi, g_Wohi);
    cudaGetSymbolAddress((void**)&pWo8, g_Wo8);
    cudaGetSymbolAddress((void**)&pScores, g_scores);
    cudaGetSymbolAddress((void**)&pIdx96, g_idx96);
    cudaGetSymbolAddress((void**)&pKex, g_kex);
    cudaGetSymbolAddress((void**)&pVex, g_vex);
    cudaGetSymbolAddress((void**)&pScex, g_scex);
    cudaGetSymbolAddress((void**)&pIdxf, g_idxf);
    cudaGetSymbolAddress((void**)&pCandf, g_candf);
    cudaGetSymbolAddress((void**)&pKsp, g_Ksp);
    cudaGetSymbolAddress((void**)&pVsp, g_Vsp);

    cudaFuncSetAttribute(gemm_bf16, cudaFuncAttributeMaxDynamicSharedMemorySize, GEMM_SMEM);
    cudaFuncSetAttribute(gemm_s8,   cudaFuncAttributeMaxDynamicSharedMemorySize, GEMM_SMEM);

    const int n4m = (int)(MSZ / 4);
    const int n4w = EE * EE / 4;
    dim3 ggrid(4, 256);

    // quantize weights + activations
    quant_w<<<n4w / 256, 256>>>(Wq, pWqhi, pWq8, n4w);
    quant_w<<<n4w / 256, 256>>>(Wo, pWohi, pWo8, n4w);
    hi_only<<<n4w / 256, 256>>>(Wk, pWkhi, n4w);
    quant_a<<<n4m / 256, 256>>>(query, pAhi, pA8, n4m);
    hi_only<<<n4m / 256, 256>>>(key, pAkhi, n4m);

    // Q = query @ Wq^T + bq : bf16 hi*hi then int8 cross-terms
    gemm_bf16<<<ggrid, 256, GEMM_SMEM>>>(pAhi, pWqhi, bq, pQ);
    gemm_s8<<<ggrid, 256, GEMM_SMEM>>>(pA8, pWq8, pQ);

    // K (selection only): single bf16 product
    gemm_bf16<<<ggrid, 256, GEMM_SMEM>>>(pAkhi, pWkhi, bk, pK);

    // approx scores -> top-96 candidates
    scores_kernel<<<MROWS / 8, 256>>>(pK, pScores);
    topk_kernel<<<BB, 1024>>>(pScores, pIdx96, NCAND);

    // exact fp32 K/V rows at candidates, exact scores, exact top-64
    dim3 pgrid(8, BB);
    project_rows<12><<<pgrid, 256>>>(key,   Wk, bk, pIdx96, NCAND, pKex);
    project_rows<12><<<pgrid, 256>>>(value, Wv, bv, pIdx96, NCAND, pVex);
    scores_kernel<<<(BB * NCAND) / 8, 256>>>(pKex, pScex);
    topk_refine_kernel<<<BB, 128>>>(pScex, pIdx96, pIdxf, pCandf);
    gatherperm_kernel<<<(BB * HH * LL * DD) / 256, 256>>>(pKex, pVex, pCandf, pKsp, pVsp);

    // attention
    dim3 agrid(SS / 64, HH, BB);
    attn_kernel<<<agrid, 64>>>(pQ, pKsp, pVsp, wout, pC);

    // out = ctx @ Wo^T + bo : bf16 hi*hi then int8 cross-terms
    quant_a<<<n4m / 256, 256>>>(pC, pAhi, pA8, n4m);
    gemm_bf16<<<ggrid, 256, GEMM_SMEM>>>(pAhi, pWohi, bo, out);
    gemm_s8<<<ggrid, 256, GEMM_SMEM>>>(pA8, pWo8, out);
}

// round 9
// speedup vs baseline: 1.8560x; 1.8560x over previous
#include <cuda_runtime.h>
#include <cuda_fp16.h>
#include <math.h>
#include <stdint.h>

#define BB 4
#define SS 8192
#define EE 1024
#define HH 16
#define DD 64
#define LL 64
#define NCAND 96
#define MROWS (BB * SS)
#define MSZ   ((size_t)MROWS * EE)

// ===================== scratch ==============================================
__device__ float  g_Q[MSZ];
__device__ float  g_K[MSZ];
__device__ __half g_A2[MSZ * 2];      // activation 2-seg fp16 [row][2048]: hi | mid (query, then ctx)
__device__ __half g_Akh[MSZ];         // key activation fp16 single
__device__ __half g_Wqh[EE * EE];
__device__ __half g_Wkh[EE * EE];
__device__ __half g_Woh[EE * EE];
__device__ float g_scores[BB * SS];
__device__ int   g_idx96[BB * NCAND];
__device__ float g_kex[BB * NCAND * EE];
__device__ float g_vex[BB * NCAND * EE];
__device__ float g_scex[BB * NCAND];
__device__ int   g_idxf[BB * LL];
__device__ int   g_candf[BB * LL];
__device__ float g_Ksp[BB * HH * LL * DD];
__device__ float g_Vsp[BB * HH * LL * DD];

// ===================== small PTX helpers ====================================
__device__ __forceinline__ uint32_t smem_u32(const void* p) {
    uint32_t a;
    asm("{ .reg .u64 t; cvta.to.shared.u64 t, %1; cvt.u32.u64 %0, t; }" : "=r"(a) : "l"(p));
    return a;
}
__device__ __forceinline__ void cp16(uint32_t dst, const void* src) {
    asm volatile("cp.async.cg.shared.global [%0], [%1], 16;" :: "r"(dst), "l"(src));
}
#define CP_COMMIT() asm volatile("cp.async.commit_group;" ::: "memory")
#define CP_WAIT1()  asm volatile("cp.async.wait_group 1;" ::: "memory")
__device__ __forceinline__ void ldm_x4(uint32_t* r, uint32_t addr) {
    asm volatile("ldmatrix.sync.aligned.m8n8.x4.shared.b16 {%0,%1,%2,%3}, [%4];"
                 : "=r"(r[0]), "=r"(r[1]), "=r"(r[2]), "=r"(r[3]) : "r"(addr));
}
#define MMAF16(d, a, b0, b1) \
    asm volatile("mma.sync.aligned.m16n8k16.row.col.f32.f16.f16.f32 " \
        "{%0,%1,%2,%3}, {%4,%5,%6,%7}, {%8,%9}, {%0,%1,%2,%3};" \
        : "+f"((d)[0]), "+f"((d)[1]), "+f"((d)[2]), "+f"((d)[3]) \
        : "r"((a)[0]), "r"((a)[1]), "r"((a)[2]), "r"((a)[3]), \
          "r"(b0), "r"(b1))

// ===================== fp32 -> fp16 conversions ==============================
__global__ __launch_bounds__(256) void conv_f16(
    const float* __restrict__ x, __half* __restrict__ h, int n4)
{
    int i = blockIdx.x * 256 + threadIdx.x;
    if (i >= n4) return;
    float4 v = ((const float4*)x)[i];
    uint32_t h0 = (uint32_t)__half_as_ushort(__float2half(v.x));
    uint32_t h1 = (uint32_t)__half_as_ushort(__float2half(v.y));
    uint32_t h2 = (uint32_t)__half_as_ushort(__float2half(v.z));
    uint32_t h3 = (uint32_t)__half_as_ushort(__float2half(v.w));
    uint2 hp; hp.x = h0 | (h1 << 16); hp.y = h2 | (h3 << 16);
    ((uint2*)h)[i] = hp;
}

// x -> hi (fp16) + mid (fp16 of residual); layout A2[row][2048] = hi | mid
__global__ __launch_bounds__(256) void quant_a2(
    const float* __restrict__ x, __half* __restrict__ a2, int n4)
{
    int i = blockIdx.x * 256 + threadIdx.x;
    if (i >= n4) return;
    float4 v = ((const float4*)x)[i];
    float vv[4] = {v.x, v.y, v.z, v.w};
    uint32_t hb[4], mb[4];
    #pragma unroll
    for (int q = 0; q < 4; q++) {
        __half h = __float2half(vv[q]);
        __half m = __float2half(vv[q] - __half2float(h));
        hb[q] = (uint32_t)__half_as_ushort(h);
        mb[q] = (uint32_t)__half_as_ushort(m);
    }
    uint2 hp, mp;
    hp.x = hb[0] | (hb[1] << 16); hp.y = hb[2] | (hb[3] << 16);
    mp.x = mb[0] | (mb[1] << 16); mp.y = mb[2] | (mb[3] << 16);
    size_t e = (size_t)i * 4;
    size_t row = e >> 10, k = e & 1023;
    *(uint2*)(a2 + row * 2048 + k)        = hp;
    *(uint2*)(a2 + row * 2048 + 1024 + k) = mp;
}

// ===================== fp16 GEMM =============================================
// C[M,1024] = A @ W^T + bias. NKT=32: A is 2-seg [row][2048] (hi|mid), W single
// fp16 -> products Ahi*W + Amid*W (exact in A, W-rounding only).
// NKT=16: single product. BM=128, BN=256, BK=64, warp tile 64x64, 3 stages.
#define GSTAGE 49152u
#define GEMM_SMEM (3 * 49152)

template<int NKT, int ASTRIDE>
__global__ __launch_bounds__(256) void gemm_f16(
    const __half* __restrict__ A, const __half* __restrict__ W,
    const float* __restrict__ bias, float* __restrict__ C)
{
    extern __shared__ __align__(128) char dsm[];
    const uint32_t sbase = smem_u32(dsm);
    const int tid  = threadIdx.x;
    const int lane = tid & 31;
    const int wid  = tid >> 5;
    const int bm = blockIdx.y * 128;
    const int bn = blockIdx.x * 256;
    const int m0 = (wid & 1) * 64;
    const int n0 = (wid >> 1) * 64;
    const int qrow = lane >> 2;
    const int qk   = (lane & 3) * 2;
    const int lrow  = lane & 7;
    const int phase = lane >> 3;
    const int g_c  = tid & 7;
    const int g_r0 = tid >> 3;

    float c[4][8][4];
    #pragma unroll
    for (int mt = 0; mt < 4; mt++)
        #pragma unroll
        for (int nt = 0; nt < 8; nt++)
            #pragma unroll
            for (int q = 0; q < 4; q++) c[mt][nt][q] = 0.f;

    auto load_tile = [&](int kt) {
        if (kt < NKT) {
            const uint32_t sA = sbase + (uint32_t)(kt % 3) * GSTAGE;
            const uint32_t sB = sA + 16384u;
            const int ka = kt << 6;                 // A column (halfs)
            const int kw = (kt & 15) << 6;          // W column repeats per seg
            #pragma unroll
            for (int i = 0; i < 4; i++) {
                int row = g_r0 + i * 32;
                uint32_t off = (uint32_t)(row * 128 + ((g_c ^ (row & 7)) << 4));
                cp16(sA + off, A + (size_t)(bm + row) * ASTRIDE + ka + g_c * 8);
            }
            #pragma unroll
            for (int i = 0; i < 8; i++) {
                int row = g_r0 + i * 32;
                uint32_t off = (uint32_t)(row * 128 + ((g_c ^ (row & 7)) << 4));
                cp16(sB + off, W + (size_t)(bn + row) * 1024 + kw + g_c * 8);
            }
        }
        CP_COMMIT();
    };

    load_tile(0);
    load_tile(1);

    for (int kt = 0; kt < NKT; kt++) {
        CP_WAIT1();
        __syncthreads();
        load_tile(kt + 2);
        const uint32_t aB = sbase + (uint32_t)(kt % 3) * GSTAGE;
        const uint32_t bB = aB + 16384u;
        #pragma unroll
        for (int ks = 0; ks < 4; ks++) {
            const int c0 = ks * 2;
            uint32_t a[4][4];
            #pragma unroll
            for (int mt = 0; mt < 4; mt++) {
                int row = m0 + mt * 16 + (phase & 1) * 8 + lrow;
                int ch  = c0 + (phase >> 1);
                ldm_x4(a[mt], aB + (uint32_t)(row * 128 + ((ch ^ (row & 7)) << 4)));
            }
            uint32_t bf[4][4];
            #pragma unroll
            for (int ng = 0; ng < 4; ng++) {
                int row = n0 + ng * 16 + (phase >> 1) * 8 + lrow;
                int ch  = c0 + (phase & 1);
                ldm_x4(bf[ng], bB + (uint32_t)(row * 128 + ((ch ^ (row & 7)) << 4)));
            }
            #pragma unroll
            for (int nt = 0; nt < 8; nt++) {
                uint32_t b0 = bf[nt >> 1][(nt & 1) * 2];
                uint32_t b1 = bf[nt >> 1][(nt & 1) * 2 + 1];
                #pragma unroll
                for (int mt = 0; mt < 4; mt++)
                    MMAF16(c[mt][nt], a[mt], b0, b1);
            }
        }
        __syncthreads();
    }

    #pragma unroll
    for (int mt = 0; mt < 4; mt++) {
        #pragma unroll
        for (int nt = 0; nt < 8; nt++) {
            int r0  = bm + m0 + mt * 16 + qrow;
            int col = bn + n0 + nt * 8 + qk;
            float2 bv = *(const float2*)(bias + col);
            float2 o0, o1;
            o0.x = c[mt][nt][0] + bv.x; o0.y = c[mt][nt][1] + bv.y;
            o1.x = c[mt][nt][2] + bv.x; o1.y = c[mt][nt][3] + bv.y;
            *(float2*)(C + (size_t)r0 * 1024 + col) = o0;
            *(float2*)(C + (size_t)(r0 + 8) * 1024 + col) = o1;
        }
    }
}

// ===================== scores[row] = mean_h ||X[row, h*64:+64]|| ============
__global__ __launch_bounds__(256) void scores_kernel(
    const float* __restrict__ Km, float* __restrict__ scores)
{
    int row  = blockIdx.x * 8 + (threadIdx.x >> 5);
    int lane = threadIdx.x & 31;
    const float* kr = Km + (size_t)row * EE;
    float acc = 0.f;
    #pragma unroll
    for (int h = 0; h < HH; h++) {
        float x0 = kr[h * 64 + lane];
        float x1 = kr[h * 64 + 32 + lane];
        float ss = x0 * x0 + x1 * x1;
        #pragma unroll
        for (int o = 16; o > 0; o >>= 1)
            ss += __shfl_xor_sync(0xffffffffu, ss, o);
        acc += sqrtf(ss);
    }
    if (lane == 0) scores[row] = acc * (1.f / 16.f);
}

// ===================== approx top-kk per batch ===============================
__global__ __launch_bounds__(1024) void topk_kernel(
    const float* __restrict__ scores, int* __restrict__ idxout, int kk)
{
    __shared__ float sv[SS];
    __shared__ float rv[1024];
    __shared__ int   ri[1024];
    const int b = blockIdx.x, t = threadIdx.x;
    for (int i = t; i < SS; i += 1024) sv[i] = scores[b * SS + i];
    __syncthreads();
    for (int l = 0; l < kk; l++) {
        float m = -INFINITY; int a = 0;
        #pragma unroll
        for (int u = 0; u < 8; u++) {
            int i = t + u * 1024;
            float v = sv[i];
            if (v > m) { m = v; a = i; }
        }
        rv[t] = m; ri[t] = a;
        __syncthreads();
        for (int s = 512; s > 0; s >>= 1) {
            if (t < s) {
                float v2 = rv[t + s]; int a2 = ri[t + s];
                if (v2 > rv[t] || (v2 == rv[t] && a2 < ri[t])) { rv[t] = v2; ri[t] = a2; }
            }
            __syncthreads();
        }
        if (t == 0) { idxout[b * kk + l] = ri[0]; sv[ri[0]] = -INFINITY; }
        __syncthreads();
    }
}

// ===================== exact fp32 projection of candidate rows ==============
template<int CPT>
__global__ __launch_bounds__(256) void project_rows(
    const float* __restrict__ X, const float* __restrict__ Wt,
    const float* __restrict__ bias, const int* __restrict__ idx,
    int ncand, float* __restrict__ outp)
{
    __shared__ float xs[NCAND * 32];
    __shared__ float ws[32 * 128];
    const int b = blockIdx.y;
    const int e0 = blockIdx.x * 128;
    const int t = threadIdx.x, tx = t & 31, ty = t >> 5;

    float acc[CPT][4];
    #pragma unroll
    for (int c = 0; c < CPT; c++)
        #pragma unroll
        for (int j = 0; j < 4; j++) acc[c][j] = 0.f;

    for (int kt = 0; kt < EE; kt += 32) {
        __syncthreads();
        for (int u = t; u < ncand * 8; u += 256) {
            int cand = u >> 3, c4 = u & 7;
            int s = idx[b * ncand + cand];
            float4 v = *(const float4*)(X + ((size_t)(b * SS + s)) * EE + kt + c4 * 4);
            *(float4*)(xs + cand * 32 + c4 * 4) = v;
        }
        for (int u = t; u < 1024; u += 256) {
            int e = u >> 3, c4 = u & 7;
            float4 v = *(const float4*)(Wt + (size_t)(e0 + e) * EE + kt + c4 * 4);
            ws[(c4 * 4 + 0) * 128 + e] = v.x;
            ws[(c4 * 4 + 1) * 128 + e] = v.y;
            ws[(c4 * 4 + 2) * 128 + e] = v.z;
            ws[(c4 * 4 + 3) * 128 + e] = v.w;
        }
        __syncthreads();
        #pragma unroll 8
        for (int k = 0; k < 32; k++) {
            float wv[4];
            #pragma unroll
            for (int j = 0; j < 4; j++) wv[j] = ws[k * 128 + tx * 4 + j];
            #pragma unroll
            for (int c = 0; c < CPT; c++) {
                float a = xs[(ty * CPT + c) * 32 + k];
                #pragma unroll
                for (int j = 0; j < 4; j++) acc[c][j] = fmaf(a, wv[j], acc[c][j]);
            }
        }
    }
    #pragma unroll
    for (int c = 0; c < CPT; c++) {
        int cand = ty * CPT + c;
        #pragma unroll
        for (int j = 0; j < 4; j++) {
            int e = e0 + tx * 4 + j;
            outp[((size_t)b * ncand + cand) * EE + e] = acc[c][j] + bias[e];
        }
    }
}

// ===================== exact top-64 among the 96 candidates =================
__global__ __launch_bounds__(128) void topk_refine_kernel(
    const float* __restrict__ scex, const int* __restrict__ idx96,
    int* __restrict__ idxfin, int* __restrict__ candfin)
{
    __shared__ float sv[NCAND];
    __shared__ int   si[NCAND];
    __shared__ float rv[128];
    __shared__ int   rc[128];
    __shared__ int   rs[128];
    const int b = blockIdx.x, t = threadIdx.x;
    if (t < NCAND) { sv[t] = scex[b * NCAND + t]; si[t] = idx96[b * NCAND + t]; }
    __syncthreads();
    for (int l = 0; l < LL; l++) {
        float m = -INFINITY; int c = 0; int sb = 0x7fffffff;
        if (t < NCAND) { m = sv[t]; c = t; sb = si[t]; }
        rv[t] = m; rc[t] = c; rs[t] = sb;
        __syncthreads();
        for (int s = 64; s > 0; s >>= 1) {
            if (t < s) {
                if (rv[t + s] > rv[t] || (rv[t + s] == rv[t] && rs[t + s] < rs[t])) {
                    rv[t] = rv[t + s]; rc[t] = rc[t + s]; rs[t] = rs[t + s];
                }
            }
            __syncthreads();
        }
        if (t == 0) {
            idxfin[b * LL + l] = rs[0];
            candfin[b * LL + l] = rc[0];
            sv[rc[0]] = -INFINITY;
        }
        __syncthreads();
    }
}

// ===================== permute exact rows into [B,H,L,D] ====================
__global__ __launch_bounds__(256) void gatherperm_kernel(
    const float* __restrict__ kex, const float* __restrict__ vex,
    const int* __restrict__ candf,
    float* __restrict__ Ksp, float* __restrict__ Vsp)
{
    int i = blockIdx.x * 256 + threadIdx.x;
    int d = i & 63;
    int l = (i >> 6) & 63;
    int h = (i >> 12) & 15;
    int b = i >> 16;
    int cp = candf[b * LL + l];
    size_t src = ((size_t)b * NCAND + cp) * EE + h * 64 + d;
    Ksp[i] = kex[src];
    Vsp[i] = vex[src];
}

// ===================== attention (ctx -> fp16 2-seg fused) ==================
__global__ __launch_bounds__(64) void attn_kernel(
    const float* __restrict__ Q, const float* __restrict__ Ksp,
    const float* __restrict__ Vsp, float* __restrict__ w_out,
    __half* __restrict__ ctx2)
{
    __shared__ float Kt[64 * 64];
    __shared__ float Vt[64 * 64];
    __shared__ float sc[64 * 64];

    const int b = blockIdx.z, h = blockIdx.y, chunk = blockIdx.x;
    const int i = threadIdx.x;

    const float* Kg = Ksp + ((size_t)(b * HH + h) << 12);
    const float* Vg = Vsp + ((size_t)(b * HH + h) << 12);
    for (int j = i; j < 1024; j += 64) {
        ((float4*)Kt)[j] = ((const float4*)Kg)[j];
        ((float4*)Vt)[j] = ((const float4*)Vg)[j];
    }
    __syncthreads();

    const int s = chunk * 64 + i;
    const float* qp = Q + ((size_t)(b * SS + s)) * EE + h * 64;
    float4 q4[16];
    #pragma unroll
    for (int j = 0; j < 16; j++) q4[j] = ((const float4*)qp)[j];

    float mx = -INFINITY;
    #pragma unroll 4
    for (int l = 0; l < 64; l++) {
        const float4* kl = (const float4*)(Kt + l * 64);
        float acc = 0.f;
        #pragma unroll
        for (int j = 0; j < 16; j++) {
            float4 kv = kl[j];
            acc = fmaf(q4[j].x, kv.x, acc);
            acc = fmaf(q4[j].y, kv.y, acc);
            acc = fmaf(q4[j].z, kv.z, acc);
            acc = fmaf(q4[j].w, kv.w, acc);
        }
        acc *= 0.125f;
        sc[l * 64 + i] = acc;
        mx = fmaxf(mx, acc);
    }

    float sum = 0.f;
    #pragma unroll 4
    for (int l = 0; l < 64; l++) {
        float e = expf(sc[l * 64 + i] - mx);
        sc[l * 64 + i] = e;
        sum += e;
    }
    const float inv = 1.f / sum;

    float4 c4[16];
    #pragma unroll
    for (int j = 0; j < 16; j++) c4[j] = make_float4(0.f, 0.f, 0.f, 0.f);

    float* wp = w_out + ((size_t)((b * HH + h) * SS + s)) * LL;
    #pragma unroll 2
    for (int l4 = 0; l4 < 16; l4++) {
        float wls[4];
        #pragma unroll
        for (int jj = 0; jj < 4; jj++) {
            int l = l4 * 4 + jj;
            float wl = sc[l * 64 + i] * inv;
            wls[jj] = wl;
            const float4* vl = (const float4*)(Vt + l * 64);
            #pragma unroll
            for (int j = 0; j < 16; j++) {
                float4 vv = vl[j];
                c4[j].x = fmaf(wl, vv.x, c4[j].x);
                c4[j].y = fmaf(wl, vv.y, c4[j].y);
                c4[j].z = fmaf(wl, vv.z, c4[j].z);
                c4[j].w = fmaf(wl, vv.w, c4[j].w);
            }
        }
        *(float4*)(wp + l4 * 4) = make_float4(wls[0], wls[1], wls[2], wls[3]);
    }

    // fused fp16 2-seg ctx write: ctx2[row][2048] = hi | mid
    __half* hp = ctx2 + ((size_t)(b * SS + s)) * 2048 + h * 64;
    __half* mp = hp + 1024;
    #pragma unroll
    for (int j = 0; j < 16; j++) {
        float vv[4] = {c4[j].x, c4[j].y, c4[j].z, c4[j].w};
        uint32_t hb[4], mb[4];
        #pragma unroll
        for (int q = 0; q < 4; q++) {
            __half hh = __float2half(vv[q]);
            __half mm = __float2half(vv[q] - __half2float(hh));
            hb[q] = (uint32_t)__half_as_ushort(hh);
            mb[q] = (uint32_t)__half_as_ushort(mm);
        }
        uint2 hv, mv;
        hv.x = hb[0] | (hb[1] << 16); hv.y = hb[2] | (hb[3] << 16);
        mv.x = mb[0] | (mb[1] << 16); mv.y = mb[2] | (mb[3] << 16);
        *(uint2*)(hp + j * 4) = hv;
        *(uint2*)(mp + j * 4) = mv;
    }
}

// ===================== launch ===============================================
extern "C" void kernel_launch(void* const* d_in, const int* in_sizes, int n_in,
                              void* d_out, int out_size)
{
    const float* query = (const float*)d_in[0];
    const float* key   = (const float*)d_in[1];
    const float* value = (const float*)d_in[2];
    const float* Wq = (const float*)d_in[3];
    const float* bq = (const float*)d_in[4];
    const float* Wk = (const float*)d_in[5];
    const float* bk = (const float*)d_in[6];
    const float* Wv = (const float*)d_in[7];
    const float* bv = (const float*)d_in[8];
    const float* Wo = (const float*)d_in[9];
    const float* bo = (const float*)d_in[10];

    float* out  = (float*)d_out;
    float* wout = out + MSZ;

    float *pQ, *pK, *pScores, *pKex, *pVex, *pScex, *pKsp, *pVsp;
    __half *pA2, *pAkh, *pWqh, *pWkh, *pWoh;
    int *pIdx96, *pIdxf, *pCandf;
    cudaGetSymbolAddress((void**)&pQ, g_Q);
    cudaGetSymbolAddress((void**)&pK, g_K);
    cudaGetSymbolAddress((void**)&pA2, g_A2);
    cudaGetSymbolAddress((void**)&pAkh, g_Akh);
    cudaGetSymbolAddress((void**)&pWqh, g_Wqh);
    cudaGetSymbolAddress((void**)&pWkh, g_Wkh);
    cudaGetSymbolAddress((void**)&pWoh, g_Woh);
    cudaGetSymbolAddress((void**)&pScores, g_scores);
    cudaGetSymbolAddress((void**)&pIdx96, g_idx96);
    cudaGetSymbolAddress((void**)&pKex, g_kex);
    cudaGetSymbolAddress((void**)&pVex, g_vex);
    cudaGetSymbolAddress((void**)&pScex, g_scex);
    cudaGetSymbolAddress((void**)&pIdxf, g_idxf);
    cudaGetSymbolAddress((void**)&pCandf, g_candf);
    cudaGetSymbolAddress((void**)&pKsp, g_Ksp);
    cudaGetSymbolAddress((void**)&pVsp, g_Vsp);

    cudaFuncSetAttribute((void*)gemm_f16<32, 2048>, cudaFuncAttributeMaxDynamicSharedMemorySize, GEMM_SMEM);
    cudaFuncSetAttribute((void*)gemm_f16<16, 1024>, cudaFuncAttributeMaxDynamicSharedMemorySize, GEMM_SMEM);

    const int n4m = (int)(MSZ / 4);
    const int n4w = EE * EE / 4;
    dim3 ggrid(4, 256);

    // launches 1-5: conversions (puts Q GEMM at launch 6 for ncu -s 5)
    conv_f16<<<n4w / 256, 256>>>(Wq, pWqh, n4w);
    conv_f16<<<n4w / 256, 256>>>(Wk, pWkh, n4w);
    conv_f16<<<n4w / 256, 256>>>(Wo, pWoh, n4w);
    quant_a2<<<n4m / 256, 256>>>(query, pA2, n4m);
    conv_f16<<<n4m / 256, 256>>>(key, pAkh, n4m);

    // Q = query(2-seg) @ fp16(Wq)^T + bq
    gemm_f16<32, 2048><<<ggrid, 256, GEMM_SMEM>>>(pA2, pWqh, bq, pQ);

    // K (selection only): single fp16 product
    gemm_f16<16, 1024><<<ggrid, 256, GEMM_SMEM>>>(pAkh, pWkh, bk, pK);

    // approx scores -> top-96 candidates
    scores_kernel<<<MROWS / 8, 256>>>(pK, pScores);
    topk_kernel<<<BB, 1024>>>(pScores, pIdx96, NCAND);

    // exact fp32 K/V rows at candidates, exact scores, exact top-64
    dim3 pgrid(8, BB);
    project_rows<12><<<pgrid, 256>>>(key,   Wk, bk, pIdx96, NCAND, pKex);
    project_rows<12><<<pgrid, 256>>>(value, Wv, bv, pIdx96, NCAND, pVex);
    scores_kernel<<<(BB * NCAND) / 8, 256>>>(pKex, pScex);
    topk_refine_kernel<<<BB, 128>>>(pScex, pIdx96, pIdxf, pCandf);
    gatherperm_kernel<<<(BB * HH * LL * DD) / 256, 256>>>(pKex, pVex, pCandf, pKsp, pVsp);

    // attention (writes w + fp16 2-seg ctx into A2)
    dim3 agrid(SS / 64, HH, BB);
    attn_kernel<<<agrid, 64>>>(pQ, pKsp, pVsp, wout, pA2);

    // out = ctx(2-seg) @ fp16(Wo)^T + bo
    gemm_f16<32, 2048><<<ggrid, 256, GEMM_SMEM>>>(pA2, pWoh, bo, out);
}

// round 10
// speedup vs baseline: 2.3163x; 1.2480x over previous
#include <cuda_runtime.h>
#include <cuda_fp16.h>
#include <math.h>
#include <stdint.h>

#define BB 4
#define SS 8192
#define EE 1024
#define HH 16
#define DD 64
#define LL 64
#define NCAND 96
#define MROWS (BB * SS)
#define MSZ   ((size_t)MROWS * EE)

// ===================== scratch ==============================================
__device__ float  g_Q[MSZ];
__device__ __half g_Aqh[MSZ];         // query fp16, later reused for ctx fp16
__device__ __half g_Akh[MSZ];         // key fp16
__device__ __half g_Wqh[EE * EE];
__device__ __half g_Wkh[EE * EE];
__device__ __half g_Woh[EE * EE];
__device__ float g_ssq[MROWS * HH];   // per-(row, head) sum of squares
__device__ float g_scores[BB * SS];
__device__ int   g_idx96[BB * NCAND];
__device__ float g_kex[BB * NCAND * EE];
__device__ float g_vex[BB * NCAND * EE];
__device__ float g_scex[BB * NCAND];
__device__ int   g_idxf[BB * LL];
__device__ int   g_candf[BB * LL];
__device__ float g_Ksp[BB * HH * LL * DD];
__device__ float g_Vsp[BB * HH * LL * DD];

// ===================== small PTX helpers ====================================
__device__ __forceinline__ uint32_t smem_u32(const void* p) {
    uint32_t a;
    asm("{ .reg .u64 t; cvta.to.shared.u64 t, %1; cvt.u32.u64 %0, t; }" : "=r"(a) : "l"(p));
    return a;
}
__device__ __forceinline__ void cp16(uint32_t dst, const void* src) {
    asm volatile("cp.async.cg.shared.global [%0], [%1], 16;" :: "r"(dst), "l"(src));
}
#define CP_COMMIT() asm volatile("cp.async.commit_group;" ::: "memory")
#define CP_WAIT1()  asm volatile("cp.async.wait_group 1;" ::: "memory")
__device__ __forceinline__ void ldm_x4(uint32_t* r, uint32_t addr) {
    asm volatile("ldmatrix.sync.aligned.m8n8.x4.shared.b16 {%0,%1,%2,%3}, [%4];"
                 : "=r"(r[0]), "=r"(r[1]), "=r"(r[2]), "=r"(r[3]) : "r"(addr));
}
#define MMAF16(d, a, b0, b1) \
    asm volatile("mma.sync.aligned.m16n8k16.row.col.f32.f16.f16.f32 " \
        "{%0,%1,%2,%3}, {%4,%5,%6,%7}, {%8,%9}, {%0,%1,%2,%3};" \
        : "+f"((d)[0]), "+f"((d)[1]), "+f"((d)[2]), "+f"((d)[3]) \
        : "r"((a)[0]), "r"((a)[1]), "r"((a)[2]), "r"((a)[3]), \
          "r"(b0), "r"(b1))

// ===================== fp32 -> fp16 conversion ===============================
__global__ __launch_bounds__(256) void conv_f16(
    const float* __restrict__ x, __half* __restrict__ h, int n4)
{
    int i = blockIdx.x * 256 + threadIdx.x;
    if (i >= n4) return;
    float4 v = ((const float4*)x)[i];
    uint32_t h0 = (uint32_t)__half_as_ushort(__float2half(v.x));
    uint32_t h1 = (uint32_t)__half_as_ushort(__float2half(v.y));
    uint32_t h2 = (uint32_t)__half_as_ushort(__float2half(v.z));
    uint32_t h3 = (uint32_t)__half_as_ushort(__float2half(v.w));
    uint2 hp; hp.x = h0 | (h1 << 16); hp.y = h2 | (h3 << 16);
    ((uint2*)h)[i] = hp;
}

// ===================== fp16 GEMM =============================================
// C[M,1024] = A @ W^T + bias. EPI=0: store C. EPI=1: store per-(row,head)
// sum-of-squares only (warp tile 64 cols == exactly one head).
// BM=128, BN=256, BK=64, 256 thr, warp grid 2x4, warp tile 64x64, 3 stages.
#define GSTAGE 49152u
#define GEMM_SMEM (3 * 49152)

template<int EPI>
__global__ __launch_bounds__(256) void gemm_f16(
    const __half* __restrict__ A, const __half* __restrict__ W,
    const float* __restrict__ bias, float* __restrict__ C)
{
    extern __shared__ __align__(128) char dsm[];
    const uint32_t sbase = smem_u32(dsm);
    const int tid  = threadIdx.x;
    const int lane = tid & 31;
    const int wid  = tid >> 5;
    const int bm = blockIdx.y * 128;
    const int bn = blockIdx.x * 256;
    const int m0 = (wid & 1) * 64;
    const int n0 = (wid >> 1) * 64;
    const int qrow = lane >> 2;
    const int qk   = (lane & 3) * 2;
    const int lrow  = lane & 7;
    const int phase = lane >> 3;
    const int g_c  = tid & 7;
    const int g_r0 = tid >> 3;

    float c[4][8][4];
    #pragma unroll
    for (int mt = 0; mt < 4; mt++)
        #pragma unroll
        for (int nt = 0; nt < 8; nt++)
            #pragma unroll
            for (int q = 0; q < 4; q++) c[mt][nt][q] = 0.f;

    auto load_tile = [&](int kt) {
        if (kt < 16) {
            const uint32_t sA = sbase + (uint32_t)(kt % 3) * GSTAGE;
            const uint32_t sB = sA + 16384u;
            const int kk = kt << 6;
            #pragma unroll
            for (int i = 0; i < 4; i++) {
                int row = g_r0 + i * 32;
                uint32_t off = (uint32_t)(row * 128 + ((g_c ^ (row & 7)) << 4));
                cp16(sA + off, A + (size_t)(bm + row) * 1024 + kk + g_c * 8);
            }
            #pragma unroll
            for (int i = 0; i < 8; i++) {
                int row = g_r0 + i * 32;
                uint32_t off = (uint32_t)(row * 128 + ((g_c ^ (row & 7)) << 4));
                cp16(sB + off, W + (size_t)(bn + row) * 1024 + kk + g_c * 8);
            }
        }
        CP_COMMIT();
    };

    load_tile(0);
    load_tile(1);

    for (int kt = 0; kt < 16; kt++) {
        CP_WAIT1();
        __syncthreads();
        load_tile(kt + 2);
        const uint32_t aB = sbase + (uint32_t)(kt % 3) * GSTAGE;
        const uint32_t bB = aB + 16384u;
        #pragma unroll
        for (int ks = 0; ks < 4; ks++) {
            const int c0 = ks * 2;
            uint32_t a[4][4];
            #pragma unroll
            for (int mt = 0; mt < 4; mt++) {
                int row = m0 + mt * 16 + (phase & 1) * 8 + lrow;
                int ch  = c0 + (phase >> 1);
                ldm_x4(a[mt], aB + (uint32_t)(row * 128 + ((ch ^ (row & 7)) << 4)));
            }
            uint32_t bf[4][4];
            #pragma unroll
            for (int ng = 0; ng < 4; ng++) {
                int row = n0 + ng * 16 + (phase >> 1) * 8 + lrow;
                int ch  = c0 + (phase & 1);
                ldm_x4(bf[ng], bB + (uint32_t)(row * 128 + ((ch ^ (row & 7)) << 4)));
            }
            #pragma unroll
            for (int nt = 0; nt < 8; nt++) {
                uint32_t b0 = bf[nt >> 1][(nt & 1) * 2];
                uint32_t b1 = bf[nt >> 1][(nt & 1) * 2 + 1];
                #pragma unroll
                for (int mt = 0; mt < 4; mt++)
                    MMAF16(c[mt][nt], a[mt], b0, b1);
            }
        }
        __syncthreads();
    }

    if (EPI == 0) {
        #pragma unroll
        for (int mt = 0; mt < 4; mt++) {
            #pragma unroll
            for (int nt = 0; nt < 8; nt++) {
                int r0  = bm + m0 + mt * 16 + qrow;
                int col = bn + n0 + nt * 8 + qk;
                float2 bv = *(const float2*)(bias + col);
                float2 o0, o1;
                o0.x = c[mt][nt][0] + bv.x; o0.y = c[mt][nt][1] + bv.y;
                o1.x = c[mt][nt][2] + bv.x; o1.y = c[mt][nt][3] + bv.y;
                *(float2*)(C + (size_t)r0 * 1024 + col) = o0;
                *(float2*)(C + (size_t)(r0 + 8) * 1024 + col) = o1;
            }
        }
    } else {
        // ssq epilogue: this warp's 64 cols = head (bn+n0)/64
        const int head = (bn + n0) >> 6;
        #pragma unroll
        for (int mt = 0; mt < 4; mt++) {
            float s0 = 0.f, s1 = 0.f;
            #pragma unroll
            for (int nt = 0; nt < 8; nt++) {
                int col = bn + n0 + nt * 8 + qk;
                float2 bv = *(const float2*)(bias + col);
                float v0 = c[mt][nt][0] + bv.x, v1 = c[mt][nt][1] + bv.y;
                float v2 = c[mt][nt][2] + bv.x, v3 = c[mt][nt][3] + bv.y;
                s0 += v0 * v0 + v1 * v1;
                s1 += v2 * v2 + v3 * v3;
            }
            s0 += __shfl_xor_sync(0xffffffffu, s0, 1);
            s0 += __shfl_xor_sync(0xffffffffu, s0, 2);
            s1 += __shfl_xor_sync(0xffffffffu, s1, 1);
            s1 += __shfl_xor_sync(0xffffffffu, s1, 2);
            if ((lane & 3) == 0) {
                int r = bm + m0 + mt * 16 + qrow;
                C[(size_t)r * HH + head] = s0;
                C[(size_t)(r + 8) * HH + head] = s1;
            }
        }
    }
}

// ===================== scores from ssq ======================================
__global__ __launch_bounds__(256) void scores_ssq(
    const float* __restrict__ ssq, float* __restrict__ scores)
{
    int row = blockIdx.x * 256 + threadIdx.x;
    const float* sp = ssq + (size_t)row * HH;
    float acc = 0.f;
    #pragma unroll
    for (int h = 0; h < HH; h++) acc += sqrtf(sp[h]);
    scores[row] = acc * (1.f / 16.f);
}

// ===================== scores[row] = mean_h ||X[row, h*64:+64]|| (fp32 rows) =
__global__ __launch_bounds__(256) void scores_kernel(
    const float* __restrict__ Km, float* __restrict__ scores)
{
    int row  = blockIdx.x * 8 + (threadIdx.x >> 5);
    int lane = threadIdx.x & 31;
    const float* kr = Km + (size_t)row * EE;
    float acc = 0.f;
    #pragma unroll
    for (int h = 0; h < HH; h++) {
        float x0 = kr[h * 64 + lane];
        float x1 = kr[h * 64 + 32 + lane];
        float ss = x0 * x0 + x1 * x1;
        #pragma unroll
        for (int o = 16; o > 0; o >>= 1)
            ss += __shfl_xor_sync(0xffffffffu, ss, o);
        acc += sqrtf(ss);
    }
    if (lane == 0) scores[row] = acc * (1.f / 16.f);
}

// ===================== approx top-kk per batch ===============================
__global__ __launch_bounds__(1024) void topk_kernel(
    const float* __restrict__ scores, int* __restrict__ idxout, int kk)
{
    __shared__ float sv[SS];
    __shared__ float rv[1024];
    __shared__ int   ri[1024];
    const int b = blockIdx.x, t = threadIdx.x;
    for (int i = t; i < SS; i += 1024) sv[i] = scores[b * SS + i];
    __syncthreads();
    for (int l = 0; l < kk; l++) {
        float m = -INFINITY; int a = 0;
        #pragma unroll
        for (int u = 0; u < 8; u++) {
            int i = t + u * 1024;
            float v = sv[i];
            if (v > m) { m = v; a = i; }
        }
        rv[t] = m; ri[t] = a;
        __syncthreads();
        for (int s = 512; s > 0; s >>= 1) {
            if (t < s) {
                float v2 = rv[t + s]; int a2 = ri[t + s];
                if (v2 > rv[t] || (v2 == rv[t] && a2 < ri[t])) { rv[t] = v2; ri[t] = a2; }
            }
            __syncthreads();
        }
        if (t == 0) { idxout[b * kk + l] = ri[0]; sv[ri[0]] = -INFINITY; }
        __syncthreads();
    }
}

// ===================== exact fp32 projection of candidate rows ==============
template<int CPT>
__global__ __launch_bounds__(256) void project_rows(
    const float* __restrict__ X, const float* __restrict__ Wt,
    const float* __restrict__ bias, const int* __restrict__ idx,
    int ncand, float* __restrict__ outp)
{
    __shared__ float xs[NCAND * 32];
    __shared__ float ws[32 * 128];
    const int b = blockIdx.y;
    const int e0 = blockIdx.x * 128;
    const int t = threadIdx.x, tx = t & 31, ty = t >> 5;

    float acc[CPT][4];
    #pragma unroll
    for (int c = 0; c < CPT; c++)
        #pragma unroll
        for (int j = 0; j < 4; j++) acc[c][j] = 0.f;

    for (int kt = 0; kt < EE; kt += 32) {
        __syncthreads();
        for (int u = t; u < ncand * 8; u += 256) {
            int cand = u >> 3, c4 = u & 7;
            int s = idx[b * ncand + cand];
            float4 v = *(const float4*)(X + ((size_t)(b * SS + s)) * EE + kt + c4 * 4);
            *(float4*)(xs + cand * 32 + c4 * 4) = v;
        }
        for (int u = t; u < 1024; u += 256) {
            int e = u >> 3, c4 = u & 7;
            float4 v = *(const float4*)(Wt + (size_t)(e0 + e) * EE + kt + c4 * 4);
            ws[(c4 * 4 + 0) * 128 + e] = v.x;
            ws[(c4 * 4 + 1) * 128 + e] = v.y;
            ws[(c4 * 4 + 2) * 128 + e] = v.z;
            ws[(c4 * 4 + 3) * 128 + e] = v.w;
        }
        __syncthreads();
        #pragma unroll 8
        for (int k = 0; k < 32; k++) {
            float wv[4];
            #pragma unroll
            for (int j = 0; j < 4; j++) wv[j] = ws[k * 128 + tx * 4 + j];
            #pragma unroll
            for (int c = 0; c < CPT; c++) {
                float a = xs[(ty * CPT + c) * 32 + k];
                #pragma unroll
                for (int j = 0; j < 4; j++) acc[c][j] = fmaf(a, wv[j], acc[c][j]);
            }
        }
    }
    #pragma unroll
    for (int c = 0; c < CPT; c++) {
        int cand = ty * CPT + c;
        #pragma unroll
        for (int j = 0; j < 4; j++) {
            int e = e0 + tx * 4 + j;
            outp[((size_t)b * ncand + cand) * EE + e] = acc[c][j] + bias[e];
        }
    }
}

// ===================== exact top-64 among the 96 candidates =================
__global__ __launch_bounds__(128) void topk_refine_kernel(
    const float* __restrict__ scex, const int* __restrict__ idx96,
    int* __restrict__ idxfin, int* __restrict__ candfin)
{
    __shared__ float sv[NCAND];
    __shared__ int   si[NCAND];
    __shared__ float rv[128];
    __shared__ int   rc[128];
    __shared__ int   rs[128];
    const int b = blockIdx.x, t = threadIdx.x;
    if (t < NCAND) { sv[t] = scex[b * NCAND + t]; si[t] = idx96[b * NCAND + t]; }
    __syncthreads();
    for (int l = 0; l < LL; l++) {
        float m = -INFINITY; int c = 0; int sb = 0x7fffffff;
        if (t < NCAND) { m = sv[t]; c = t; sb = si[t]; }
        rv[t] = m; rc[t] = c; rs[t] = sb;
        __syncthreads();
        for (int s = 64; s > 0; s >>= 1) {
            if (t < s) {
                if (rv[t + s] > rv[t] || (rv[t + s] == rv[t] && rs[t + s] < rs[t])) {
                    rv[t] = rv[t + s]; rc[t] = rc[t + s]; rs[t] = rs[t + s];
                }
            }
            __syncthreads();
        }
        if (t == 0) {
            idxfin[b * LL + l] = rs[0];
            candfin[b * LL + l] = rc[0];
            sv[rc[0]] = -INFINITY;
        }
        __syncthreads();
    }
}

// ===================== permute exact rows into [B,H,L,D] ====================
__global__ __launch_bounds__(256) void gatherperm_kernel(
    const float* __restrict__ kex, const float* __restrict__ vex,
    const int* __restrict__ candf,
    float* __restrict__ Ksp, float* __restrict__ Vsp)
{
    int i = blockIdx.x * 256 + threadIdx.x;
    int d = i & 63;
    int l = (i >> 6) & 63;
    int h = (i >> 12) & 15;
    int b = i >> 16;
    int cp = candf[b * LL + l];
    size_t src = ((size_t)b * NCAND + cp) * EE + h * 64 + d;
    Ksp[i] = kex[src];
    Vsp[i] = vex[src];
}

// ===================== attention (ctx -> plain fp16 fused) ==================
__global__ __launch_bounds__(64) void attn_kernel(
    const float* __restrict__ Q, const float* __restrict__ Ksp,
    const float* __restrict__ Vsp, float* __restrict__ w_out,
    __half* __restrict__ ctxh)
{
    __shared__ float Kt[64 * 64];
    __shared__ float Vt[64 * 64];
    __shared__ float sc[64 * 64];

    const int b = blockIdx.z, h = blockIdx.y, chunk = blockIdx.x;
    const int i = threadIdx.x;

    const float* Kg = Ksp + ((size_t)(b * HH + h) << 12);
    const float* Vg = Vsp + ((size_t)(b * HH + h) << 12);
    for (int j = i; j < 1024; j += 64) {
        ((float4*)Kt)[j] = ((const float4*)Kg)[j];
        ((float4*)Vt)[j] = ((const float4*)Vg)[j];
    }
    __syncthreads();

    const int s = chunk * 64 + i;
    const float* qp = Q + ((size_t)(b * SS + s)) * EE + h * 64;
    float4 q4[16];
    #pragma unroll
    for (int j = 0; j < 16; j++) q4[j] = ((const float4*)qp)[j];

    float mx = -INFINITY;
    #pragma unroll 4
    for (int l = 0; l < 64; l++) {
        const float4* kl = (const float4*)(Kt + l * 64);
        float acc = 0.f;
        #pragma unroll
        for (int j = 0; j < 16; j++) {
            float4 kv = kl[j];
            acc = fmaf(q4[j].x, kv.x, acc);
            acc = fmaf(q4[j].y, kv.y, acc);
            acc = fmaf(q4[j].z, kv.z, acc);
            acc = fmaf(q4[j].w, kv.w, acc);
        }
        acc *= 0.125f;
        sc[l * 64 + i] = acc;
        mx = fmaxf(mx, acc);
    }

    float sum = 0.f;
    #pragma unroll 4
    for (int l = 0; l < 64; l++) {
        float e = expf(sc[l * 64 + i] - mx);
        sc[l * 64 + i] = e;
        sum += e;
    }
    const float inv = 1.f / sum;

    float4 c4[16];
    #pragma unroll
    for (int j = 0; j < 16; j++) c4[j] = make_float4(0.f, 0.f, 0.f, 0.f);

    float* wp = w_out + ((size_t)((b * HH + h) * SS + s)) * LL;
    #pragma unroll 2
    for (int l4 = 0; l4 < 16; l4++) {
        float wls[4];
        #pragma unroll
        for (int jj = 0; jj < 4; jj++) {
            int l = l4 * 4 + jj;
            float wl = sc[l * 64 + i] * inv;
            wls[jj] = wl;
            const float4* vl = (const float4*)(Vt + l * 64);
            #pragma unroll
            for (int j = 0; j < 16; j++) {
                float4 vv = vl[j];
                c4[j].x = fmaf(wl, vv.x, c4[j].x);
                c4[j].y = fmaf(wl, vv.y, c4[j].y);
                c4[j].z = fmaf(wl, vv.z, c4[j].z);
                c4[j].w = fmaf(wl, vv.w, c4[j].w);
            }
        }
        *(float4*)(wp + l4 * 4) = make_float4(wls[0], wls[1], wls[2], wls[3]);
    }

    // fused fp16 ctx write
    __half* hp = ctxh + ((size_t)(b * SS + s)) * 1024 + h * 64;
    #pragma unroll
    for (int j = 0; j < 16; j++) {
        uint32_t h0 = (uint32_t)__half_as_ushort(__float2half(c4[j].x));
        uint32_t h1 = (uint32_t)__half_as_ushort(__float2half(c4[j].y));
        uint32_t h2 = (uint32_t)__half_as_ushort(__float2half(c4[j].z));
        uint32_t h3 = (uint32_t)__half_as_ushort(__float2half(c4[j].w));
        uint2 hv; hv.x = h0 | (h1 << 16); hv.y = h2 | (h3 << 16);
        *(uint2*)(hp + j * 4) = hv;
    }
}

// ===================== launch ===============================================
extern "C" void kernel_launch(void* const* d_in, const int* in_sizes, int n_in,
                              void* d_out, int out_size)
{
    const float* query = (const float*)d_in[0];
    const float* key   = (const float*)d_in[1];
    const float* value = (const float*)d_in[2];
    const float* Wq = (const float*)d_in[3];
    const float* bq = (const float*)d_in[4];
    const float* Wk = (const float*)d_in[5];
    const float* bk = (const float*)d_in[6];
    const float* Wv = (const float*)d_in[7];
    const float* bv = (const float*)d_in[8];
    const float* Wo = (const float*)d_in[9];
    const float* bo = (const float*)d_in[10];

    float* out  = (float*)d_out;
    float* wout = out + MSZ;

    float *pQ, *pSsq, *pScores, *pKex, *pVex, *pScex, *pKsp, *pVsp;
    __half *pAqh, *pAkh, *pWqh, *pWkh, *pWoh;
    int *pIdx96, *pIdxf, *pCandf;
    cudaGetSymbolAddress((void**)&pQ, g_Q);
    cudaGetSymbolAddress((void**)&pAqh, g_Aqh);
    cudaGetSymbolAddress((void**)&pAkh, g_Akh);
    cudaGetSymbolAddress((void**)&pWqh, g_Wqh);
    cudaGetSymbolAddress((void**)&pWkh, g_Wkh);
    cudaGetSymbolAddress((void**)&pWoh, g_Woh);
    cudaGetSymbolAddress((void**)&pSsq, g_ssq);
    cudaGetSymbolAddress((void**)&pScores, g_scores);
    cudaGetSymbolAddress((void**)&pIdx96, g_idx96);
    cudaGetSymbolAddress((void**)&pKex, g_kex);
    cudaGetSymbolAddress((void**)&pVex, g_vex);
    cudaGetSymbolAddress((void**)&pScex, g_scex);
    cudaGetSymbolAddress((void**)&pIdxf, g_idxf);
    cudaGetSymbolAddress((void**)&pCandf, g_candf);
    cudaGetSymbolAddress((void**)&pKsp, g_Ksp);
    cudaGetSymbolAddress((void**)&pVsp, g_Vsp);

    cudaFuncSetAttribute((void*)gemm_f16<0>, cudaFuncAttributeMaxDynamicSharedMemorySize, GEMM_SMEM);
    cudaFuncSetAttribute((void*)gemm_f16<1>, cudaFuncAttributeMaxDynamicSharedMemorySize, GEMM_SMEM);

    const int n4m = (int)(MSZ / 4);
    const int n4w = EE * EE / 4;
    dim3 ggrid(4, 256);

    // launches 1-5: conversions (puts Q GEMM at launch 6 for ncu -s 5)
    conv_f16<<<n4w / 256, 256>>>(Wq, pWqh, n4w);
    conv_f16<<<n4w / 256, 256>>>(Wk, pWkh, n4w);
    conv_f16<<<n4w / 256, 256>>>(Wo, pWoh, n4w);
    conv_f16<<<n4m / 256, 256>>>(query, pAqh, n4m);
    conv_f16<<<n4m / 256, 256>>>(key, pAkh, n4m);

    // Q = fp16(query) @ fp16(Wq)^T + bq
    gemm_f16<0><<<ggrid, 256, GEMM_SMEM>>>(pAqh, pWqh, bq, pQ);

    // K projection fused into per-(row,head) sum-of-squares (selection only)
    gemm_f16<1><<<ggrid, 256, GEMM_SMEM>>>(pAkh, pWkh, bk, pSsq);

    // scores -> top-96 candidates
    scores_ssq<<<MROWS / 256, 256>>>(pSsq, pScores);
    topk_kernel<<<BB, 1024>>>(pScores, pIdx96, NCAND);

    // exact fp32 K/V rows at candidates, exact scores, exact top-64
    dim3 pgrid(8, BB);
    project_rows<12><<<pgrid, 256>>>(key,   Wk, bk, pIdx96, NCAND, pKex);
    project_rows<12><<<pgrid, 256>>>(value, Wv, bv, pIdx96, NCAND, pVex);
    scores_kernel<<<(BB * NCAND) / 8, 256>>>(pKex, pScex);
    topk_refine_kernel<<<BB, 128>>>(pScex, pIdx96, pIdxf, pCandf);
    gatherperm_kernel<<<(BB * HH * LL * DD) / 256, 256>>>(pKex, pVex, pCandf, pKsp, pVsp);

    // attention (writes w + fp16 ctx into Aqh buffer)
    dim3 agrid(SS / 64, HH, BB);
    attn_kernel<<<agrid, 64>>>(pQ, pKsp, pVsp, wout, pAqh);

    // out = fp16(ctx) @ fp16(Wo)^T + bo
    gemm_f16<0><<<ggrid, 256, GEMM_SMEM>>>(pAqh, pWoh, bo, out);
}

// round 11
// speedup vs baseline: 2.6624x; 1.1494x over previous
#include <cuda_runtime.h>
#include <cuda_fp16.h>
#include <math.h>
#include <stdint.h>

#define BB 4
#define SS 8192
#define EE 1024
#define HH 16
#define DD 64
#define LL 64
#define NCAND 96
#define NCMAX 128
#define MROWS (BB * SS)
#define MSZ   ((size_t)MROWS * EE)

// ===================== scratch ==============================================
__device__ __half g_Qh[MSZ];          // projected q, fp16
__device__ __half g_Aqh[MSZ];         // query fp16 input; later reused for ctx fp16
__device__ __half g_Akh[MSZ];         // key fp16 input
__device__ __half g_Wqh[EE * EE];
__device__ __half g_Wkh[EE * EE];
__device__ __half g_Woh[EE * EE];
__device__ float g_ssq[MROWS * HH];
__device__ float g_scores[BB * SS];
__device__ int   g_idxc[BB * NCMAX];
__device__ int   g_ncand[BB];
__device__ float g_kex[BB * NCMAX * EE];
__device__ float g_vex[BB * NCMAX * EE];
__device__ float g_scex[BB * NCMAX];
__device__ int   g_idxf[BB * LL];
__device__ int   g_candf[BB * LL];
__device__ float g_Ksp[BB * HH * LL * DD];
__device__ float g_Vsp[BB * HH * LL * DD];

// ===================== small PTX helpers ====================================
__device__ __forceinline__ uint32_t smem_u32(const void* p) {
    uint32_t a;
    asm("{ .reg .u64 t; cvta.to.shared.u64 t, %1; cvt.u32.u64 %0, t; }" : "=r"(a) : "l"(p));
    return a;
}
__device__ __forceinline__ void cp16(uint32_t dst, const void* src) {
    asm volatile("cp.async.cg.shared.global [%0], [%1], 16;" :: "r"(dst), "l"(src));
}
#define CP_COMMIT() asm volatile("cp.async.commit_group;" ::: "memory")
#define CP_WAIT1()  asm volatile("cp.async.wait_group 1;" ::: "memory")
__device__ __forceinline__ void ldm_x4(uint32_t* r, uint32_t addr) {
    asm volatile("ldmatrix.sync.aligned.m8n8.x4.shared.b16 {%0,%1,%2,%3}, [%4];"
                 : "=r"(r[0]), "=r"(r[1]), "=r"(r[2]), "=r"(r[3]) : "r"(addr));
}
#define MMAF16(d, a, b0, b1) \
    asm volatile("mma.sync.aligned.m16n8k16.row.col.f32.f16.f16.f32 " \
        "{%0,%1,%2,%3}, {%4,%5,%6,%7}, {%8,%9}, {%0,%1,%2,%3};" \
        : "+f"((d)[0]), "+f"((d)[1]), "+f"((d)[2]), "+f"((d)[3]) \
        : "r"((a)[0]), "r"((a)[1]), "r"((a)[2]), "r"((a)[3]), \
          "r"(b0), "r"(b1))

// ===================== fp32 -> fp16 conversion ===============================
__global__ __launch_bounds__(256) void conv_f16(
    const float* __restrict__ x, __half* __restrict__ h, int n4)
{
    int i = blockIdx.x * 256 + threadIdx.x;
    if (i >= n4) return;
    float4 v = ((const float4*)x)[i];
    uint32_t h0 = (uint32_t)__half_as_ushort(__float2half(v.x));
    uint32_t h1 = (uint32_t)__half_as_ushort(__float2half(v.y));
    uint32_t h2 = (uint32_t)__half_as_ushort(__float2half(v.z));
    uint32_t h3 = (uint32_t)__half_as_ushort(__float2half(v.w));
    uint2 hp; hp.x = h0 | (h1 << 16); hp.y = h2 | (h3 << 16);
    ((uint2*)h)[i] = hp;
}

// ===================== fp16 GEMM =============================================
// EPI=0: fp32 C + bias. EPI=1: per-(row,head) sum-of-squares. EPI=2: fp16 C + bias.
#define GSTAGE 49152u
#define GEMM_SMEM (3 * 49152)

template<int EPI>
__global__ __launch_bounds__(256) void gemm_f16(
    const __half* __restrict__ A, const __half* __restrict__ W,
    const float* __restrict__ bias, void* __restrict__ Cv)
{
    extern __shared__ __align__(128) char dsm[];
    const uint32_t sbase = smem_u32(dsm);
    const int tid  = threadIdx.x;
    const int lane = tid & 31;
    const int wid  = tid >> 5;
    const int bm = blockIdx.y * 128;
    const int bn = blockIdx.x * 256;
    const int m0 = (wid & 1) * 64;
    const int n0 = (wid >> 1) * 64;
    const int qrow = lane >> 2;
    const int qk   = (lane & 3) * 2;
    const int lrow  = lane & 7;
    const int phase = lane >> 3;
    const int g_c  = tid & 7;
    const int g_r0 = tid >> 3;

    float c[4][8][4];
    #pragma unroll
    for (int mt = 0; mt < 4; mt++)
        #pragma unroll
        for (int nt = 0; nt < 8; nt++)
            #pragma unroll
            for (int q = 0; q < 4; q++) c[mt][nt][q] = 0.f;

    auto load_tile = [&](int kt) {
        if (kt < 16) {
            const uint32_t sA = sbase + (uint32_t)(kt % 3) * GSTAGE;
            const uint32_t sB = sA + 16384u;
            const int kk = kt << 6;
            #pragma unroll
            for (int i = 0; i < 4; i++) {
                int row = g_r0 + i * 32;
                uint32_t off = (uint32_t)(row * 128 + ((g_c ^ (row & 7)) << 4));
                cp16(sA + off, A + (size_t)(bm + row) * 1024 + kk + g_c * 8);
            }
            #pragma unroll
            for (int i = 0; i < 8; i++) {
                int row = g_r0 + i * 32;
                uint32_t off = (uint32_t)(row * 128 + ((g_c ^ (row & 7)) << 4));
                cp16(sB + off, W + (size_t)(bn + row) * 1024 + kk + g_c * 8);
            }
        }
        CP_COMMIT();
    };

    load_tile(0);
    load_tile(1);

    for (int kt = 0; kt < 16; kt++) {
        CP_WAIT1();
        __syncthreads();
        load_tile(kt + 2);
        const uint32_t aB = sbase + (uint32_t)(kt % 3) * GSTAGE;
        const uint32_t bB = aB + 16384u;
        #pragma unroll
        for (int ks = 0; ks < 4; ks++) {
            const int c0 = ks * 2;
            uint32_t a[4][4];
            #pragma unroll
            for (int mt = 0; mt < 4; mt++) {
                int row = m0 + mt * 16 + (phase & 1) * 8 + lrow;
                int ch  = c0 + (phase >> 1);
                ldm_x4(a[mt], aB + (uint32_t)(row * 128 + ((ch ^ (row & 7)) << 4)));
            }
            uint32_t bf[4][4];
            #pragma unroll
            for (int ng = 0; ng < 4; ng++) {
                int row = n0 + ng * 16 + (phase >> 1) * 8 + lrow;
                int ch  = c0 + (phase & 1);
                ldm_x4(bf[ng], bB + (uint32_t)(row * 128 + ((ch ^ (row & 7)) << 4)));
            }
            #pragma unroll
            for (int nt = 0; nt < 8; nt++) {
                uint32_t b0 = bf[nt >> 1][(nt & 1) * 2];
                uint32_t b1 = bf[nt >> 1][(nt & 1) * 2 + 1];
                #pragma unroll
                for (int mt = 0; mt < 4; mt++)
                    MMAF16(c[mt][nt], a[mt], b0, b1);
            }
        }
        __syncthreads();
    }

    if (EPI == 0) {
        float* C = (float*)Cv;
        #pragma unroll
        for (int mt = 0; mt < 4; mt++) {
            #pragma unroll
            for (int nt = 0; nt < 8; nt++) {
                int r0  = bm + m0 + mt * 16 + qrow;
                int col = bn + n0 + nt * 8 + qk;
                float2 bv = *(const float2*)(bias + col);
                float2 o0, o1;
                o0.x = c[mt][nt][0] + bv.x; o0.y = c[mt][nt][1] + bv.y;
                o1.x = c[mt][nt][2] + bv.x; o1.y = c[mt][nt][3] + bv.y;
                *(float2*)(C + (size_t)r0 * 1024 + col) = o0;
                *(float2*)(C + (size_t)(r0 + 8) * 1024 + col) = o1;
            }
        }
    } else if (EPI == 1) {
        float* C = (float*)Cv;
        const int head = (bn + n0) >> 6;
        #pragma unroll
        for (int mt = 0; mt < 4; mt++) {
            float s0 = 0.f, s1 = 0.f;
            #pragma unroll
            for (int nt = 0; nt < 8; nt++) {
                int col = bn + n0 + nt * 8 + qk;
                float2 bv = *(const float2*)(bias + col);
                float v0 = c[mt][nt][0] + bv.x, v1 = c[mt][nt][1] + bv.y;
                float v2 = c[mt][nt][2] + bv.x, v3 = c[mt][nt][3] + bv.y;
                s0 += v0 * v0 + v1 * v1;
                s1 += v2 * v2 + v3 * v3;
            }
            s0 += __shfl_xor_sync(0xffffffffu, s0, 1);
            s0 += __shfl_xor_sync(0xffffffffu, s0, 2);
            s1 += __shfl_xor_sync(0xffffffffu, s1, 1);
            s1 += __shfl_xor_sync(0xffffffffu, s1, 2);
            if ((lane & 3) == 0) {
                int r = bm + m0 + mt * 16 + qrow;
                C[(size_t)r * HH + head] = s0;
                C[(size_t)(r + 8) * HH + head] = s1;
            }
        }
    } else {
        __half* C = (__half*)Cv;
        #pragma unroll
        for (int mt = 0; mt < 4; mt++) {
            #pragma unroll
            for (int nt = 0; nt < 8; nt++) {
                int r0  = bm + m0 + mt * 16 + qrow;
                int col = bn + n0 + nt * 8 + qk;
                float2 bv = *(const float2*)(bias + col);
                __half2 h0 = __floats2half2_rn(c[mt][nt][0] + bv.x, c[mt][nt][1] + bv.y);
                __half2 h1 = __floats2half2_rn(c[mt][nt][2] + bv.x, c[mt][nt][3] + bv.y);
                *(__half2*)(C + (size_t)r0 * 1024 + col) = h0;
                *(__half2*)(C + (size_t)(r0 + 8) * 1024 + col) = h1;
            }
        }
    }
}

// ===================== scores from ssq ======================================
__global__ __launch_bounds__(256) void scores_ssq(
    const float* __restrict__ ssq, float* __restrict__ scores)
{
    int row = blockIdx.x * 256 + threadIdx.x;
    const float* sp = ssq + (size_t)row * HH;
    float acc = 0.f;
    #pragma unroll
    for (int h = 0; h < HH; h++) acc += sqrtf(sp[h]);
    scores[row] = acc * (1.f / 16.f);
}

// ===================== scores of fp32 rows (for candidates) =================
__global__ __launch_bounds__(256) void scores_kernel(
    const float* __restrict__ Km, float* __restrict__ scores)
{
    int row  = blockIdx.x * 8 + (threadIdx.x >> 5);
    int lane = threadIdx.x & 31;
    const float* kr = Km + (size_t)row * EE;
    float acc = 0.f;
    #pragma unroll
    for (int h = 0; h < HH; h++) {
        float x0 = kr[h * 64 + lane];
        float x1 = kr[h * 64 + 32 + lane];
        float ss = x0 * x0 + x1 * x1;
        #pragma unroll
        for (int o = 16; o > 0; o >>= 1)
            ss += __shfl_xor_sync(0xffffffffu, ss, o);
        acc += sqrtf(ss);
    }
    if (lane == 0) scores[row] = acc * (1.f / 16.f);
}

// ===================== radix-select top-96 (superset, capped 128) ===========
// Scores are strictly positive -> uint bit pattern is order-preserving.
__global__ __launch_bounds__(256) void topk_radix(
    const float* __restrict__ scores, int* __restrict__ idxout,
    int* __restrict__ ncand)
{
    __shared__ int hist[256];
    __shared__ unsigned s_prefix;
    __shared__ int s_remaining;
    __shared__ int s_cnt;
    const int b = blockIdx.x, t = threadIdx.x;
    const float* sp = scores + b * SS;

    if (t == 0) { s_prefix = 0; s_remaining = NCAND; s_cnt = 0; }
    __syncthreads();

    for (int round = 0; round < 4; round++) {
        const int shift = 24 - 8 * round;
        hist[t] = 0;
        __syncthreads();
        const unsigned pfx = s_prefix;
        for (int i = t; i < SS; i += 256) {
            unsigned key = __float_as_uint(sp[i]);
            bool match = (round == 0) || (((key ^ pfx) >> (shift + 8)) == 0);
            if (match) atomicAdd(&hist[(key >> shift) & 255], 1);
        }
        __syncthreads();
        if (t == 0) {
            int rem = s_remaining, cum = 0, bin = 255;
            for (; bin > 0; bin--) {
                cum += hist[bin];
                if (cum >= rem) break;
            }
            if (cum < rem) cum += hist[0];   // bin==0 fallthrough
            s_remaining = rem - (cum - hist[bin]);
            s_prefix = pfx | ((unsigned)bin << shift);
        }
        __syncthreads();
    }
    const unsigned thresh = s_prefix;
    for (int i = t; i < SS; i += 256) {
        unsigned key = __float_as_uint(sp[i]);
        if (key >= thresh) {
            int pos = atomicAdd(&s_cnt, 1);
            if (pos < NCMAX) idxout[b * NCMAX + pos] = i;
        }
    }
    __syncthreads();
    int c = s_cnt < NCMAX ? s_cnt : NCMAX;
    if (t == 0) ncand[b] = c;
    for (int i = c + t; i < NCMAX; i += 256) idxout[b * NCMAX + i] = 0;  // safe pad
}

// ===================== exact fp32 projection (K and V fused via z) ==========
template<int CPT>
__global__ __launch_bounds__(256) void project_rows2(
    const float* __restrict__ X0, const float* __restrict__ W0,
    const float* __restrict__ b0, float* __restrict__ o0,
    const float* __restrict__ X1, const float* __restrict__ W1,
    const float* __restrict__ b1, float* __restrict__ o1,
    const int* __restrict__ idx)
{
    __shared__ float xs[NCMAX * 32];
    __shared__ float ws[32 * 128];
    const int b = blockIdx.y;
    const int e0 = blockIdx.x * 128;
    const float* X  = blockIdx.z ? X1 : X0;
    const float* Wt = blockIdx.z ? W1 : W0;
    const float* bias = blockIdx.z ? b1 : b0;
    float* outp = blockIdx.z ? o1 : o0;
    const int t = threadIdx.x, tx = t & 31, ty = t >> 5;

    float acc[CPT][4];
    #pragma unroll
    for (int c = 0; c < CPT; c++)
        #pragma unroll
        for (int j = 0; j < 4; j++) acc[c][j] = 0.f;

    for (int kt = 0; kt < EE; kt += 32) {
        __syncthreads();
        for (int u = t; u < NCMAX * 8; u += 256) {
            int cand = u >> 3, c4 = u & 7;
            int s = idx[b * NCMAX + cand];
            float4 v = *(const float4*)(X + ((size_t)(b * SS + s)) * EE + kt + c4 * 4);
            *(float4*)(xs + cand * 32 + c4 * 4) = v;
        }
        for (int u = t; u < 1024; u += 256) {
            int e = u >> 3, c4 = u & 7;
            float4 v = *(const float4*)(Wt + (size_t)(e0 + e) * EE + kt + c4 * 4);
            ws[(c4 * 4 + 0) * 128 + e] = v.x;
            ws[(c4 * 4 + 1) * 128 + e] = v.y;
            ws[(c4 * 4 + 2) * 128 + e] = v.z;
            ws[(c4 * 4 + 3) * 128 + e] = v.w;
        }
        __syncthreads();
        #pragma unroll 8
        for (int k = 0; k < 32; k++) {
            float wv[4];
            #pragma unroll
            for (int j = 0; j < 4; j++) wv[j] = ws[k * 128 + tx * 4 + j];
            #pragma unroll
            for (int c = 0; c < CPT; c++) {
                float a = xs[(ty * CPT + c) * 32 + k];
                #pragma unroll
                for (int j = 0; j < 4; j++) acc[c][j] = fmaf(a, wv[j], acc[c][j]);
            }
        }
    }
    #pragma unroll
    for (int c = 0; c < CPT; c++) {
        int cand = ty * CPT + c;
        #pragma unroll
        for (int j = 0; j < 4; j++) {
            int e = e0 + tx * 4 + j;
            outp[((size_t)b * NCMAX + cand) * EE + e] = acc[c][j] + bias[e];
        }
    }
}

// ===================== exact top-64 among candidates ========================
__global__ __launch_bounds__(128) void topk_refine_kernel(
    const float* __restrict__ scex, const int* __restrict__ idxc,
    const int* __restrict__ ncand,
    int* __restrict__ idxfin, int* __restrict__ candfin)
{
    __shared__ float sv[NCMAX];
    __shared__ int   si[NCMAX];
    __shared__ float rv[128];
    __shared__ int   rc[128];
    __shared__ int   rs[128];
    const int b = blockIdx.x, t = threadIdx.x;
    const int cnt = ncand[b];
    sv[t] = (t < cnt) ? scex[b * NCMAX + t] : -INFINITY;
    si[t] = (t < cnt) ? idxc[b * NCMAX + t] : 0x7fffffff;
    __syncthreads();
    for (int l = 0; l < LL; l++) {
        rv[t] = sv[t]; rc[t] = t; rs[t] = si[t];
        __syncthreads();
        for (int s = 64; s > 0; s >>= 1) {
            if (t < s) {
                if (rv[t + s] > rv[t] || (rv[t + s] == rv[t] && rs[t + s] < rs[t])) {
                    rv[t] = rv[t + s]; rc[t] = rc[t + s]; rs[t] = rs[t + s];
                }
            }
            __syncthreads();
        }
        if (t == 0) {
            idxfin[b * LL + l] = rs[0];
            candfin[b * LL + l] = rc[0];
            sv[rc[0]] = -INFINITY;
        }
        __syncthreads();
    }
}

// ===================== permute exact rows into [B,H,L,D] ====================
__global__ __launch_bounds__(256) void gatherperm_kernel(
    const float* __restrict__ kex, const float* __restrict__ vex,
    const int* __restrict__ candf,
    float* __restrict__ Ksp, float* __restrict__ Vsp)
{
    int i = blockIdx.x * 256 + threadIdx.x;
    int d = i & 63;
    int l = (i >> 6) & 63;
    int h = (i >> 12) & 15;
    int b = i >> 16;
    int cp = candf[b * LL + l];
    size_t src = ((size_t)b * NCMAX + cp) * EE + h * 64 + d;
    Ksp[i] = kex[src];
    Vsp[i] = vex[src];
}

// ===================== attention (fp16 Q in, fp16 ctx out) ==================
__global__ __launch_bounds__(64) void attn_kernel(
    const __half* __restrict__ Qh, const float* __restrict__ Ksp,
    const float* __restrict__ Vsp, float* __restrict__ w_out,
    __half* __restrict__ ctxh)
{
    __shared__ float Kt[64 * 64];
    __shared__ float Vt[64 * 64];
    __shared__ float sc[64 * 64];

    const int b = blockIdx.z, h = blockIdx.y, chunk = blockIdx.x;
    const int i = threadIdx.x;

    const float* Kg = Ksp + ((size_t)(b * HH + h) << 12);
    const float* Vg = Vsp + ((size_t)(b * HH + h) << 12);
    for (int j = i; j < 1024; j += 64) {
        ((float4*)Kt)[j] = ((const float4*)Kg)[j];
        ((float4*)Vt)[j] = ((const float4*)Vg)[j];
    }
    __syncthreads();

    const int s = chunk * 64 + i;
    const __half2* qp = (const __half2*)(Qh + ((size_t)(b * SS + s)) * EE + h * 64);
    float4 q4[16];
    #pragma unroll
    for (int j = 0; j < 16; j++) {
        float2 lo = __half22float2(qp[2 * j]);
        float2 hi = __half22float2(qp[2 * j + 1]);
        q4[j] = make_float4(lo.x, lo.y, hi.x, hi.y);
    }

    float mx = -INFINITY;
    #pragma unroll 4
    for (int l = 0; l < 64; l++) {
        const float4* kl = (const float4*)(Kt + l * 64);
        float acc = 0.f;
        #pragma unroll
        for (int j = 0; j < 16; j++) {
            float4 kv = kl[j];
            acc = fmaf(q4[j].x, kv.x, acc);
            acc = fmaf(q4[j].y, kv.y, acc);
            acc = fmaf(q4[j].z, kv.z, acc);
            acc = fmaf(q4[j].w, kv.w, acc);
        }
        acc *= 0.125f;
        sc[l * 64 + i] = acc;
        mx = fmaxf(mx, acc);
    }

    float sum = 0.f;
    #pragma unroll 4
    for (int l = 0; l < 64; l++) {
        float e = expf(sc[l * 64 + i] - mx);
        sc[l * 64 + i] = e;
        sum += e;
    }
    const float inv = 1.f / sum;

    float4 c4[16];
    #pragma unroll
    for (int j = 0; j < 16; j++) c4[j] = make_float4(0.f, 0.f, 0.f, 0.f);

    float* wp = w_out + ((size_t)((b * HH + h) * SS + s)) * LL;
    #pragma unroll 2
    for (int l4 = 0; l4 < 16; l4++) {
        float wls[4];
        #pragma unroll
        for (int jj = 0; jj < 4; jj++) {
            int l = l4 * 4 + jj;
            float wl = sc[l * 64 + i] * inv;
            wls[jj] = wl;
            const float4* vl = (const float4*)(Vt + l * 64);
            #pragma unroll
            for (int j = 0; j < 16; j++) {
                float4 vv = vl[j];
                c4[j].x = fmaf(wl, vv.x, c4[j].x);
                c4[j].y = fmaf(wl, vv.y, c4[j].y);
                c4[j].z = fmaf(wl, vv.z, c4[j].z);
                c4[j].w = fmaf(wl, vv.w, c4[j].w);
            }
        }
        *(float4*)(wp + l4 * 4) = make_float4(wls[0], wls[1], wls[2], wls[3]);
    }

    __half* hp = ctxh + ((size_t)(b * SS + s)) * 1024 + h * 64;
    #pragma unroll
    for (int j = 0; j < 16; j++) {
        __half2 h0 = __floats2half2_rn(c4[j].x, c4[j].y);
        __half2 h1 = __floats2half2_rn(c4[j].z, c4[j].w);
        *(__half2*)(hp + j * 4) = h0;
        *(__half2*)(hp + j * 4 + 2) = h1;
    }
}

// ===================== launch ===============================================
extern "C" void kernel_launch(void* const* d_in, const int* in_sizes, int n_in,
                              void* d_out, int out_size)
{
    const float* query = (const float*)d_in[0];
    const float* key   = (const float*)d_in[1];
    const float* value = (const float*)d_in[2];
    const float* Wq = (const float*)d_in[3];
    const float* bq = (const float*)d_in[4];
    const float* Wk = (const float*)d_in[5];
    const float* bk = (const float*)d_in[6];
    const float* Wv = (const float*)d_in[7];
    const float* bv = (const float*)d_in[8];
    const float* Wo = (const float*)d_in[9];
    const float* bo = (const float*)d_in[10];

    float* out  = (float*)d_out;
    float* wout = out + MSZ;

    float *pSsq, *pScores, *pKex, *pVex, *pScex, *pKsp, *pVsp;
    __half *pQh, *pAqh, *pAkh, *pWqh, *pWkh, *pWoh;
    int *pIdxc, *pNcand, *pIdxf, *pCandf;
    cudaGetSymbolAddress((void**)&pQh, g_Qh);
    cudaGetSymbolAddress((void**)&pAqh, g_Aqh);
    cudaGetSymbolAddress((void**)&pAkh, g_Akh);
    cudaGetSymbolAddress((void**)&pWqh, g_Wqh);
    cudaGetSymbolAddress((void**)&pWkh, g_Wkh);
    cudaGetSymbolAddress((void**)&pWoh, g_Woh);
    cudaGetSymbolAddress((void**)&pSsq, g_ssq);
    cudaGetSymbolAddress((void**)&pScores, g_scores);
    cudaGetSymbolAddress((void**)&pIdxc, g_idxc);
    cudaGetSymbolAddress((void**)&pNcand, g_ncand);
    cudaGetSymbolAddress((void**)&pKex, g_kex);
    cudaGetSymbolAddress((void**)&pVex, g_vex);
    cudaGetSymbolAddress((void**)&pScex, g_scex);
    cudaGetSymbolAddress((void**)&pIdxf, g_idxf);
    cudaGetSymbolAddress((void**)&pCandf, g_candf);
    cudaGetSymbolAddress((void**)&pKsp, g_Ksp);
    cudaGetSymbolAddress((void**)&pVsp, g_Vsp);

    cudaFuncSetAttribute((void*)gemm_f16<0>, cudaFuncAttributeMaxDynamicSharedMemorySize, GEMM_SMEM);
    cudaFuncSetAttribute((void*)gemm_f16<1>, cudaFuncAttributeMaxDynamicSharedMemorySize, GEMM_SMEM);
    cudaFuncSetAttribute((void*)gemm_f16<2>, cudaFuncAttributeMaxDynamicSharedMemorySize, GEMM_SMEM);

    const int n4m = (int)(MSZ / 4);
    const int n4w = EE * EE / 4;
    dim3 ggrid(4, 256);

    // launches 1-4: conversions; launch 5 = Q GEMM (ncu captures 5th)
    conv_f16<<<n4w / 256, 256>>>(Wq, pWqh, n4w);
    conv_f16<<<n4w / 256, 256>>>(Wk, pWkh, n4w);
    conv_f16<<<n4w / 256, 256>>>(Wo, pWoh, n4w);
    conv_f16<<<n4m / 256, 256>>>(query, pAqh, n4m);

    // Q = fp16(query) @ fp16(Wq)^T + bq  -> fp16
    gemm_f16<2><<<ggrid, 256, GEMM_SMEM>>>(pAqh, pWqh, bq, pQh);

    conv_f16<<<n4m / 256, 256>>>(key, pAkh, n4m);

    // K projection fused into per-(row,head) sum-of-squares (selection only)
    gemm_f16<1><<<ggrid, 256, GEMM_SMEM>>>(pAkh, pWkh, bk, pSsq);

    // scores -> radix-select top-96 superset (<=128 candidates)
    scores_ssq<<<MROWS / 256, 256>>>(pSsq, pScores);
    topk_radix<<<BB, 256>>>(pScores, pIdxc, pNcand);

    // exact fp32 K+V rows at candidates (fused), exact scores, exact top-64
    dim3 pgrid(8, BB, 2);
    project_rows2<16><<<pgrid, 256>>>(key, Wk, bk, pKex, value, Wv, bv, pVex, pIdxc);
    scores_kernel<<<(BB * NCMAX) / 8, 256>>>(pKex, pScex);
    topk_refine_kernel<<<BB, 128>>>(pScex, pIdxc, pNcand, pIdxf, pCandf);
    gatherperm_kernel<<<(BB * HH * LL * DD) / 256, 256>>>(pKex, pVex, pCandf, pKsp, pVsp);

    // attention (fp16 Q in, writes w + fp16 ctx into Aqh)
    dim3 agrid(SS / 64, HH, BB);
    attn_kernel<<<agrid, 64>>>(pQh, pKsp, pVsp, wout, pAqh);

    // out = fp16(ctx) @ fp16(Wo)^T + bo
    gemm_f16<0><<<ggrid, 256, GEMM_SMEM>>>(pAqh, pWoh, bo, out);
}

// round 12
// speedup vs baseline: 3.6697x; 1.3784x over previous
#include <cuda_runtime.h>
#include <cuda_fp16.h>
#include <math.h>
#include <stdint.h>

#define BB 4
#define SS 8192
#define EE 1024
#define HH 16
#define DD 64
#define LL 64
#define NCAND 96
#define NCMAX 128
#define MROWS (BB * SS)
#define MSZ   ((size_t)MROWS * EE)

// ===================== scratch ==============================================
__device__ __half g_Qh[MSZ];          // projected q, fp16
__device__ __half g_Aqh[MSZ];         // query fp16 input; later reused for ctx fp16
__device__ __half g_Akh[MSZ];         // key fp16 input
__device__ __half g_Wqh[EE * EE];
__device__ __half g_Wkh[EE * EE];
__device__ __half g_Woh[EE * EE];
__device__ float g_ssq[MROWS * HH];
__device__ float g_scores[BB * SS];
__device__ int   g_idxc[BB * NCMAX];
__device__ int   g_ncand[BB];
__device__ float g_kex[BB * NCMAX * EE];
__device__ float g_vex[BB * NCMAX * EE];
__device__ float g_scex[BB * NCMAX];
__device__ int   g_idxf[BB * LL];
__device__ int   g_candf[BB * LL];
__device__ __half g_Ksph[BB * HH * LL * DD];   // [b,h,l,d] fp16
__device__ __half g_Vspt[BB * HH * DD * LL];   // [b,h,d,l] fp16 (transposed)

// ===================== small PTX helpers ====================================
__device__ __forceinline__ uint32_t smem_u32(const void* p) {
    uint32_t a;
    asm("{ .reg .u64 t; cvta.to.shared.u64 t, %1; cvt.u32.u64 %0, t; }" : "=r"(a) : "l"(p));
    return a;
}
__device__ __forceinline__ void cp16(uint32_t dst, const void* src) {
    asm volatile("cp.async.cg.shared.global [%0], [%1], 16;" :: "r"(dst), "l"(src));
}
#define CP_COMMIT() asm volatile("cp.async.commit_group;" ::: "memory")
#define CP_WAIT1()  asm volatile("cp.async.wait_group 1;" ::: "memory")
#define CP_WAIT0()  asm volatile("cp.async.wait_group 0;" ::: "memory")
__device__ __forceinline__ void ldm_x4(uint32_t* r, uint32_t addr) {
    asm volatile("ldmatrix.sync.aligned.m8n8.x4.shared.b16 {%0,%1,%2,%3}, [%4];"
                 : "=r"(r[0]), "=r"(r[1]), "=r"(r[2]), "=r"(r[3]) : "r"(addr));
}
#define MMAF16(d, a, b0, b1) \
    asm volatile("mma.sync.aligned.m16n8k16.row.col.f32.f16.f16.f32 " \
        "{%0,%1,%2,%3}, {%4,%5,%6,%7}, {%8,%9}, {%0,%1,%2,%3};" \
        : "+f"((d)[0]), "+f"((d)[1]), "+f"((d)[2]), "+f"((d)[3]) \
        : "r"((a)[0]), "r"((a)[1]), "r"((a)[2]), "r"((a)[3]), \
          "r"(b0), "r"(b1))
__device__ __forceinline__ uint32_t packh2(float a, float b) {
    __half2 h = __floats2half2_rn(a, b);
    return *(uint32_t*)&h;
}

// ===================== fp32 -> fp16 conversion ===============================
__global__ __launch_bounds__(256) void conv_f16(
    const float* __restrict__ x, __half* __restrict__ h, int n4)
{
    int i = blockIdx.x * 256 + threadIdx.x;
    if (i >= n4) return;
    float4 v = ((const float4*)x)[i];
    uint32_t h0 = (uint32_t)__half_as_ushort(__float2half(v.x));
    uint32_t h1 = (uint32_t)__half_as_ushort(__float2half(v.y));
    uint32_t h2 = (uint32_t)__half_as_ushort(__float2half(v.z));
    uint32_t h3 = (uint32_t)__half_as_ushort(__float2half(v.w));
    uint2 hp; hp.x = h0 | (h1 << 16); hp.y = h2 | (h3 << 16);
    ((uint2*)h)[i] = hp;
}

// ===================== fp16 GEMM =============================================
// EPI=0: fp32 C + bias. EPI=1: per-(row,head) ssq. EPI=2: fp16 C + bias.
#define GSTAGE 49152u
#define GEMM_SMEM (3 * 49152)

template<int EPI>
__global__ __launch_bounds__(256) void gemm_f16(
    const __half* __restrict__ A, const __half* __restrict__ W,
    const float* __restrict__ bias, void* __restrict__ Cv)
{
    extern __shared__ __align__(128) char dsm[];
    const uint32_t sbase = smem_u32(dsm);
    const int tid  = threadIdx.x;
    const int lane = tid & 31;
    const int wid  = tid >> 5;
    const int bm = blockIdx.y * 128;
    const int bn = blockIdx.x * 256;
    const int m0 = (wid & 1) * 64;
    const int n0 = (wid >> 1) * 64;
    const int qrow = lane >> 2;
    const int qk   = (lane & 3) * 2;
    const int lrow  = lane & 7;
    const int phase = lane >> 3;
    const int g_c  = tid & 7;
    const int g_r0 = tid >> 3;

    float c[4][8][4];
    #pragma unroll
    for (int mt = 0; mt < 4; mt++)
        #pragma unroll
        for (int nt = 0; nt < 8; nt++)
            #pragma unroll
            for (int q = 0; q < 4; q++) c[mt][nt][q] = 0.f;

    auto load_tile = [&](int kt) {
        if (kt < 16) {
            const uint32_t sA = sbase + (uint32_t)(kt % 3) * GSTAGE;
            const uint32_t sB = sA + 16384u;
            const int kk = kt << 6;
            #pragma unroll
            for (int i = 0; i < 4; i++) {
                int row = g_r0 + i * 32;
                uint32_t off = (uint32_t)(row * 128 + ((g_c ^ (row & 7)) << 4));
                cp16(sA + off, A + (size_t)(bm + row) * 1024 + kk + g_c * 8);
            }
            #pragma unroll
            for (int i = 0; i < 8; i++) {
                int row = g_r0 + i * 32;
                uint32_t off = (uint32_t)(row * 128 + ((g_c ^ (row & 7)) << 4));
                cp16(sB + off, W + (size_t)(bn + row) * 1024 + kk + g_c * 8);
            }
        }
        CP_COMMIT();
    };

    load_tile(0);
    load_tile(1);

    for (int kt = 0; kt < 16; kt++) {
        CP_WAIT1();
        __syncthreads();
        load_tile(kt + 2);
        const uint32_t aB = sbase + (uint32_t)(kt % 3) * GSTAGE;
        const uint32_t bB = aB + 16384u;
        #pragma unroll
        for (int ks = 0; ks < 4; ks++) {
            const int c0 = ks * 2;
            uint32_t a[4][4];
            #pragma unroll
            for (int mt = 0; mt < 4; mt++) {
                int row = m0 + mt * 16 + (phase & 1) * 8 + lrow;
                int ch  = c0 + (phase >> 1);
                ldm_x4(a[mt], aB + (uint32_t)(row * 128 + ((ch ^ (row & 7)) << 4)));
            }
            uint32_t bf[4][4];
            #pragma unroll
            for (int ng = 0; ng < 4; ng++) {
                int row = n0 + ng * 16 + (phase >> 1) * 8 + lrow;
                int ch  = c0 + (phase & 1);
                ldm_x4(bf[ng], bB + (uint32_t)(row * 128 + ((ch ^ (row & 7)) << 4)));
            }
            #pragma unroll
            for (int nt = 0; nt < 8; nt++) {
                uint32_t b0 = bf[nt >> 1][(nt & 1) * 2];
                uint32_t b1 = bf[nt >> 1][(nt & 1) * 2 + 1];
                #pragma unroll
                for (int mt = 0; mt < 4; mt++)
                    MMAF16(c[mt][nt], a[mt], b0, b1);
            }
        }
        __syncthreads();
    }

    if (EPI == 0) {
        float* C = (float*)Cv;
        #pragma unroll
        for (int mt = 0; mt < 4; mt++) {
            #pragma unroll
            for (int nt = 0; nt < 8; nt++) {
                int r0  = bm + m0 + mt * 16 + qrow;
                int col = bn + n0 + nt * 8 + qk;
                float2 bv = *(const float2*)(bias + col);
                float2 o0, o1;
                o0.x = c[mt][nt][0] + bv.x; o0.y = c[mt][nt][1] + bv.y;
                o1.x = c[mt][nt][2] + bv.x; o1.y = c[mt][nt][3] + bv.y;
                *(float2*)(C + (size_t)r0 * 1024 + col) = o0;
                *(float2*)(C + (size_t)(r0 + 8) * 1024 + col) = o1;
            }
        }
    } else if (EPI == 1) {
        float* C = (float*)Cv;
        const int head = (bn + n0) >> 6;
        #pragma unroll
        for (int mt = 0; mt < 4; mt++) {
            float s0 = 0.f, s1 = 0.f;
            #pragma unroll
            for (int nt = 0; nt < 8; nt++) {
                int col = bn + n0 + nt * 8 + qk;
                float2 bv = *(const float2*)(bias + col);
                float v0 = c[mt][nt][0] + bv.x, v1 = c[mt][nt][1] + bv.y;
                float v2 = c[mt][nt][2] + bv.x, v3 = c[mt][nt][3] + bv.y;
                s0 += v0 * v0 + v1 * v1;
                s1 += v2 * v2 + v3 * v3;
            }
            s0 += __shfl_xor_sync(0xffffffffu, s0, 1);
            s0 += __shfl_xor_sync(0xffffffffu, s0, 2);
            s1 += __shfl_xor_sync(0xffffffffu, s1, 1);
            s1 += __shfl_xor_sync(0xffffffffu, s1, 2);
            if ((lane & 3) == 0) {
                int r = bm + m0 + mt * 16 + qrow;
                C[(size_t)r * HH + head] = s0;
                C[(size_t)(r + 8) * HH + head] = s1;
            }
        }
    } else {
        __half* C = (__half*)Cv;
        #pragma unroll
        for (int mt = 0; mt < 4; mt++) {
            #pragma unroll
            for (int nt = 0; nt < 8; nt++) {
                int r0  = bm + m0 + mt * 16 + qrow;
                int col = bn + n0 + nt * 8 + qk;
                float2 bv = *(const float2*)(bias + col);
                __half2 h0 = __floats2half2_rn(c[mt][nt][0] + bv.x, c[mt][nt][1] + bv.y);
                __half2 h1 = __floats2half2_rn(c[mt][nt][2] + bv.x, c[mt][nt][3] + bv.y);
                *(__half2*)(C + (size_t)r0 * 1024 + col) = h0;
                *(__half2*)(C + (size_t)(r0 + 8) * 1024 + col) = h1;
            }
        }
    }
}

// ===================== scores from ssq ======================================
__global__ __launch_bounds__(256) void scores_ssq(
    const float* __restrict__ ssq, float* __restrict__ scores)
{
    int row = blockIdx.x * 256 + threadIdx.x;
    const float* sp = ssq + (size_t)row * HH;
    float acc = 0.f;
    #pragma unroll
    for (int h = 0; h < HH; h++) acc += sqrtf(sp[h]);
    scores[row] = acc * (1.f / 16.f);
}

// ===================== scores of fp32 rows (candidate rescoring) ============
__global__ __launch_bounds__(256) void scores_kernel(
    const float* __restrict__ Km, float* __restrict__ scores)
{
    int row  = blockIdx.x * 8 + (threadIdx.x >> 5);
    int lane = threadIdx.x & 31;
    const float* kr = Km + (size_t)row * EE;
    float acc = 0.f;
    #pragma unroll
    for (int h = 0; h < HH; h++) {
        float x0 = kr[h * 64 + lane];
        float x1 = kr[h * 64 + 32 + lane];
        float ss = x0 * x0 + x1 * x1;
        #pragma unroll
        for (int o = 16; o > 0; o >>= 1)
            ss += __shfl_xor_sync(0xffffffffu, ss, o);
        acc += sqrtf(ss);
    }
    if (lane == 0) scores[row] = acc * (1.f / 16.f);
}

// ===================== radix-select top-96 superset (<=128) =================
__global__ __launch_bounds__(256) void topk_radix(
    const float* __restrict__ scores, int* __restrict__ idxout,
    int* __restrict__ ncand)
{
    __shared__ int hist[256];
    __shared__ unsigned s_prefix;
    __shared__ int s_remaining;
    __shared__ int s_cnt;
    const int b = blockIdx.x, t = threadIdx.x;
    const float* sp = scores + b * SS;

    if (t == 0) { s_prefix = 0; s_remaining = NCAND; s_cnt = 0; }
    __syncthreads();

    for (int round = 0; round < 4; round++) {
        const int shift = 24 - 8 * round;
        hist[t] = 0;
        __syncthreads();
        const unsigned pfx = s_prefix;
        for (int i = t; i < SS; i += 256) {
            unsigned key = __float_as_uint(sp[i]);
            bool match = (round == 0) || (((key ^ pfx) >> (shift + 8)) == 0);
            if (match) atomicAdd(&hist[(key >> shift) & 255], 1);
        }
        __syncthreads();
        if (t == 0) {
            int rem = s_remaining, cum = 0, bin = 255;
            for (; bin > 0; bin--) {
                cum += hist[bin];
                if (cum >= rem) break;
            }
            if (cum < rem) cum += hist[0];
            s_remaining = rem - (cum - hist[bin]);
            s_prefix = pfx | ((unsigned)bin << shift);
        }
        __syncthreads();
    }
    const unsigned thresh = s_prefix;
    for (int i = t; i < SS; i += 256) {
        unsigned key = __float_as_uint(sp[i]);
        if (key >= thresh) {
            int pos = atomicAdd(&s_cnt, 1);
            if (pos < NCMAX) idxout[b * NCMAX + pos] = i;
        }
    }
    __syncthreads();
    int c = s_cnt < NCMAX ? s_cnt : NCMAX;
    if (t == 0) ncand[b] = c;
    for (int i = c + t; i < NCMAX; i += 256) idxout[b * NCMAX + i] = 0;
}

// ===================== exact fp32 projection (K and V via z) ================
template<int CPT>
__global__ __launch_bounds__(256) void project_rows2(
    const float* __restrict__ X0, const float* __restrict__ W0,
    const float* __restrict__ b0, float* __restrict__ o0,
    const float* __restrict__ X1, const float* __restrict__ W1,
    const float* __restrict__ b1, float* __restrict__ o1,
    const int* __restrict__ idx)
{
    __shared__ float xs[NCMAX * 32];
    __shared__ float ws[32 * 128];
    const int b = blockIdx.y;
    const int e0 = blockIdx.x * 128;
    const float* X  = blockIdx.z ? X1 : X0;
    const float* Wt = blockIdx.z ? W1 : W0;
    const float* bias = blockIdx.z ? b1 : b0;
    float* outp = blockIdx.z ? o1 : o0;
    const int t = threadIdx.x, tx = t & 31, ty = t >> 5;

    float acc[CPT][4];
    #pragma unroll
    for (int c = 0; c < CPT; c++)
        #pragma unroll
        for (int j = 0; j < 4; j++) acc[c][j] = 0.f;

    for (int kt = 0; kt < EE; kt += 32) {
        __syncthreads();
        for (int u = t; u < NCMAX * 8; u += 256) {
            int cand = u >> 3, c4 = u & 7;
            int s = idx[b * NCMAX + cand];
            float4 v = *(const float4*)(X + ((size_t)(b * SS + s)) * EE + kt + c4 * 4);
            *(float4*)(xs + cand * 32 + c4 * 4) = v;
        }
        for (int u = t; u < 1024; u += 256) {
            int e = u >> 3, c4 = u & 7;
            float4 v = *(const float4*)(Wt + (size_t)(e0 + e) * EE + kt + c4 * 4);
            ws[(c4 * 4 + 0) * 128 + e] = v.x;
            ws[(c4 * 4 + 1) * 128 + e] = v.y;
            ws[(c4 * 4 + 2) * 128 + e] = v.z;
            ws[(c4 * 4 + 3) * 128 + e] = v.w;
        }
        __syncthreads();
        #pragma unroll 8
        for (int k = 0; k < 32; k++) {
            float wv[4];
            #pragma unroll
            for (int j = 0; j < 4; j++) wv[j] = ws[k * 128 + tx * 4 + j];
            #pragma unroll
            for (int c = 0; c < CPT; c++) {
                float a = xs[(ty * CPT + c) * 32 + k];
                #pragma unroll
                for (int j = 0; j < 4; j++) acc[c][j] = fmaf(a, wv[j], acc[c][j]);
            }
        }
    }
    #pragma unroll
    for (int c = 0; c < CPT; c++) {
        int cand = ty * CPT + c;
        #pragma unroll
        for (int j = 0; j < 4; j++) {
            int e = e0 + tx * 4 + j;
            outp[((size_t)b * NCMAX + cand) * EE + e] = acc[c][j] + bias[e];
        }
    }
}

// ===================== exact top-64 among candidates ========================
__global__ __launch_bounds__(128) void topk_refine_kernel(
    const float* __restrict__ scex, const int* __restrict__ idxc,
    const int* __restrict__ ncand,
    int* __restrict__ idxfin, int* __restrict__ candfin)
{
    __shared__ float sv[NCMAX];
    __shared__ int   si[NCMAX];
    __shared__ float rv[128];
    __shared__ int   rc[128];
    __shared__ int   rs[128];
    const int b = blockIdx.x, t = threadIdx.x;
    const int cnt = ncand[b];
    sv[t] = (t < cnt) ? scex[b * NCMAX + t] : -INFINITY;
    si[t] = (t < cnt) ? idxc[b * NCMAX + t] : 0x7fffffff;
    __syncthreads();
    for (int l = 0; l < LL; l++) {
        rv[t] = sv[t]; rc[t] = t; rs[t] = si[t];
        __syncthreads();
        for (int s = 64; s > 0; s >>= 1) {
            if (t < s) {
                if (rv[t + s] > rv[t] || (rv[t + s] == rv[t] && rs[t + s] < rs[t])) {
                    rv[t] = rv[t + s]; rc[t] = rc[t + s]; rs[t] = rs[t + s];
                }
            }
            __syncthreads();
        }
        if (t == 0) {
            idxfin[b * LL + l] = rs[0];
            candfin[b * LL + l] = rc[0];
            sv[rc[0]] = -INFINITY;
        }
        __syncthreads();
    }
}

// ===================== gather -> fp16 K [b,h,l,d] + V^T [b,h,d,l] ===========
__global__ __launch_bounds__(256) void gatherperm_f16(
    const float* __restrict__ kex, const float* __restrict__ vex,
    const int* __restrict__ candf,
    __half* __restrict__ Kh, __half* __restrict__ Vth)
{
    int i = blockIdx.x * 256 + threadIdx.x;
    int d = i & 63;
    int l = (i >> 6) & 63;
    int h = (i >> 12) & 15;
    int b = i >> 16;
    int cp = candf[b * LL + l];
    size_t src = ((size_t)b * NCMAX + cp) * EE + h * 64 + d;
    Kh[i] = __float2half(kex[src]);
    Vth[(((size_t)(b * HH + h)) << 12) + d * 64 + l] = __float2half(vex[src]);
}

// ===================== tensor-core attention ================================
// Block = (chunk of 128 rows, h, b), 128 threads (4 warps), warp tile 32x64.
// smem: Q 16K | K 8K | V^T 8K | staging 34816 (w fp32 stride-68 / ctx fp16 stride-72)
#define ATTN_SMEM (32768 + 34816)

__global__ __launch_bounds__(128) void attn_mma(
    const __half* __restrict__ Qh, const __half* __restrict__ Kh,
    const __half* __restrict__ Vth, float* __restrict__ w_out,
    __half* __restrict__ ctxh)
{
    extern __shared__ __align__(128) char asmem[];
    const uint32_t sb = smem_u32(asmem);
    const uint32_t sQ = sb;
    const uint32_t sK = sb + 16384u;
    const uint32_t sV = sb + 24576u;
    float*  wsm = (float*)(asmem + 32768);
    __half* csm = (__half*)(asmem + 32768);

    const int b = blockIdx.z, h = blockIdx.y, chunk = blockIdx.x;
    const int t = threadIdx.x;
    const int lane = t & 31, wid = t >> 5;
    const int m0 = wid * 32;
    const int qrow = lane >> 2, qk = (lane & 3) * 2;
    const int lrow = lane & 7, phase = lane >> 3;

    // loads (swizzled, cp.async)
    const __half* Qg = Qh + ((size_t)(b * SS + chunk * 128)) * EE + h * 64;
    #pragma unroll
    for (int i = 0; i < 8; i++) {
        int idx = t + i * 128;
        int row = idx >> 3, ch = idx & 7;
        uint32_t off = (uint32_t)(row * 128 + ((ch ^ (row & 7)) << 4));
        cp16(sQ + off, Qg + (size_t)row * EE + ch * 8);
    }
    const __half* Kg = Kh + ((size_t)(b * HH + h) << 12);
    const __half* Vg = Vth + ((size_t)(b * HH + h) << 12);
    #pragma unroll
    for (int i = 0; i < 4; i++) {
        int idx = t + i * 128;
        int row = idx >> 3, ch = idx & 7;
        uint32_t off = (uint32_t)(row * 128 + ((ch ^ (row & 7)) << 4));
        cp16(sK + off, Kg + row * 64 + ch * 8);
        cp16(sV + off, Vg + row * 64 + ch * 8);
    }
    CP_COMMIT();
    CP_WAIT0();
    __syncthreads();

    // ---- QK^T : c[mt][nt][4], rows m0+mt*16+qrow (+8), cols nt*8+qk (+1) ----
    float c[2][8][4];
    #pragma unroll
    for (int mt = 0; mt < 2; mt++)
        #pragma unroll
        for (int nt = 0; nt < 8; nt++)
            #pragma unroll
            for (int q = 0; q < 4; q++) c[mt][nt][q] = 0.f;

    #pragma unroll
    for (int ks = 0; ks < 4; ks++) {
        uint32_t a[2][4];
        #pragma unroll
        for (int mt = 0; mt < 2; mt++) {
            int row = m0 + mt * 16 + (phase & 1) * 8 + lrow;
            int ch  = ks * 2 + (phase >> 1);
            ldm_x4(a[mt], sQ + (uint32_t)(row * 128 + ((ch ^ (row & 7)) << 4)));
        }
        uint32_t bf[4][4];
        #pragma unroll
        for (int ng = 0; ng < 4; ng++) {
            int row = ng * 16 + (phase >> 1) * 8 + lrow;
            int ch  = ks * 2 + (phase & 1);
            ldm_x4(bf[ng], sK + (uint32_t)(row * 128 + ((ch ^ (row & 7)) << 4)));
        }
        #pragma unroll
        for (int nt = 0; nt < 8; nt++) {
            uint32_t b0 = bf[nt >> 1][(nt & 1) * 2];
            uint32_t b1 = bf[nt >> 1][(nt & 1) * 2 + 1];
            MMAF16(c[0][nt], a[0], b0, b1);
            MMAF16(c[1][nt], a[1], b0, b1);
        }
    }

    // ---- softmax (scale 1/8; quad reduction over lane^1, lane^2) ----
    float inv[2][2];
    #pragma unroll
    for (int mt = 0; mt < 2; mt++) {
        float mx0 = -INFINITY, mx1 = -INFINITY;
        #pragma unroll
        for (int nt = 0; nt < 8; nt++) {
            #pragma unroll
            for (int q = 0; q < 4; q++) c[mt][nt][q] *= 0.125f;
            mx0 = fmaxf(mx0, fmaxf(c[mt][nt][0], c[mt][nt][1]));
            mx1 = fmaxf(mx1, fmaxf(c[mt][nt][2], c[mt][nt][3]));
        }
        mx0 = fmaxf(mx0, __shfl_xor_sync(0xffffffffu, mx0, 1));
        mx0 = fmaxf(mx0, __shfl_xor_sync(0xffffffffu, mx0, 2));
        mx1 = fmaxf(mx1, __shfl_xor_sync(0xffffffffu, mx1, 1));
        mx1 = fmaxf(mx1, __shfl_xor_sync(0xffffffffu, mx1, 2));
        float s0 = 0.f, s1 = 0.f;
        #pragma unroll
        for (int nt = 0; nt < 8; nt++) {
            c[mt][nt][0] = expf(c[mt][nt][0] - mx0);
            c[mt][nt][1] = expf(c[mt][nt][1] - mx0);
            c[mt][nt][2] = expf(c[mt][nt][2] - mx1);
            c[mt][nt][3] = expf(c[mt][nt][3] - mx1);
            s0 += c[mt][nt][0] + c[mt][nt][1];
            s1 += c[mt][nt][2] + c[mt][nt][3];
        }
        s0 += __shfl_xor_sync(0xffffffffu, s0, 1);
        s0 += __shfl_xor_sync(0xffffffffu, s0, 2);
        s1 += __shfl_xor_sync(0xffffffffu, s1, 1);
        s1 += __shfl_xor_sync(0xffffffffu, s1, 2);
        inv[mt][0] = 1.f / s0;
        inv[mt][1] = 1.f / s1;
    }

    // ---- w to smem staging + build fp16 A fragments (FA2 C->A trick) ----
    uint32_t wh[2][4][4];
    #pragma unroll
    for (int mt = 0; mt < 2; mt++) {
        int r0 = m0 + mt * 16 + qrow;
        #pragma unroll
        for (int nt = 0; nt < 8; nt++) {
            float w0 = c[mt][nt][0] * inv[mt][0];
            float w1 = c[mt][nt][1] * inv[mt][0];
            float w2 = c[mt][nt][2] * inv[mt][1];
            float w3 = c[mt][nt][3] * inv[mt][1];
            int col = nt * 8 + qk;
            wsm[r0 * 68 + col] = w0;       wsm[r0 * 68 + col + 1] = w1;
            wsm[(r0 + 8) * 68 + col] = w2; wsm[(r0 + 8) * 68 + col + 1] = w3;
            int j = nt >> 1;
            if ((nt & 1) == 0) {
                wh[mt][j][0] = packh2(w0, w1);
                wh[mt][j][1] = packh2(w2, w3);
            } else {
                wh[mt][j][2] = packh2(w0, w1);
                wh[mt][j][3] = packh2(w2, w3);
            }
        }
    }

    // ---- AV : o = w @ V (V^T tiles as B operand) ----
    float o[2][8][4];
    #pragma unroll
    for (int mt = 0; mt < 2; mt++)
        #pragma unroll
        for (int nt = 0; nt < 8; nt++)
            #pragma unroll
            for (int q = 0; q < 4; q++) o[mt][nt][q] = 0.f;

    #pragma unroll
    for (int j = 0; j < 4; j++) {
        uint32_t bf[4][4];
        #pragma unroll
        for (int ng = 0; ng < 4; ng++) {
            int row = ng * 16 + (phase >> 1) * 8 + lrow;
            int ch  = j * 2 + (phase & 1);
            ldm_x4(bf[ng], sV + (uint32_t)(row * 128 + ((ch ^ (row & 7)) << 4)));
        }
        #pragma unroll
        for (int nt = 0; nt < 8; nt++) {
            uint32_t b0 = bf[nt >> 1][(nt & 1) * 2];
            uint32_t b1 = bf[nt >> 1][(nt & 1) * 2 + 1];
            MMAF16(o[0][nt], wh[0][j], b0, b1);
            MMAF16(o[1][nt], wh[1][j], b0, b1);
        }
    }

    // ---- coalesced w write ----
    __syncthreads();
    float* wb = w_out + ((size_t)((b * HH + h) * SS + chunk * 128)) * LL;
    #pragma unroll
    for (int i = 0; i < 16; i++) {
        int idx = t + i * 128;
        int row = idx >> 4, c4 = idx & 15;
        *(float4*)(wb + row * 64 + c4 * 4) = *(const float4*)(wsm + row * 68 + c4 * 4);
    }
    __syncthreads();

    // ---- ctx fragments -> fp16 staging ----
    #pragma unroll
    for (int mt = 0; mt < 2; mt++) {
        int r0 = m0 + mt * 16 + qrow;
        #pragma unroll
        for (int nt = 0; nt < 8; nt++) {
            int col = nt * 8 + qk;
            *(__half2*)(csm + r0 * 72 + col)       = __floats2half2_rn(o[mt][nt][0], o[mt][nt][1]);
            *(__half2*)(csm + (r0 + 8) * 72 + col) = __floats2half2_rn(o[mt][nt][2], o[mt][nt][3]);
        }
    }
    __syncthreads();
    __half* cb = ctxh + ((size_t)(b * SS + chunk * 128)) * EE + h * 64;
    #pragma unroll
    for (int i = 0; i < 8; i++) {
        int idx = t + i * 128;
        int row = idx >> 3, seg = idx & 7;
        *(uint4*)(cb + (size_t)row * EE + seg * 8) = *(const uint4*)(csm + row * 72 + seg * 8);
    }
}

// ===================== launch ===============================================
extern "C" void kernel_launch(void* const* d_in, const int* in_sizes, int n_in,
                              void* d_out, int out_size)
{
    const float* query = (const float*)d_in[0];
    const float* key   = (const float*)d_in[1];
    const float* value = (const float*)d_in[2];
    const float* Wq = (const float*)d_in[3];
    const float* bq = (const float*)d_in[4];
    const float* Wk = (const float*)d_in[5];
    const float* bk = (const float*)d_in[6];
    const float* Wv = (const float*)d_in[7];
    const float* bv = (const float*)d_in[8];
    const float* Wo = (const float*)d_in[9];
    const float* bo = (const float*)d_in[10];

    float* out  = (float*)d_out;
    float* wout = out + MSZ;

    float *pSsq, *pScores, *pKex, *pVex, *pScex;
    __half *pQh, *pAqh, *pAkh, *pWqh, *pWkh, *pWoh, *pKsph, *pVspt;
    int *pIdxc, *pNcand, *pIdxf, *pCandf;
    cudaGetSymbolAddress((void**)&pQh, g_Qh);
    cudaGetSymbolAddress((void**)&pAqh, g_Aqh);
    cudaGetSymbolAddress((void**)&pAkh, g_Akh);
    cudaGetSymbolAddress((void**)&pWqh, g_Wqh);
    cudaGetSymbolAddress((void**)&pWkh, g_Wkh);
    cudaGetSymbolAddress((void**)&pWoh, g_Woh);
    cudaGetSymbolAddress((void**)&pSsq, g_ssq);
    cudaGetSymbolAddress((void**)&pScores, g_scores);
    cudaGetSymbolAddress((void**)&pIdxc, g_idxc);
    cudaGetSymbolAddress((void**)&pNcand, g_ncand);
    cudaGetSymbolAddress((void**)&pKex, g_kex);
    cudaGetSymbolAddress((void**)&pVex, g_vex);
    cudaGetSymbolAddress((void**)&pScex, g_scex);
    cudaGetSymbolAddress((void**)&pIdxf, g_idxf);
    cudaGetSymbolAddress((void**)&pCandf, g_candf);
    cudaGetSymbolAddress((void**)&pKsph, g_Ksph);
    cudaGetSymbolAddress((void**)&pVspt, g_Vspt);

    cudaFuncSetAttribute((void*)gemm_f16<0>, cudaFuncAttributeMaxDynamicSharedMemorySize, GEMM_SMEM);
    cudaFuncSetAttribute((void*)gemm_f16<1>, cudaFuncAttributeMaxDynamicSharedMemorySize, GEMM_SMEM);
    cudaFuncSetAttribute((void*)gemm_f16<2>, cudaFuncAttributeMaxDynamicSharedMemorySize, GEMM_SMEM);
    cudaFuncSetAttribute((void*)attn_mma, cudaFuncAttributeMaxDynamicSharedMemorySize, ATTN_SMEM);

    const int n4m = (int)(MSZ / 4);
    const int n4w = EE * EE / 4;
    dim3 ggrid(4, 256);

    // launches 1-4: conversions; 5 & 6 = GEMMs (ncu -s 5 -c 1 lands on one)
    conv_f16<<<n4w / 256, 256>>>(Wq, pWqh, n4w);
    conv_f16<<<n4w / 256, 256>>>(Wk, pWkh, n4w);
    conv_f16<<<n4m / 256, 256>>>(key, pAkh, n4m);
    conv_f16<<<n4m / 256, 256>>>(query, pAqh, n4m);

    // Q = fp16(query) @ fp16(Wq)^T + bq  -> fp16
    gemm_f16<2><<<ggrid, 256, GEMM_SMEM>>>(pAqh, pWqh, bq, pQh);
    // K projection fused into per-(row,head) sum-of-squares (selection only)
    gemm_f16<1><<<ggrid, 256, GEMM_SMEM>>>(pAkh, pWkh, bk, pSsq);

    conv_f16<<<n4w / 256, 256>>>(Wo, pWoh, n4w);

    // scores -> radix-select top-96 superset (<=128 candidates)
    scores_ssq<<<MROWS / 256, 256>>>(pSsq, pScores);
    topk_radix<<<BB, 256>>>(pScores, pIdxc, pNcand);

    // exact fp32 K+V rows at candidates (fused), exact scores, exact top-64
    dim3 pgrid(8, BB, 2);
    project_rows2<16><<<pgrid, 256>>>(key, Wk, bk, pKex, value, Wv, bv, pVex, pIdxc);
    scores_kernel<<<(BB * NCMAX) / 8, 256>>>(pKex, pScex);
    topk_refine_kernel<<<BB, 128>>>(pScex, pIdxc, pNcand, pIdxf, pCandf);
    gatherperm_f16<<<(BB * HH * LL * DD) / 256, 256>>>(pKex, pVex, pCandf, pKsph, pVspt);

    // tensor-core attention (fp16 Q/K/V, writes w fp32 + fp16 ctx into Aqh)
    dim3 agrid(SS / 128, HH, BB);
    attn_mma<<<agrid, 128, ATTN_SMEM>>>(pQh, pKsph, pVspt, wout, pAqh);

    // out = fp16(ctx) @ fp16(Wo)^T + bo
    gemm_f16<0><<<ggrid, 256, GEMM_SMEM>>>(pAqh, pWoh, bo, out);
}

// round 13
// speedup vs baseline: 3.8109x; 1.0385x over previous
#include <cuda_runtime.h>
#include <cuda_fp16.h>
#include <math.h>
#include <stdint.h>

#define BB 4
#define SS 8192
#define EE 1024
#define HH 16
#define DD 64
#define LL 64
#define NCAND 96
#define NCMAX 128
#define MROWS (BB * SS)
#define MSZ   ((size_t)MROWS * EE)

// ===================== scratch ==============================================
__device__ __half g_Qh[MSZ];
__device__ __half g_Aqh[MSZ];         // query fp16 in; reused as fp16 ctx
__device__ __half g_Akh[MSZ];
__device__ __half g_Wqh[EE * EE];
__device__ __half g_Wkh[EE * EE];
__device__ __half g_Woh[EE * EE];
__device__ float g_ssq[MROWS * HH];
__device__ float g_scores[BB * SS];
__device__ int   g_idxc[BB * NCMAX];
__device__ int   g_ncand[BB];
__device__ float g_kex[BB * NCMAX * EE];
__device__ float g_vex[BB * NCMAX * EE];
__device__ float g_scex[BB * NCMAX];
__device__ int   g_idxf[BB * LL];
__device__ int   g_candf[BB * LL];
__device__ __half g_Ksph[BB * HH * LL * DD];   // [b,h,l,d]
__device__ __half g_Vspt[BB * HH * DD * LL];   // [b,h,d,l]

// ===================== small PTX helpers ====================================
__device__ __forceinline__ uint32_t smem_u32(const void* p) {
    uint32_t a;
    asm("{ .reg .u64 t; cvta.to.shared.u64 t, %1; cvt.u32.u64 %0, t; }" : "=r"(a) : "l"(p));
    return a;
}
__device__ __forceinline__ void cp16(uint32_t dst, const void* src) {
    asm volatile("cp.async.cg.shared.global [%0], [%1], 16;" :: "r"(dst), "l"(src));
}
#define CP_COMMIT() asm volatile("cp.async.commit_group;" ::: "memory")
#define CP_WAIT1()  asm volatile("cp.async.wait_group 1;" ::: "memory")
#define CP_WAIT0()  asm volatile("cp.async.wait_group 0;" ::: "memory")
__device__ __forceinline__ void ldm_x4(uint32_t* r, uint32_t addr) {
    asm volatile("ldmatrix.sync.aligned.m8n8.x4.shared.b16 {%0,%1,%2,%3}, [%4];"
                 : "=r"(r[0]), "=r"(r[1]), "=r"(r[2]), "=r"(r[3]) : "r"(addr));
}
#define MMAF16(d, a, b0, b1) \
    asm volatile("mma.sync.aligned.m16n8k16.row.col.f32.f16.f16.f32 " \
        "{%0,%1,%2,%3}, {%4,%5,%6,%7}, {%8,%9}, {%0,%1,%2,%3};" \
        : "+f"((d)[0]), "+f"((d)[1]), "+f"((d)[2]), "+f"((d)[3]) \
        : "r"((a)[0]), "r"((a)[1]), "r"((a)[2]), "r"((a)[3]), \
          "r"(b0), "r"(b1))
__device__ __forceinline__ uint32_t packh2(float a, float b) {
    __half2 h = __floats2half2_rn(a, b);
    return *(uint32_t*)&h;
}

// ===================== fp32 -> fp16 conversions ==============================
__global__ __launch_bounds__(256) void conv_f16(
    const float* __restrict__ x, __half* __restrict__ h, int n4)
{
    int i = blockIdx.x * 256 + threadIdx.x;
    if (i >= n4) return;
    float4 v = ((const float4*)x)[i];
    uint32_t h0 = (uint32_t)__half_as_ushort(__float2half(v.x));
    uint32_t h1 = (uint32_t)__half_as_ushort(__float2half(v.y));
    uint32_t h2 = (uint32_t)__half_as_ushort(__float2half(v.z));
    uint32_t h3 = (uint32_t)__half_as_ushort(__float2half(v.w));
    uint2 hp; hp.x = h0 | (h1 << 16); hp.y = h2 | (h3 << 16);
    ((uint2*)h)[i] = hp;
}

// 3 weight matrices in one launch (blockIdx.y selects)
__global__ __launch_bounds__(256) void conv3_f16(
    const float* __restrict__ x0, __half* __restrict__ h0,
    const float* __restrict__ x1, __half* __restrict__ h1,
    const float* __restrict__ x2, __half* __restrict__ h2, int n4)
{
    int i = blockIdx.x * 256 + threadIdx.x;
    if (i >= n4) return;
    const float* x = blockIdx.y == 0 ? x0 : (blockIdx.y == 1 ? x1 : x2);
    __half* h = blockIdx.y == 0 ? h0 : (blockIdx.y == 1 ? h1 : h2);
    float4 v = ((const float4*)x)[i];
    uint32_t a0 = (uint32_t)__half_as_ushort(__float2half(v.x));
    uint32_t a1 = (uint32_t)__half_as_ushort(__float2half(v.y));
    uint32_t a2 = (uint32_t)__half_as_ushort(__float2half(v.z));
    uint32_t a3 = (uint32_t)__half_as_ushort(__float2half(v.w));
    uint2 hp; hp.x = a0 | (a1 << 16); hp.y = a2 | (a3 << 16);
    ((uint2*)h)[i] = hp;
}

// ===================== fp16 GEMM core (macro-shared mainloop) ===============
#define GSTAGE 49152u
#define GEMM_SMEM (3 * 49152)

// EPI=0: fp32 C + bias (out GEMM).
template<int EPI>
__global__ __launch_bounds__(256) void gemm_f16(
    const __half* __restrict__ A, const __half* __restrict__ W,
    const float* __restrict__ bias, void* __restrict__ Cv)
{
    extern __shared__ __align__(128) char dsm[];
    const uint32_t sbase = smem_u32(dsm);
    const int tid  = threadIdx.x;
    const int lane = tid & 31;
    const int wid  = tid >> 5;
    const int bm = blockIdx.y * 128;
    const int bn = blockIdx.x * 256;
    const int m0 = (wid & 1) * 64;
    const int n0 = (wid >> 1) * 64;
    const int qrow = lane >> 2;
    const int qk   = (lane & 3) * 2;
    const int lrow  = lane & 7;
    const int phase = lane >> 3;
    const int g_c  = tid & 7;
    const int g_r0 = tid >> 3;

    float c[4][8][4];
    #pragma unroll
    for (int mt = 0; mt < 4; mt++)
        #pragma unroll
        for (int nt = 0; nt < 8; nt++)
            #pragma unroll
            for (int q = 0; q < 4; q++) c[mt][nt][q] = 0.f;

    auto load_tile = [&](int kt) {
        if (kt < 16) {
            const uint32_t sA = sbase + (uint32_t)(kt % 3) * GSTAGE;
            const uint32_t sB = sA + 16384u;
            const int kk = kt << 6;
            #pragma unroll
            for (int i = 0; i < 4; i++) {
                int row = g_r0 + i * 32;
                uint32_t off = (uint32_t)(row * 128 + ((g_c ^ (row & 7)) << 4));
                cp16(sA + off, A + (size_t)(bm + row) * 1024 + kk + g_c * 8);
            }
            #pragma unroll
            for (int i = 0; i < 8; i++) {
                int row = g_r0 + i * 32;
                uint32_t off = (uint32_t)(row * 128 + ((g_c ^ (row & 7)) << 4));
                cp16(sB + off, W + (size_t)(bn + row) * 1024 + kk + g_c * 8);
            }
        }
        CP_COMMIT();
    };

    load_tile(0);
    load_tile(1);

    for (int kt = 0; kt < 16; kt++) {
        CP_WAIT1();
        __syncthreads();
        load_tile(kt + 2);
        const uint32_t aB = sbase + (uint32_t)(kt % 3) * GSTAGE;
        const uint32_t bB = aB + 16384u;
        #pragma unroll
        for (int ks = 0; ks < 4; ks++) {
            const int c0 = ks * 2;
            uint32_t a[4][4];
            #pragma unroll
            for (int mt = 0; mt < 4; mt++) {
                int row = m0 + mt * 16 + (phase & 1) * 8 + lrow;
                int ch  = c0 + (phase >> 1);
                ldm_x4(a[mt], aB + (uint32_t)(row * 128 + ((ch ^ (row & 7)) << 4)));
            }
            uint32_t bf[4][4];
            #pragma unroll
            for (int ng = 0; ng < 4; ng++) {
                int row = n0 + ng * 16 + (phase >> 1) * 8 + lrow;
                int ch  = c0 + (phase & 1);
                ldm_x4(bf[ng], bB + (uint32_t)(row * 128 + ((ch ^ (row & 7)) << 4)));
            }
            #pragma unroll
            for (int nt = 0; nt < 8; nt++) {
                uint32_t b0 = bf[nt >> 1][(nt & 1) * 2];
                uint32_t b1 = bf[nt >> 1][(nt & 1) * 2 + 1];
                #pragma unroll
                for (int mt = 0; mt < 4; mt++)
                    MMAF16(c[mt][nt], a[mt], b0, b1);
            }
        }
        __syncthreads();
    }

    float* C = (float*)Cv;
    #pragma unroll
    for (int mt = 0; mt < 4; mt++) {
        #pragma unroll
        for (int nt = 0; nt < 8; nt++) {
            int r0  = bm + m0 + mt * 16 + qrow;
            int col = bn + n0 + nt * 8 + qk;
            float2 bv = *(const float2*)(bias + col);
            float2 o0, o1;
            o0.x = c[mt][nt][0] + bv.x; o0.y = c[mt][nt][1] + bv.y;
            o1.x = c[mt][nt][2] + bv.x; o1.y = c[mt][nt][3] + bv.y;
            *(float2*)(C + (size_t)r0 * 1024 + col) = o0;
            *(float2*)(C + (size_t)(r0 + 8) * 1024 + col) = o1;
        }
    }
}

// Merged Q+K GEMM: z=0 -> Q (fp16 out), z=1 -> K (ssq out).
__global__ __launch_bounds__(256) void gemm_qk(
    const __half* __restrict__ A0, const __half* __restrict__ W0,
    const float* __restrict__ b0, __half* __restrict__ C0,
    const __half* __restrict__ A1, const __half* __restrict__ W1,
    const float* __restrict__ b1, float* __restrict__ C1)
{
    extern __shared__ __align__(128) char dsm[];
    const uint32_t sbase = smem_u32(dsm);
    const int z = blockIdx.z;
    const __half* A = z ? A1 : A0;
    const __half* W = z ? W1 : W0;
    const float* bias = z ? b1 : b0;

    const int tid  = threadIdx.x;
    const int lane = tid & 31;
    const int wid  = tid >> 5;
    const int bm = blockIdx.y * 128;
    const int bn = blockIdx.x * 256;
    const int m0 = (wid & 1) * 64;
    const int n0 = (wid >> 1) * 64;
    const int qrow = lane >> 2;
    const int qk   = (lane & 3) * 2;
    const int lrow  = lane & 7;
    const int phase = lane >> 3;
    const int g_c  = tid & 7;
    const int g_r0 = tid >> 3;

    float c[4][8][4];
    #pragma unroll
    for (int mt = 0; mt < 4; mt++)
        #pragma unroll
        for (int nt = 0; nt < 8; nt++)
            #pragma unroll
            for (int q = 0; q < 4; q++) c[mt][nt][q] = 0.f;

    auto load_tile = [&](int kt) {
        if (kt < 16) {
            const uint32_t sA = sbase + (uint32_t)(kt % 3) * GSTAGE;
            const uint32_t sB = sA + 16384u;
            const int kk = kt << 6;
            #pragma unroll
            for (int i = 0; i < 4; i++) {
                int row = g_r0 + i * 32;
                uint32_t off = (uint32_t)(row * 128 + ((g_c ^ (row & 7)) << 4));
                cp16(sA + off, A + (size_t)(bm + row) * 1024 + kk + g_c * 8);
            }
            #pragma unroll
            for (int i = 0; i < 8; i++) {
                int row = g_r0 + i * 32;
                uint32_t off = (uint32_t)(row * 128 + ((g_c ^ (row & 7)) << 4));
                cp16(sB + off, W + (size_t)(bn + row) * 1024 + kk + g_c * 8);
            }
        }
        CP_COMMIT();
    };

    load_tile(0);
    load_tile(1);

    for (int kt = 0; kt < 16; kt++) {
        CP_WAIT1();
        __syncthreads();
        load_tile(kt + 2);
        const uint32_t aB = sbase + (uint32_t)(kt % 3) * GSTAGE;
        const uint32_t bB = aB + 16384u;
        #pragma unroll
        for (int ks = 0; ks < 4; ks++) {
            const int c0 = ks * 2;
            uint32_t a[4][4];
            #pragma unroll
            for (int mt = 0; mt < 4; mt++) {
                int row = m0 + mt * 16 + (phase & 1) * 8 + lrow;
                int ch  = c0 + (phase >> 1);
                ldm_x4(a[mt], aB + (uint32_t)(row * 128 + ((ch ^ (row & 7)) << 4)));
            }
            uint32_t bf[4][4];
            #pragma unroll
            for (int ng = 0; ng < 4; ng++) {
                int row = n0 + ng * 16 + (phase >> 1) * 8 + lrow;
                int ch  = c0 + (phase & 1);
                ldm_x4(bf[ng], bB + (uint32_t)(row * 128 + ((ch ^ (row & 7)) << 4)));
            }
            #pragma unroll
            for (int nt = 0; nt < 8; nt++) {
                uint32_t b0 = bf[nt >> 1][(nt & 1) * 2];
                uint32_t b1 = bf[nt >> 1][(nt & 1) * 2 + 1];
                #pragma unroll
                for (int mt = 0; mt < 4; mt++)
                    MMAF16(c[mt][nt], a[mt], b0, b1);
            }
        }
        __syncthreads();
    }

    if (z == 0) {
        __half* C = C0;
        #pragma unroll
        for (int mt = 0; mt < 4; mt++) {
            #pragma unroll
            for (int nt = 0; nt < 8; nt++) {
                int r0  = bm + m0 + mt * 16 + qrow;
                int col = bn + n0 + nt * 8 + qk;
                float2 bv = *(const float2*)(bias + col);
                __half2 h0 = __floats2half2_rn(c[mt][nt][0] + bv.x, c[mt][nt][1] + bv.y);
                __half2 h1 = __floats2half2_rn(c[mt][nt][2] + bv.x, c[mt][nt][3] + bv.y);
                *(__half2*)(C + (size_t)r0 * 1024 + col) = h0;
                *(__half2*)(C + (size_t)(r0 + 8) * 1024 + col) = h1;
            }
        }
    } else {
        float* C = C1;
        const int head = (bn + n0) >> 6;
        #pragma unroll
        for (int mt = 0; mt < 4; mt++) {
            float s0 = 0.f, s1 = 0.f;
            #pragma unroll
            for (int nt = 0; nt < 8; nt++) {
                int col = bn + n0 + nt * 8 + qk;
                float2 bv = *(const float2*)(bias + col);
                float v0 = c[mt][nt][0] + bv.x, v1 = c[mt][nt][1] + bv.y;
                float v2 = c[mt][nt][2] + bv.x, v3 = c[mt][nt][3] + bv.y;
                s0 += v0 * v0 + v1 * v1;
                s1 += v2 * v2 + v3 * v3;
            }
            s0 += __shfl_xor_sync(0xffffffffu, s0, 1);
            s0 += __shfl_xor_sync(0xffffffffu, s0, 2);
            s1 += __shfl_xor_sync(0xffffffffu, s1, 1);
            s1 += __shfl_xor_sync(0xffffffffu, s1, 2);
            if ((lane & 3) == 0) {
                int r = bm + m0 + mt * 16 + qrow;
                C[(size_t)r * HH + head] = s0;
                C[(size_t)(r + 8) * HH + head] = s1;
            }
        }
    }
}

// ===================== scores from ssq ======================================
__global__ __launch_bounds__(256) void scores_ssq(
    const float* __restrict__ ssq, float* __restrict__ scores)
{
    int row = blockIdx.x * 256 + threadIdx.x;
    const float* sp = ssq + (size_t)row * HH;
    float acc = 0.f;
    #pragma unroll
    for (int h = 0; h < HH; h++) acc += sqrtf(sp[h]);
    scores[row] = acc * (1.f / 16.f);
}

// ===================== scores of fp32 rows (candidate rescoring) ============
__global__ __launch_bounds__(256) void scores_kernel(
    const float* __restrict__ Km, float* __restrict__ scores)
{
    int row  = blockIdx.x * 8 + (threadIdx.x >> 5);
    int lane = threadIdx.x & 31;
    const float* kr = Km + (size_t)row * EE;
    float acc = 0.f;
    #pragma unroll
    for (int h = 0; h < HH; h++) {
        float x0 = kr[h * 64 + lane];
        float x1 = kr[h * 64 + 32 + lane];
        float ss = x0 * x0 + x1 * x1;
        #pragma unroll
        for (int o = 16; o > 0; o >>= 1)
            ss += __shfl_xor_sync(0xffffffffu, ss, o);
        acc += sqrtf(ss);
    }
    if (lane == 0) scores[row] = acc * (1.f / 16.f);
}

// ===================== radix-select top-96 superset (<=128) =================
__global__ __launch_bounds__(256) void topk_radix(
    const float* __restrict__ scores, int* __restrict__ idxout,
    int* __restrict__ ncand)
{
    __shared__ int hist[256];
    __shared__ unsigned s_prefix;
    __shared__ int s_remaining;
    __shared__ int s_cnt;
    const int b = blockIdx.x, t = threadIdx.x;
    const float* sp = scores + b * SS;

    if (t == 0) { s_prefix = 0; s_remaining = NCAND; s_cnt = 0; }
    __syncthreads();

    for (int round = 0; round < 4; round++) {
        const int shift = 24 - 8 * round;
        hist[t] = 0;
        __syncthreads();
        const unsigned pfx = s_prefix;
        for (int i = t; i < SS; i += 256) {
            unsigned key = __float_as_uint(sp[i]);
            bool match = (round == 0) || (((key ^ pfx) >> (shift + 8)) == 0);
            if (match) atomicAdd(&hist[(key >> shift) & 255], 1);
        }
        __syncthreads();
        if (t == 0) {
            int rem = s_remaining, cum = 0, bin = 255;
            for (; bin > 0; bin--) {
                cum += hist[bin];
                if (cum >= rem) break;
            }
            if (cum < rem) cum += hist[0];
            s_remaining = rem - (cum - hist[bin]);
            s_prefix = pfx | ((unsigned)bin << shift);
        }
        __syncthreads();
    }
    const unsigned thresh = s_prefix;
    for (int i = t; i < SS; i += 256) {
        unsigned key = __float_as_uint(sp[i]);
        if (key >= thresh) {
            int pos = atomicAdd(&s_cnt, 1);
            if (pos < NCMAX) idxout[b * NCMAX + pos] = i;
        }
    }
    __syncthreads();
    int c = s_cnt < NCMAX ? s_cnt : NCMAX;
    if (t == 0) ncand[b] = c;
    for (int i = c + t; i < NCMAX; i += 256) idxout[b * NCMAX + i] = 0;
}

// ===================== exact fp32 projection (K/V via z, 64-col blocks) =====
__global__ __launch_bounds__(256) void project_rows2(
    const float* __restrict__ X0, const float* __restrict__ W0,
    const float* __restrict__ b0, float* __restrict__ o0,
    const float* __restrict__ X1, const float* __restrict__ W1,
    const float* __restrict__ b1, float* __restrict__ o1,
    const int* __restrict__ idx)
{
    __shared__ float xs[NCMAX * 32];
    __shared__ float ws[32 * 64];
    const int b = blockIdx.y;
    const int e0 = blockIdx.x * 64;
    const float* X  = blockIdx.z ? X1 : X0;
    const float* Wt = blockIdx.z ? W1 : W0;
    const float* bias = blockIdx.z ? b1 : b0;
    float* outp = blockIdx.z ? o1 : o0;
    const int t = threadIdx.x, tx = t & 15, ty = t >> 4;  // 16 e-groups x 16 cand-groups

    float acc[8][4];
    #pragma unroll
    for (int c = 0; c < 8; c++)
        #pragma unroll
        for (int j = 0; j < 4; j++) acc[c][j] = 0.f;

    for (int kt = 0; kt < EE; kt += 32) {
        __syncthreads();
        for (int u = t; u < NCMAX * 8; u += 256) {
            int cand = u >> 3, c4 = u & 7;
            int s = idx[b * NCMAX + cand];
            float4 v = *(const float4*)(X + ((size_t)(b * SS + s)) * EE + kt + c4 * 4);
            *(float4*)(xs + cand * 32 + c4 * 4) = v;
        }
        for (int u = t; u < 512; u += 256) {
            int e = u >> 3, c4 = u & 7;
            float4 v = *(const float4*)(Wt + (size_t)(e0 + e) * EE + kt + c4 * 4);
            ws[(c4 * 4 + 0) * 64 + e] = v.x;
            ws[(c4 * 4 + 1) * 64 + e] = v.y;
            ws[(c4 * 4 + 2) * 64 + e] = v.z;
            ws[(c4 * 4 + 3) * 64 + e] = v.w;
        }
        __syncthreads();
        #pragma unroll 8
        for (int k = 0; k < 32; k++) {
            float wv[4];
            #pragma unroll
            for (int j = 0; j < 4; j++) wv[j] = ws[k * 64 + tx * 4 + j];
            #pragma unroll
            for (int c = 0; c < 8; c++) {
                float a = xs[(ty * 8 + c) * 32 + k];
                #pragma unroll
                for (int j = 0; j < 4; j++) acc[c][j] = fmaf(a, wv[j], acc[c][j]);
            }
        }
    }
    #pragma unroll
    for (int c = 0; c < 8; c++) {
        int cand = ty * 8 + c;
        #pragma unroll
        for (int j = 0; j < 4; j++) {
            int e = e0 + tx * 4 + j;
            outp[((size_t)b * NCMAX + cand) * EE + e] = acc[c][j] + bias[e];
        }
    }
}

// ===================== exact top-64 among candidates ========================
__global__ __launch_bounds__(128) void topk_refine_kernel(
    const float* __restrict__ scex, const int* __restrict__ idxc,
    const int* __restrict__ ncand,
    int* __restrict__ idxfin, int* __restrict__ candfin)
{
    __shared__ float sv[NCMAX];
    __shared__ int   si[NCMAX];
    __shared__ float rv[128];
    __shared__ int   rc[128];
    __shared__ int   rs[128];
    const int b = blockIdx.x, t = threadIdx.x;
    const int cnt = ncand[b];
    sv[t] = (t < cnt) ? scex[b * NCMAX + t] : -INFINITY;
    si[t] = (t < cnt) ? idxc[b * NCMAX + t] : 0x7fffffff;
    __syncthreads();
    for (int l = 0; l < LL; l++) {
        rv[t] = sv[t]; rc[t] = t; rs[t] = si[t];
        __syncthreads();
        for (int s = 64; s > 0; s >>= 1) {
            if (t < s) {
                if (rv[t + s] > rv[t] || (rv[t + s] == rv[t] && rs[t + s] < rs[t])) {
                    rv[t] = rv[t + s]; rc[t] = rc[t + s]; rs[t] = rs[t + s];
                }
            }
            __syncthreads();
        }
        if (t == 0) {
            idxfin[b * LL + l] = rs[0];
            candfin[b * LL + l] = rc[0];
            sv[rc[0]] = -INFINITY;
        }
        __syncthreads();
    }
}

// ===================== gather -> fp16 K [b,h,l,d] + V^T [b,h,d,l] ===========
__global__ __launch_bounds__(256) void gatherperm_f16(
    const float* __restrict__ kex, const float* __restrict__ vex,
    const int* __restrict__ candf,
    __half* __restrict__ Kh, __half* __restrict__ Vth)
{
    int i = blockIdx.x * 256 + threadIdx.x;
    int d = i & 63;
    int l = (i >> 6) & 63;
    int h = (i >> 12) & 15;
    int b = i >> 16;
    int cp = candf[b * LL + l];
    size_t src = ((size_t)b * NCMAX + cp) * EE + h * 64 + d;
    Kh[i] = __float2half(kex[src]);
    Vth[(((size_t)(b * HH + h)) << 12) + d * 64 + l] = __float2half(vex[src]);
}

// ===================== tensor-core attention (256 rows / 256 thr) ===========
// smem: Q 32K | K 8K | V^T 8K | staging 69632 (w fp32 stride-68 / ctx fp16 stride-72)
#define ATTN_SMEM (49152 + 69632)

__global__ __launch_bounds__(256) void attn_mma(
    const __half* __restrict__ Qh, const __half* __restrict__ Kh,
    const __half* __restrict__ Vth, float* __restrict__ w_out,
    __half* __restrict__ ctxh)
{
    extern __shared__ __align__(128) char asmem[];
    const uint32_t sb = smem_u32(asmem);
    const uint32_t sQ = sb;
    const uint32_t sK = sb + 32768u;
    const uint32_t sV = sb + 40960u;
    float*  wsm = (float*)(asmem + 49152);
    __half* csm = (__half*)(asmem + 49152);

    const int b = blockIdx.z, h = blockIdx.y, chunk = blockIdx.x;
    const int t = threadIdx.x;
    const int lane = t & 31, wid = t >> 5;
    const int m0 = wid * 32;
    const int qrow = lane >> 2, qk = (lane & 3) * 2;
    const int lrow = lane & 7, phase = lane >> 3;

    const __half* Qg = Qh + ((size_t)(b * SS + chunk * 256)) * EE + h * 64;
    #pragma unroll
    for (int i = 0; i < 8; i++) {
        int idx = t + i * 256;
        int row = idx >> 3, ch = idx & 7;
        uint32_t off = (uint32_t)(row * 128 + ((ch ^ (row & 7)) << 4));
        cp16(sQ + off, Qg + (size_t)row * EE + ch * 8);
    }
    const __half* Kg = Kh + ((size_t)(b * HH + h) << 12);
    const __half* Vg = Vth + ((size_t)(b * HH + h) << 12);
    #pragma unroll
    for (int i = 0; i < 2; i++) {
        int idx = t + i * 256;
        int row = idx >> 3, ch = idx & 7;
        uint32_t off = (uint32_t)(row * 128 + ((ch ^ (row & 7)) << 4));
        cp16(sK + off, Kg + row * 64 + ch * 8);
        cp16(sV + off, Vg + row * 64 + ch * 8);
    }
    CP_COMMIT();
    CP_WAIT0();
    __syncthreads();

    // ---- QK^T ----
    float c[2][8][4];
    #pragma unroll
    for (int mt = 0; mt < 2; mt++)
        #pragma unroll
        for (int nt = 0; nt < 8; nt++)
            #pragma unroll
            for (int q = 0; q < 4; q++) c[mt][nt][q] = 0.f;

    #pragma unroll
    for (int ks = 0; ks < 4; ks++) {
        uint32_t a[2][4];
        #pragma unroll
        for (int mt = 0; mt < 2; mt++) {
            int row = m0 + mt * 16 + (phase & 1) * 8 + lrow;
            int ch  = ks * 2 + (phase >> 1);
            ldm_x4(a[mt], sQ + (uint32_t)(row * 128 + ((ch ^ (row & 7)) << 4)));
        }
        uint32_t bf[4][4];
        #pragma unroll
        for (int ng = 0; ng < 4; ng++) {
            int row = ng * 16 + (phase >> 1) * 8 + lrow;
            int ch  = ks * 2 + (phase & 1);
            ldm_x4(bf[ng], sK + (uint32_t)(row * 128 + ((ch ^ (row & 7)) << 4)));
        }
        #pragma unroll
        for (int nt = 0; nt < 8; nt++) {
            uint32_t b0 = bf[nt >> 1][(nt & 1) * 2];
            uint32_t b1 = bf[nt >> 1][(nt & 1) * 2 + 1];
            MMAF16(c[0][nt], a[0], b0, b1);
            MMAF16(c[1][nt], a[1], b0, b1);
        }
    }

    // ---- softmax ----
    float inv[2][2];
    #pragma unroll
    for (int mt = 0; mt < 2; mt++) {
        float mx0 = -INFINITY, mx1 = -INFINITY;
        #pragma unroll
        for (int nt = 0; nt < 8; nt++) {
            #pragma unroll
            for (int q = 0; q < 4; q++) c[mt][nt][q] *= 0.125f;
            mx0 = fmaxf(mx0, fmaxf(c[mt][nt][0], c[mt][nt][1]));
            mx1 = fmaxf(mx1, fmaxf(c[mt][nt][2], c[mt][nt][3]));
        }
        mx0 = fmaxf(mx0, __shfl_xor_sync(0xffffffffu, mx0, 1));
        mx0 = fmaxf(mx0, __shfl_xor_sync(0xffffffffu, mx0, 2));
        mx1 = fmaxf(mx1, __shfl_xor_sync(0xffffffffu, mx1, 1));
        mx1 = fmaxf(mx1, __shfl_xor_sync(0xffffffffu, mx1, 2));
        float s0 = 0.f, s1 = 0.f;
        #pragma unroll
        for (int nt = 0; nt < 8; nt++) {
            c[mt][nt][0] = expf(c[mt][nt][0] - mx0);
            c[mt][nt][1] = expf(c[mt][nt][1] - mx0);
            c[mt][nt][2] = expf(c[mt][nt][2] - mx1);
            c[mt][nt][3] = expf(c[mt][nt][3] - mx1);
            s0 += c[mt][nt][0] + c[mt][nt][1];
            s1 += c[mt][nt][2] + c[mt][nt][3];
        }
        s0 += __shfl_xor_sync(0xffffffffu, s0, 1);
        s0 += __shfl_xor_sync(0xffffffffu, s0, 2);
        s1 += __shfl_xor_sync(0xffffffffu, s1, 1);
        s1 += __shfl_xor_sync(0xffffffffu, s1, 2);
        inv[mt][0] = 1.f / s0;
        inv[mt][1] = 1.f / s1;
    }

    // ---- w staging + fp16 A fragments ----
    uint32_t wh[2][4][4];
    #pragma unroll
    for (int mt = 0; mt < 2; mt++) {
        int r0 = m0 + mt * 16 + qrow;
        #pragma unroll
        for (int nt = 0; nt < 8; nt++) {
            float w0 = c[mt][nt][0] * inv[mt][0];
            float w1 = c[mt][nt][1] * inv[mt][0];
            float w2 = c[mt][nt][2] * inv[mt][1];
            float w3 = c[mt][nt][3] * inv[mt][1];
            int col = nt * 8 + qk;
            wsm[r0 * 68 + col] = w0;       wsm[r0 * 68 + col + 1] = w1;
            wsm[(r0 + 8) * 68 + col] = w2; wsm[(r0 + 8) * 68 + col + 1] = w3;
            int j = nt >> 1;
            if ((nt & 1) == 0) {
                wh[mt][j][0] = packh2(w0, w1);
                wh[mt][j][1] = packh2(w2, w3);
            } else {
                wh[mt][j][2] = packh2(w0, w1);
                wh[mt][j][3] = packh2(w2, w3);
            }
        }
    }

    // ---- AV ----
    float o[2][8][4];
    #pragma unroll
    for (int mt = 0; mt < 2; mt++)
        #pragma unroll
        for (int nt = 0; nt < 8; nt++)
            #pragma unroll
            for (int q = 0; q < 4; q++) o[mt][nt][q] = 0.f;

    #pragma unroll
    for (int j = 0; j < 4; j++) {
        uint32_t bf[4][4];
        #pragma unroll
        for (int ng = 0; ng < 4; ng++) {
            int row = ng * 16 + (phase >> 1) * 8 + lrow;
            int ch  = j * 2 + (phase & 1);
            ldm_x4(bf[ng], sV + (uint32_t)(row * 128 + ((ch ^ (row & 7)) << 4)));
        }
        #pragma unroll
        for (int nt = 0; nt < 8; nt++) {
            uint32_t b0 = bf[nt >> 1][(nt & 1) * 2];
            uint32_t b1 = bf[nt >> 1][(nt & 1) * 2 + 1];
            MMAF16(o[0][nt], wh[0][j], b0, b1);
            MMAF16(o[1][nt], wh[1][j], b0, b1);
        }
    }

    // ---- coalesced w write ----
    __syncthreads();
    float* wb = w_out + ((size_t)((b * HH + h) * SS + chunk * 256)) * LL;
    #pragma unroll
    for (int i = 0; i < 16; i++) {
        int idx = t + i * 256;
        int row = idx >> 4, c4 = idx & 15;
        *(float4*)(wb + row * 64 + c4 * 4) = *(const float4*)(wsm + row * 68 + c4 * 4);
    }
    __syncthreads();

    // ---- ctx -> fp16 staging + coalesced write ----
    #pragma unroll
    for (int mt = 0; mt < 2; mt++) {
        int r0 = m0 + mt * 16 + qrow;
        #pragma unroll
        for (int nt = 0; nt < 8; nt++) {
            int col = nt * 8 + qk;
            *(__half2*)(csm + r0 * 72 + col)       = __floats2half2_rn(o[mt][nt][0], o[mt][nt][1]);
            *(__half2*)(csm + (r0 + 8) * 72 + col) = __floats2half2_rn(o[mt][nt][2], o[mt][nt][3]);
        }
    }
    __syncthreads();
    __half* cb = ctxh + ((size_t)(b * SS + chunk * 256)) * EE + h * 64;
    #pragma unroll
    for (int i = 0; i < 8; i++) {
        int idx = t + i * 256;
        int row = idx >> 3, seg = idx & 7;
        *(uint4*)(cb + (size_t)row * EE + seg * 8) = *(const uint4*)(csm + row * 72 + seg * 8);
    }
}

// ===================== launch ===============================================
extern "C" void kernel_launch(void* const* d_in, const int* in_sizes, int n_in,
                              void* d_out, int out_size)
{
    const float* query = (const float*)d_in[0];
    const float* key   = (const float*)d_in[1];
    const float* value = (const float*)d_in[2];
    const float* Wq = (const float*)d_in[3];
    const float* bq = (const float*)d_in[4];
    const float* Wk = (const float*)d_in[5];
    const float* bk = (const float*)d_in[6];
    const float* Wv = (const float*)d_in[7];
    const float* bv = (const float*)d_in[8];
    const float* Wo = (const float*)d_in[9];
    const float* bo = (const float*)d_in[10];

    float* out  = (float*)d_out;
    float* wout = out + MSZ;

    float *pSsq, *pScores, *pKex, *pVex, *pScex;
    __half *pQh, *pAqh, *pAkh, *pWqh, *pWkh, *pWoh, *pKsph, *pVspt;
    int *pIdxc, *pNcand, *pIdxf, *pCandf;
    cudaGetSymbolAddress((void**)&pQh, g_Qh);
    cudaGetSymbolAddress((void**)&pAqh, g_Aqh);
    cudaGetSymbolAddress((void**)&pAkh, g_Akh);
    cudaGetSymbolAddress((void**)&pWqh, g_Wqh);
    cudaGetSymbolAddress((void**)&pWkh, g_Wkh);
    cudaGetSymbolAddress((void**)&pWoh, g_Woh);
    cudaGetSymbolAddress((void**)&pSsq, g_ssq);
    cudaGetSymbolAddress((void**)&pScores, g_scores);
    cudaGetSymbolAddress((void**)&pIdxc, g_idxc);
    cudaGetSymbolAddress((void**)&pNcand, g_ncand);
    cudaGetSymbolAddress((void**)&pKex, g_kex);
    cudaGetSymbolAddress((void**)&pVex, g_vex);
    cudaGetSymbolAddress((void**)&pScex, g_scex);
    cudaGetSymbolAddress((void**)&pIdxf, g_idxf);
    cudaGetSymbolAddress((void**)&pCandf, g_candf);
    cudaGetSymbolAddress((void**)&pKsph, g_Ksph);
    cudaGetSymbolAddress((void**)&pVspt, g_Vspt);

    cudaFuncSetAttribute((void*)gemm_f16<0>, cudaFuncAttributeMaxDynamicSharedMemorySize, GEMM_SMEM);
    cudaFuncSetAttribute((void*)gemm_qk, cudaFuncAttributeMaxDynamicSharedMemorySize, GEMM_SMEM);
    cudaFuncSetAttribute((void*)attn_mma, cudaFuncAttributeMaxDynamicSharedMemorySize, ATTN_SMEM);

    const int n4m = (int)(MSZ / 4);
    const int n4w = EE * EE / 4;

    // conversions
    dim3 cw(n4w / 256, 3);
    conv3_f16<<<cw, 256>>>(Wq, pWqh, Wk, pWkh, Wo, pWoh, n4w);
    conv_f16<<<n4m / 256, 256>>>(query, pAqh, n4m);
    conv_f16<<<n4m / 256, 256>>>(key, pAkh, n4m);

    // Q GEMM (fp16 out) + K GEMM (ssq out), merged
    dim3 qkgrid(4, 256, 2);
    gemm_qk<<<qkgrid, 256, GEMM_SMEM>>>(pAqh, pWqh, bq, pQh,
                                        pAkh, pWkh, bk, pSsq);

    // scores -> radix-select top-96 superset
    scores_ssq<<<MROWS / 256, 256>>>(pSsq, pScores);
    topk_radix<<<BB, 256>>>(pScores, pIdxc, pNcand);

    // exact fp32 K+V candidate rows, exact scores, exact top-64
    dim3 pgrid(16, BB, 2);
    project_rows2<<<pgrid, 256>>>(key, Wk, bk, pKex, value, Wv, bv, pVex, pIdxc);
    scores_kernel<<<(BB * NCMAX) / 8, 256>>>(pKex, pScex);
    topk_refine_kernel<<<BB, 128>>>(pScex, pIdxc, pNcand, pIdxf, pCandf);
    gatherperm_f16<<<(BB * HH * LL * DD) / 256, 256>>>(pKex, pVex, pCandf, pKsph, pVspt);

    // tensor-core attention (256-row blocks)
    dim3 agrid(SS / 256, HH, BB);
    attn_mma<<<agrid, 256, ATTN_SMEM>>>(pQh, pKsph, pVspt, wout, pAqh);

    // out = fp16(ctx) @ fp16(Wo)^T + bo
    dim3 ggrid(4, 256);
    gemm_f16<0><<<ggrid, 256, GEMM_SMEM>>>(pAqh, pWoh, bo, out);
}

// round 15
// speedup vs baseline: 4.0294x; 1.0573x over previous
#include <cuda_runtime.h>
#include <cuda_fp16.h>
#include <math.h>
#include <stdint.h>

#define BB 4
#define SS 8192
#define EE 1024
#define HH 16
#define DD 64
#define LL 64
#define NCAND 96
#define NCMAX 128
#define MROWS (BB * SS)
#define MSZ   ((size_t)MROWS * EE)

// ===================== scratch ==============================================
__device__ __half g_Qh[MSZ];
__device__ __half g_Aqh[MSZ];         // query fp16 in; reused as fp16 ctx
__device__ __half g_Akh[MSZ];
__device__ __half g_Wqh[EE * EE];
__device__ __half g_Wkh[EE * EE];
__device__ __half g_Woh[EE * EE];
__device__ float g_ssq[MROWS * HH];
__device__ float g_scores[BB * SS];
__device__ int   g_idxc[BB * NCMAX];
__device__ int   g_ncand[BB];
__device__ float g_kex[BB * NCMAX * EE];
__device__ float g_vex[BB * NCMAX * EE];
__device__ float g_scex[BB * NCMAX];
__device__ int   g_idxf[BB * LL];
__device__ int   g_candf[BB * LL];
__device__ __half g_Ksph[BB * HH * LL * DD];   // [b,h,l,d]
__device__ __half g_Vspt[BB * HH * DD * LL];   // [b,h,d,l]

// ===================== small PTX helpers ====================================
__device__ __forceinline__ uint32_t smem_u32(const void* p) {
    uint32_t a;
    asm("{ .reg .u64 t; cvta.to.shared.u64 t, %1; cvt.u32.u64 %0, t; }" : "=r"(a) : "l"(p));
    return a;
}
__device__ __forceinline__ void cp16(uint32_t dst, const void* src) {
    asm volatile("cp.async.cg.shared.global [%0], [%1], 16;" :: "r"(dst), "l"(src));
}
#define CP_COMMIT() asm volatile("cp.async.commit_group;" ::: "memory")
#define CP_WAIT1()  asm volatile("cp.async.wait_group 1;" ::: "memory")
#define CP_WAIT0()  asm volatile("cp.async.wait_group 0;" ::: "memory")
__device__ __forceinline__ void ldm_x4(uint32_t* r, uint32_t addr) {
    asm volatile("ldmatrix.sync.aligned.m8n8.x4.shared.b16 {%0,%1,%2,%3}, [%4];"
                 : "=r"(r[0]), "=r"(r[1]), "=r"(r[2]), "=r"(r[3]) : "r"(addr));
}
#define MMAF16(d, a, b0, b1) \
    asm volatile("mma.sync.aligned.m16n8k16.row.col.f32.f16.f16.f32 " \
        "{%0,%1,%2,%3}, {%4,%5,%6,%7}, {%8,%9}, {%0,%1,%2,%3};" \
        : "+f"((d)[0]), "+f"((d)[1]), "+f"((d)[2]), "+f"((d)[3]) \
        : "r"((a)[0]), "r"((a)[1]), "r"((a)[2]), "r"((a)[3]), \
          "r"(b0), "r"(b1))
__device__ __forceinline__ uint32_t packh2(float a, float b) {
    __half2 h = __floats2half2_rn(a, b);
    return *(uint32_t*)&h;
}

// ===================== fp32 -> fp16 conversions ==============================
// query+key fused (blockIdx.y selects)
__global__ __launch_bounds__(256) void conv2_f16(
    const float* __restrict__ x0, __half* __restrict__ h0,
    const float* __restrict__ x1, __half* __restrict__ h1, int n4)
{
    int i = blockIdx.x * 256 + threadIdx.x;
    if (i >= n4) return;
    const float* x = blockIdx.y ? x1 : x0;
    __half* h = blockIdx.y ? h1 : h0;
    float4 v = ((const float4*)x)[i];
    uint32_t a0 = (uint32_t)__half_as_ushort(__float2half(v.x));
    uint32_t a1 = (uint32_t)__half_as_ushort(__float2half(v.y));
    uint32_t a2 = (uint32_t)__half_as_ushort(__float2half(v.z));
    uint32_t a3 = (uint32_t)__half_as_ushort(__float2half(v.w));
    uint2 hp; hp.x = a0 | (a1 << 16); hp.y = a2 | (a3 << 16);
    ((uint2*)h)[i] = hp;
}

__global__ __launch_bounds__(256) void conv3_f16(
    const float* __restrict__ x0, __half* __restrict__ h0,
    const float* __restrict__ x1, __half* __restrict__ h1,
    const float* __restrict__ x2, __half* __restrict__ h2, int n4)
{
    int i = blockIdx.x * 256 + threadIdx.x;
    if (i >= n4) return;
    const float* x = blockIdx.y == 0 ? x0 : (blockIdx.y == 1 ? x1 : x2);
    __half* h = blockIdx.y == 0 ? h0 : (blockIdx.y == 1 ? h1 : h2);
    float4 v = ((const float4*)x)[i];
    uint32_t a0 = (uint32_t)__half_as_ushort(__float2half(v.x));
    uint32_t a1 = (uint32_t)__half_as_ushort(__float2half(v.y));
    uint32_t a2 = (uint32_t)__half_as_ushort(__float2half(v.z));
    uint32_t a3 = (uint32_t)__half_as_ushort(__float2half(v.w));
    uint2 hp; hp.x = a0 | (a1 << 16); hp.y = a2 | (a3 << 16);
    ((uint2*)h)[i] = hp;
}

// ===================== fp16 GEMM (R13 proven mainloop) ======================
#define GSTAGE 49152u
#define GEMM_SMEM (3 * 49152)

// EPI=0: fp32 C + bias (out GEMM).
template<int EPI>
__global__ __launch_bounds__(256) void gemm_f16(
    const __half* __restrict__ A, const __half* __restrict__ W,
    const float* __restrict__ bias, void* __restrict__ Cv)
{
    extern __shared__ __align__(128) char dsm[];
    const uint32_t sbase = smem_u32(dsm);
    const int tid  = threadIdx.x;
    const int lane = tid & 31;
    const int wid  = tid >> 5;
    const int bm = blockIdx.y * 128;
    const int bn = blockIdx.x * 256;
    const int m0 = (wid & 1) * 64;
    const int n0 = (wid >> 1) * 64;
    const int qrow = lane >> 2;
    const int qk   = (lane & 3) * 2;
    const int lrow  = lane & 7;
    const int phase = lane >> 3;
    const int g_c  = tid & 7;
    const int g_r0 = tid >> 3;

    float c[4][8][4];
    #pragma unroll
    for (int mt = 0; mt < 4; mt++)
        #pragma unroll
        for (int nt = 0; nt < 8; nt++)
            #pragma unroll
            for (int q = 0; q < 4; q++) c[mt][nt][q] = 0.f;

    auto load_tile = [&](int kt) {
        if (kt < 16) {
            const uint32_t sA = sbase + (uint32_t)(kt % 3) * GSTAGE;
            const uint32_t sB = sA + 16384u;
            const int kk = kt << 6;
            #pragma unroll
            for (int i = 0; i < 4; i++) {
                int row = g_r0 + i * 32;
                uint32_t off = (uint32_t)(row * 128 + ((g_c ^ (row & 7)) << 4));
                cp16(sA + off, A + (size_t)(bm + row) * 1024 + kk + g_c * 8);
            }
            #pragma unroll
            for (int i = 0; i < 8; i++) {
                int row = g_r0 + i * 32;
                uint32_t off = (uint32_t)(row * 128 + ((g_c ^ (row & 7)) << 4));
                cp16(sB + off, W + (size_t)(bn + row) * 1024 + kk + g_c * 8);
            }
        }
        CP_COMMIT();
    };

    load_tile(0);
    load_tile(1);

    for (int kt = 0; kt < 16; kt++) {
        CP_WAIT1();
        __syncthreads();
        load_tile(kt + 2);
        const uint32_t aB = sbase + (uint32_t)(kt % 3) * GSTAGE;
        const uint32_t bB = aB + 16384u;
        #pragma unroll
        for (int ks = 0; ks < 4; ks++) {
            const int c0 = ks * 2;
            uint32_t a[4][4];
            #pragma unroll
            for (int mt = 0; mt < 4; mt++) {
                int row = m0 + mt * 16 + (phase & 1) * 8 + lrow;
                int ch  = c0 + (phase >> 1);
                ldm_x4(a[mt], aB + (uint32_t)(row * 128 + ((ch ^ (row & 7)) << 4)));
            }
            uint32_t bf[4][4];
            #pragma unroll
            for (int ng = 0; ng < 4; ng++) {
                int row = n0 + ng * 16 + (phase >> 1) * 8 + lrow;
                int ch  = c0 + (phase & 1);
                ldm_x4(bf[ng], bB + (uint32_t)(row * 128 + ((ch ^ (row & 7)) << 4)));
            }
            #pragma unroll
            for (int nt = 0; nt < 8; nt++) {
                uint32_t b0 = bf[nt >> 1][(nt & 1) * 2];
                uint32_t b1 = bf[nt >> 1][(nt & 1) * 2 + 1];
                #pragma unroll
                for (int mt = 0; mt < 4; mt++)
                    MMAF16(c[mt][nt], a[mt], b0, b1);
            }
        }
        __syncthreads();
    }

    float* C = (float*)Cv;
    #pragma unroll
    for (int mt = 0; mt < 4; mt++) {
        #pragma unroll
        for (int nt = 0; nt < 8; nt++) {
            int r0  = bm + m0 + mt * 16 + qrow;
            int col = bn + n0 + nt * 8 + qk;
            float2 bv = *(const float2*)(bias + col);
            float2 o0, o1;
            o0.x = c[mt][nt][0] + bv.x; o0.y = c[mt][nt][1] + bv.y;
            o1.x = c[mt][nt][2] + bv.x; o1.y = c[mt][nt][3] + bv.y;
            *(float2*)(C + (size_t)r0 * 1024 + col) = o0;
            *(float2*)(C + (size_t)(r0 + 8) * 1024 + col) = o1;
        }
    }
}

// Merged Q+K GEMM: z=0 -> Q (fp16 out), z=1 -> K (ssq out).
__global__ __launch_bounds__(256) void gemm_qk(
    const __half* __restrict__ A0, const __half* __restrict__ W0,
    const float* __restrict__ b0, __half* __restrict__ C0,
    const __half* __restrict__ A1, const __half* __restrict__ W1,
    const float* __restrict__ b1, float* __restrict__ C1)
{
    extern __shared__ __align__(128) char dsm[];
    const uint32_t sbase = smem_u32(dsm);
    const int z = blockIdx.z;
    const __half* A = z ? A1 : A0;
    const __half* W = z ? W1 : W0;
    const float* bias = z ? b1 : b0;

    const int tid  = threadIdx.x;
    const int lane = tid & 31;
    const int wid  = tid >> 5;
    const int bm = blockIdx.y * 128;
    const int bn = blockIdx.x * 256;
    const int m0 = (wid & 1) * 64;
    const int n0 = (wid >> 1) * 64;
    const int qrow = lane >> 2;
    const int qk   = (lane & 3) * 2;
    const int lrow  = lane & 7;
    const int phase = lane >> 3;
    const int g_c  = tid & 7;
    const int g_r0 = tid >> 3;

    float c[4][8][4];
    #pragma unroll
    for (int mt = 0; mt < 4; mt++)
        #pragma unroll
        for (int nt = 0; nt < 8; nt++)
            #pragma unroll
            for (int q = 0; q < 4; q++) c[mt][nt][q] = 0.f;

    auto load_tile = [&](int kt) {
        if (kt < 16) {
            const uint32_t sA = sbase + (uint32_t)(kt % 3) * GSTAGE;
            const uint32_t sB = sA + 16384u;
            const int kk = kt << 6;
            #pragma unroll
            for (int i = 0; i < 4; i++) {
                int row = g_r0 + i * 32;
                uint32_t off = (uint32_t)(row * 128 + ((g_c ^ (row & 7)) << 4));
                cp16(sA + off, A + (size_t)(bm + row) * 1024 + kk + g_c * 8);
            }
            #pragma unroll
            for (int i = 0; i < 8; i++) {
                int row = g_r0 + i * 32;
                uint32_t off = (uint32_t)(row * 128 + ((g_c ^ (row & 7)) << 4));
                cp16(sB + off, W + (size_t)(bn + row) * 1024 + kk + g_c * 8);
            }
        }
        CP_COMMIT();
    };

    load_tile(0);
    load_tile(1);

    for (int kt = 0; kt < 16; kt++) {
        CP_WAIT1();
        __syncthreads();
        load_tile(kt + 2);
        const uint32_t aB = sbase + (uint32_t)(kt % 3) * GSTAGE;
        const uint32_t bB = aB + 16384u;
        #pragma unroll
        for (int ks = 0; ks < 4; ks++) {
            const int c0 = ks * 2;
            uint32_t a[4][4];
            #pragma unroll
            for (int mt = 0; mt < 4; mt++) {
                int row = m0 + mt * 16 + (phase & 1) * 8 + lrow;
                int ch  = c0 + (phase >> 1);
                ldm_x4(a[mt], aB + (uint32_t)(row * 128 + ((ch ^ (row & 7)) << 4)));
            }
            uint32_t bf[4][4];
            #pragma unroll
            for (int ng = 0; ng < 4; ng++) {
                int row = n0 + ng * 16 + (phase >> 1) * 8 + lrow;
                int ch  = c0 + (phase & 1);
                ldm_x4(bf[ng], bB + (uint32_t)(row * 128 + ((ch ^ (row & 7)) << 4)));
            }
            #pragma unroll
            for (int nt = 0; nt < 8; nt++) {
                uint32_t p0 = bf[nt >> 1][(nt & 1) * 2];
                uint32_t p1 = bf[nt >> 1][(nt & 1) * 2 + 1];
                #pragma unroll
                for (int mt = 0; mt < 4; mt++)
                    MMAF16(c[mt][nt], a[mt], p0, p1);
            }
        }
        __syncthreads();
    }

    if (z == 0) {
        __half* C = C0;
        #pragma unroll
        for (int mt = 0; mt < 4; mt++) {
            #pragma unroll
            for (int nt = 0; nt < 8; nt++) {
                int r0  = bm + m0 + mt * 16 + qrow;
                int col = bn + n0 + nt * 8 + qk;
                float2 bv = *(const float2*)(bias + col);
                __half2 h0 = __floats2half2_rn(c[mt][nt][0] + bv.x, c[mt][nt][1] + bv.y);
                __half2 h1 = __floats2half2_rn(c[mt][nt][2] + bv.x, c[mt][nt][3] + bv.y);
                *(__half2*)(C + (size_t)r0 * 1024 + col) = h0;
                *(__half2*)(C + (size_t)(r0 + 8) * 1024 + col) = h1;
            }
        }
    } else {
        float* C = C1;
        const int head = (bn + n0) >> 6;
        #pragma unroll
        for (int mt = 0; mt < 4; mt++) {
            float s0 = 0.f, s1 = 0.f;
            #pragma unroll
            for (int nt = 0; nt < 8; nt++) {
                int col = bn + n0 + nt * 8 + qk;
                float2 bv = *(const float2*)(bias + col);
                float v0 = c[mt][nt][0] + bv.x, v1 = c[mt][nt][1] + bv.y;
                float v2 = c[mt][nt][2] + bv.x, v3 = c[mt][nt][3] + bv.y;
                s0 += v0 * v0 + v1 * v1;
                s1 += v2 * v2 + v3 * v3;
            }
            s0 += __shfl_xor_sync(0xffffffffu, s0, 1);
            s0 += __shfl_xor_sync(0xffffffffu, s0, 2);
            s1 += __shfl_xor_sync(0xffffffffu, s1, 1);
            s1 += __shfl_xor_sync(0xffffffffu, s1, 2);
            if ((lane & 3) == 0) {
                int r = bm + m0 + mt * 16 + qrow;
                C[(size_t)r * HH + head] = s0;
                C[(size_t)(r + 8) * HH + head] = s1;
            }
        }
    }
}

// ===================== scores from ssq ======================================
__global__ __launch_bounds__(256) void scores_ssq(
    const float* __restrict__ ssq, float* __restrict__ scores)
{
    int row = blockIdx.x * 256 + threadIdx.x;
    const float* sp = ssq + (size_t)row * HH;
    float acc = 0.f;
    #pragma unroll
    for (int h = 0; h < HH; h++) acc += sqrtf(sp[h]);
    scores[row] = acc * (1.f / 16.f);
}

// ===================== scores of fp32 rows (candidate rescoring) ============
__global__ __launch_bounds__(256) void scores_kernel(
    const float* __restrict__ Km, float* __restrict__ scores)
{
    int row  = blockIdx.x * 8 + (threadIdx.x >> 5);
    int lane = threadIdx.x & 31;
    const float* kr = Km + (size_t)row * EE;
    float acc = 0.f;
    #pragma unroll
    for (int h = 0; h < HH; h++) {
        float x0 = kr[h * 64 + lane];
        float x1 = kr[h * 64 + 32 + lane];
        float ss = x0 * x0 + x1 * x1;
        #pragma unroll
        for (int o = 16; o > 0; o >>= 1)
            ss += __shfl_xor_sync(0xffffffffu, ss, o);
        acc += sqrtf(ss);
    }
    if (lane == 0) scores[row] = acc * (1.f / 16.f);
}

// ===================== radix-select top-96 superset (<=128) =================
__global__ __launch_bounds__(256) void topk_radix(
    const float* __restrict__ scores, int* __restrict__ idxout,
    int* __restrict__ ncand)
{
    __shared__ int hist[256];
    __shared__ unsigned s_prefix;
    __shared__ int s_remaining;
    __shared__ int s_cnt;
    const int b = blockIdx.x, t = threadIdx.x;
    const float* sp = scores + b * SS;

    if (t == 0) { s_prefix = 0; s_remaining = NCAND; s_cnt = 0; }
    __syncthreads();

    for (int round = 0; round < 4; round++) {
        const int shift = 24 - 8 * round;
        hist[t] = 0;
        __syncthreads();
        const unsigned pfx = s_prefix;
        for (int i = t; i < SS; i += 256) {
            unsigned key = __float_as_uint(sp[i]);
            bool match = (round == 0) || (((key ^ pfx) >> (shift + 8)) == 0);
            if (match) atomicAdd(&hist[(key >> shift) & 255], 1);
        }
        __syncthreads();
        if (t == 0) {
            int rem = s_remaining, cum = 0, bin = 255;
            for (; bin > 0; bin--) {
                cum += hist[bin];
                if (cum >= rem) break;
            }
            if (cum < rem) cum += hist[0];
            s_remaining = rem - (cum - hist[bin]);
            s_prefix = pfx | ((unsigned)bin << shift);
        }
        __syncthreads();
    }
    const unsigned thresh = s_prefix;
    for (int i = t; i < SS; i += 256) {
        unsigned key = __float_as_uint(sp[i]);
        if (key >= thresh) {
            int pos = atomicAdd(&s_cnt, 1);
            if (pos < NCMAX) idxout[b * NCMAX + pos] = i;
        }
    }
    __syncthreads();
    int c = s_cnt < NCMAX ? s_cnt : NCMAX;
    if (t == 0) ncand[b] = c;
    for (int i = c + t; i < NCMAX; i += 256) idxout[b * NCMAX + i] = 0;
}

// ===================== exact fp32 projection (512 thr, K/V via z) ===========
__global__ __launch_bounds__(512) void project_rows2(
    const float* __restrict__ X0, const float* __restrict__ W0,
    const float* __restrict__ b0, float* __restrict__ o0,
    const float* __restrict__ X1, const float* __restrict__ W1,
    const float* __restrict__ b1, float* __restrict__ o1,
    const int* __restrict__ idx)
{
    __shared__ float xs[NCMAX * 32];
    __shared__ float ws[32 * 64];
    const int b = blockIdx.y;
    const int e0 = blockIdx.x * 64;
    const float* X  = blockIdx.z ? X1 : X0;
    const float* Wt = blockIdx.z ? W1 : W0;
    const float* bias = blockIdx.z ? b1 : b0;
    float* outp = blockIdx.z ? o1 : o0;
    const int t = threadIdx.x, tx = t & 15, ty = t >> 4;   // ty 0..31

    float acc[4][4];
    #pragma unroll
    for (int c = 0; c < 4; c++)
        #pragma unroll
        for (int j = 0; j < 4; j++) acc[c][j] = 0.f;

    for (int kt = 0; kt < EE; kt += 32) {
        __syncthreads();
        for (int u = t; u < NCMAX * 8; u += 512) {
            int cand = u >> 3, c4 = u & 7;
            int s = idx[b * NCMAX + cand];
            float4 v = *(const float4*)(X + ((size_t)(b * SS + s)) * EE + kt + c4 * 4);
            *(float4*)(xs + cand * 32 + c4 * 4) = v;
        }
        {
            int e = t >> 3, c4 = t & 7;
            float4 v = *(const float4*)(Wt + (size_t)(e0 + e) * EE + kt + c4 * 4);
            ws[(c4 * 4 + 0) * 64 + e] = v.x;
            ws[(c4 * 4 + 1) * 64 + e] = v.y;
            ws[(c4 * 4 + 2) * 64 + e] = v.z;
            ws[(c4 * 4 + 3) * 64 + e] = v.w;
        }
        __syncthreads();
        #pragma unroll 8
        for (int k = 0; k < 32; k++) {
            float wv[4];
            #pragma unroll
            for (int j = 0; j < 4; j++) wv[j] = ws[k * 64 + tx * 4 + j];
            #pragma unroll
            for (int c = 0; c < 4; c++) {
                float a = xs[(ty * 4 + c) * 32 + k];
                #pragma unroll
                for (int j = 0; j < 4; j++) acc[c][j] = fmaf(a, wv[j], acc[c][j]);
            }
        }
    }
    #pragma unroll
    for (int c = 0; c < 4; c++) {
        int cand = ty * 4 + c;
        #pragma unroll
        for (int j = 0; j < 4; j++) {
            int e = e0 + tx * 4 + j;
            outp[((size_t)b * NCMAX + cand) * EE + e] = acc[c][j] + bias[e];
        }
    }
}

// ===================== exact top-64 among candidates ========================
__global__ __launch_bounds__(128) void topk_refine_kernel(
    const float* __restrict__ scex, const int* __restrict__ idxc,
    const int* __restrict__ ncand,
    int* __restrict__ idxfin, int* __restrict__ candfin)
{
    __shared__ float sv[NCMAX];
    __shared__ int   si[NCMAX];
    __shared__ float rv[128];
    __shared__ int   rc[128];
    __shared__ int   rs[128];
    const int b = blockIdx.x, t = threadIdx.x;
    const int cnt = ncand[b];
    sv[t] = (t < cnt) ? scex[b * NCMAX + t] : -INFINITY;
    si[t] = (t < cnt) ? idxc[b * NCMAX + t] : 0x7fffffff;
    __syncthreads();
    for (int l = 0; l < LL; l++) {
        rv[t] = sv[t]; rc[t] = t; rs[t] = si[t];
        __syncthreads();
        for (int s = 64; s > 0; s >>= 1) {
            if (t < s) {
                if (rv[t + s] > rv[t] || (rv[t + s] == rv[t] && rs[t + s] < rs[t])) {
                    rv[t] = rv[t + s]; rc[t] = rc[t + s]; rs[t] = rs[t + s];
                }
            }
            __syncthreads();
        }
        if (t == 0) {
            idxfin[b * LL + l] = rs[0];
            candfin[b * LL + l] = rc[0];
            sv[rc[0]] = -INFINITY;
        }
        __syncthreads();
    }
}

// ===================== gather -> fp16 K [b,h,l,d] + V^T [b,h,d,l] ===========
__global__ __launch_bounds__(256) void gatherperm_f16(
    const float* __restrict__ kex, const float* __restrict__ vex,
    const int* __restrict__ candf,
    __half* __restrict__ Kh, __half* __restrict__ Vth)
{
    int i = blockIdx.x * 256 + threadIdx.x;
    int d = i & 63;
    int l = (i >> 6) & 63;
    int h = (i >> 12) & 15;
    int b = i >> 16;
    int cp = candf[b * LL + l];
    size_t src = ((size_t)b * NCMAX + cp) * EE + h * 64 + d;
    Kh[i] = __float2half(kex[src]);
    Vth[(((size_t)(b * HH + h)) << 12) + d * 64 + l] = __float2half(vex[src]);
}

// ===================== tensor-core attention (256 rows / 256 thr) ===========
#define ATTN_SMEM (49152 + 69632)

__global__ __launch_bounds__(256) void attn_mma(
    const __half* __restrict__ Qh, const __half* __restrict__ Kh,
    const __half* __restrict__ Vth, float* __restrict__ w_out,
    __half* __restrict__ ctxh)
{
    extern __shared__ __align__(128) char asmem[];
    const uint32_t sb = smem_u32(asmem);
    const uint32_t sQ = sb;
    const uint32_t sK = sb + 32768u;
    const uint32_t sV = sb + 40960u;
    float*  wsm = (float*)(asmem + 49152);
    __half* csm = (__half*)(asmem + 49152);

    const int b = blockIdx.z, h = blockIdx.y, chunk = blockIdx.x;
    const int t = threadIdx.x;
    const int lane = t & 31, wid = t >> 5;
    const int m0 = wid * 32;
    const int qrow = lane >> 2, qk = (lane & 3) * 2;
    const int lrow = lane & 7, phase = lane >> 3;

    const __half* Qg = Qh + ((size_t)(b * SS + chunk * 256)) * EE + h * 64;
    #pragma unroll
    for (int i = 0; i < 8; i++) {
        int idx = t + i * 256;
        int row = idx >> 3, ch = idx & 7;
        uint32_t off = (uint32_t)(row * 128 + ((ch ^ (row & 7)) << 4));
        cp16(sQ + off, Qg + (size_t)row * EE + ch * 8);
    }
    const __half* Kg = Kh + ((size_t)(b * HH + h) << 12);
    const __half* Vg = Vth + ((size_t)(b * HH + h) << 12);
    #pragma unroll
    for (int i = 0; i < 2; i++) {
        int idx = t + i * 256;
        int row = idx >> 3, ch = idx & 7;
        uint32_t off = (uint32_t)(row * 128 + ((ch ^ (row & 7)) << 4));
        cp16(sK + off, Kg + row * 64 + ch * 8);
        cp16(sV + off, Vg + row * 64 + ch * 8);
    }
    CP_COMMIT();
    CP_WAIT0();
    __syncthreads();

    float c[2][8][4];
    #pragma unroll
    for (int mt = 0; mt < 2; mt++)
        #pragma unroll
        for (int nt = 0; nt < 8; nt++)
            #pragma unroll
            for (int q = 0; q < 4; q++) c[mt][nt][q] = 0.f;

    #pragma unroll
    for (int ks = 0; ks < 4; ks++) {
        uint32_t a[2][4];
        #pragma unroll
        for (int mt = 0; mt < 2; mt++) {
            int row = m0 + mt * 16 + (phase & 1) * 8 + lrow;
            int ch  = ks * 2 + (phase >> 1);
            ldm_x4(a[mt], sQ + (uint32_t)(row * 128 + ((ch ^ (row & 7)) << 4)));
        }
        uint32_t bf[4][4];
        #pragma unroll
        for (int ng = 0; ng < 4; ng++) {
            int row = ng * 16 + (phase >> 1) * 8 + lrow;
            int ch  = ks * 2 + (phase & 1);
            ldm_x4(bf[ng], sK + (uint32_t)(row * 128 + ((ch ^ (row & 7)) << 4)));
        }
        #pragma unroll
        for (int nt = 0; nt < 8; nt++) {
            uint32_t b0 = bf[nt >> 1][(nt & 1) * 2];
            uint32_t b1 = bf[nt >> 1][(nt & 1) * 2 + 1];
            MMAF16(c[0][nt], a[0], b0, b1);
            MMAF16(c[1][nt], a[1], b0, b1);
        }
    }

    float inv[2][2];
    #pragma unroll
    for (int mt = 0; mt < 2; mt++) {
        float mx0 = -INFINITY, mx1 = -INFINITY;
        #pragma unroll
        for (int nt = 0; nt < 8; nt++) {
            #pragma unroll
            for (int q = 0; q < 4; q++) c[mt][nt][q] *= 0.125f;
            mx0 = fmaxf(mx0, fmaxf(c[mt][nt][0], c[mt][nt][1]));
            mx1 = fmaxf(mx1, fmaxf(c[mt][nt][2], c[mt][nt][3]));
        }
        mx0 = fmaxf(mx0, __shfl_xor_sync(0xffffffffu, mx0, 1));
        mx0 = fmaxf(mx0, __shfl_xor_sync(0xffffffffu, mx0, 2));
        mx1 = fmaxf(mx1, __shfl_xor_sync(0xffffffffu, mx1, 1));
        mx1 = fmaxf(mx1, __shfl_xor_sync(0xffffffffu, mx1, 2));
        float s0 = 0.f, s1 = 0.f;
        #pragma unroll
        for (int nt = 0; nt < 8; nt++) {
            c[mt][nt][0] = expf(c[mt][nt][0] - mx0);
            c[mt][nt][1] = expf(c[mt][nt][1] - mx0);
            c[mt][nt][2] = expf(c[mt][nt][2] - mx1);
            c[mt][nt][3] = expf(c[mt][nt][3] - mx1);
            s0 += c[mt][nt][0] + c[mt][nt][1];
            s1 += c[mt][nt][2] + c[mt][nt][3];
        }
        s0 += __shfl_xor_sync(0xffffffffu, s0, 1);
        s0 += __shfl_xor_sync(0xffffffffu, s0, 2);
        s1 += __shfl_xor_sync(0xffffffffu, s1, 1);
        s1 += __shfl_xor_sync(0xffffffffu, s1, 2);
        inv[mt][0] = 1.f / s0;
        inv[mt][1] = 1.f / s1;
    }

    uint32_t wh[2][4][4];
    #pragma unroll
    for (int mt = 0; mt < 2; mt++) {
        int r0 = m0 + mt * 16 + qrow;
        #pragma unroll
        for (int nt = 0; nt < 8; nt++) {
            float w0 = c[mt][nt][0] * inv[mt][0];
            float w1 = c[mt][nt][1] * inv[mt][0];
            float w2 = c[mt][nt][2] * inv[mt][1];
            float w3 = c[mt][nt][3] * inv[mt][1];
            int col = nt * 8 + qk;
            wsm[r0 * 68 + col] = w0;       wsm[r0 * 68 + col + 1] = w1;
            wsm[(r0 + 8) * 68 + col] = w2; wsm[(r0 + 8) * 68 + col + 1] = w3;
            int j = nt >> 1;
            if ((nt & 1) == 0) {
                wh[mt][j][0] = packh2(w0, w1);
                wh[mt][j][1] = packh2(w2, w3);
            } else {
                wh[mt][j][2] = packh2(w0, w1);
                wh[mt][j][3] = packh2(w2, w3);
            }
        }
    }

    float o[2][8][4];
    #pragma unroll
    for (int mt = 0; mt < 2; mt++)
        #pragma unroll
        for (int nt = 0; nt < 8; nt++)
            #pragma unroll
            for (int q = 0; q < 4; q++) o[mt][nt][q] = 0.f;

    #pragma unroll
    for (int j = 0; j < 4; j++) {
        uint32_t bf[4][4];
        #pragma unroll
        for (int ng = 0; ng < 4; ng++) {
            int row = ng * 16 + (phase >> 1) * 8 + lrow;
            int ch  = j * 2 + (phase & 1);
            ldm_x4(bf[ng], sV + (uint32_t)(row * 128 + ((ch ^ (row & 7)) << 4)));
        }
        #pragma unroll
        for (int nt = 0; nt < 8; nt++) {
            uint32_t b0 = bf[nt >> 1][(nt & 1) * 2];
            uint32_t b1 = bf[nt >> 1][(nt & 1) * 2 + 1];
            MMAF16(o[0][nt], wh[0][j], b0, b1);
            MMAF16(o[1][nt], wh[1][j], b0, b1);
        }
    }

    __syncthreads();
    float* wb = w_out + ((size_t)((b * HH + h) * SS + chunk * 256)) * LL;
    #pragma unroll
    for (int i = 0; i < 16; i++) {
        int idx = t + i * 256;
        int row = idx >> 4, c4 = idx & 15;
        *(float4*)(wb + row * 64 + c4 * 4) = *(const float4*)(wsm + row * 68 + c4 * 4);
    }
    __syncthreads();

    #pragma unroll
    for (int mt = 0; mt < 2; mt++) {
        int r0 = m0 + mt * 16 + qrow;
        #pragma unroll
        for (int nt = 0; nt < 8; nt++) {
            int col = nt * 8 + qk;
            *(__half2*)(csm + r0 * 72 + col)       = __floats2half2_rn(o[mt][nt][0], o[mt][nt][1]);
            *(__half2*)(csm + (r0 + 8) * 72 + col) = __floats2half2_rn(o[mt][nt][2], o[mt][nt][3]);
        }
    }
    __syncthreads();
    __half* cb = ctxh + ((size_t)(b * SS + chunk * 256)) * EE + h * 64;
    #pragma unroll
    for (int i = 0; i < 8; i++) {
        int idx = t + i * 256;
        int row = idx >> 3, seg = idx & 7;
        *(uint4*)(cb + (size_t)row * EE + seg * 8) = *(const uint4*)(csm + row * 72 + seg * 8);
    }
}

// ===================== launch ===============================================
extern "C" void kernel_launch(void* const* d_in, const int* in_sizes, int n_in,
                              void* d_out, int out_size)
{
    const float* query = (const float*)d_in[0];
    const float* key   = (const float*)d_in[1];
    const float* value = (const float*)d_in[2];
    const float* Wq = (const float*)d_in[3];
    const float* bq = (const float*)d_in[4];
    const float* Wk = (const float*)d_in[5];
    const float* bk = (const float*)d_in[6];
    const float* Wv = (const float*)d_in[7];
    const float* bv = (const float*)d_in[8];
    const float* Wo = (const float*)d_in[9];
    const float* bo = (const float*)d_in[10];

    float* out  = (float*)d_out;
    float* wout = out + MSZ;

    float *pSsq, *pScores, *pKex, *pVex, *pScex;
    __half *pQh, *pAqh, *pAkh, *pWqh, *pWkh, *pWoh, *pKsph, *pVspt;
    int *pIdxc, *pNcand, *pIdxf, *pCandf;
    cudaGetSymbolAddress((void**)&pQh, g_Qh);
    cudaGetSymbolAddress((void**)&pAqh, g_Aqh);
    cudaGetSymbolAddress((void**)&pAkh, g_Akh);
    cudaGetSymbolAddress((void**)&pWqh, g_Wqh);
    cudaGetSymbolAddress((void**)&pWkh, g_Wkh);
    cudaGetSymbolAddress((void**)&pWoh, g_Woh);
    cudaGetSymbolAddress((void**)&pSsq, g_ssq);
    cudaGetSymbolAddress((void**)&pScores, g_scores);
    cudaGetSymbolAddress((void**)&pIdxc, g_idxc);
    cudaGetSymbolAddress((void**)&pNcand, g_ncand);
    cudaGetSymbolAddress((void**)&pKex, g_kex);
    cudaGetSymbolAddress((void**)&pVex, g_vex);
    cudaGetSymbolAddress((void**)&pScex, g_scex);
    cudaGetSymbolAddress((void**)&pIdxf, g_idxf);
    cudaGetSymbolAddress((void**)&pCandf, g_candf);
    cudaGetSymbolAddress((void**)&pKsph, g_Ksph);
    cudaGetSymbolAddress((void**)&pVspt, g_Vspt);

    cudaFuncSetAttribute((void*)gemm_f16<0>, cudaFuncAttributeMaxDynamicSharedMemorySize, GEMM_SMEM);
    cudaFuncSetAttribute((void*)gemm_qk, cudaFuncAttributeMaxDynamicSharedMemorySize, GEMM_SMEM);
    cudaFuncSetAttribute((void*)attn_mma, cudaFuncAttributeMaxDynamicSharedMemorySize, ATTN_SMEM);

    const int n4m = (int)(MSZ / 4);
    const int n4w = EE * EE / 4;

    dim3 cw(n4w / 256, 3);
    conv3_f16<<<cw, 256>>>(Wq, pWqh, Wk, pWkh, Wo, pWoh, n4w);
    dim3 ca(n4m / 256, 2);
    conv2_f16<<<ca, 256>>>(query, pAqh, key, pAkh, n4m);

    // Q GEMM (fp16 out) + K GEMM (ssq out), merged
    dim3 qkgrid(4, 256, 2);
    gemm_qk<<<qkgrid, 256, GEMM_SMEM>>>(pAqh, pWqh, bq, pQh,
                                        pAkh, pWkh, bk, pSsq);

    scores_ssq<<<MROWS / 256, 256>>>(pSsq, pScores);
    topk_radix<<<BB, 256>>>(pScores, pIdxc, pNcand);

    dim3 pgrid(16, BB, 2);
    project_rows2<<<pgrid, 512>>>(key, Wk, bk, pKex, value, Wv, bv, pVex, pIdxc);
    scores_kernel<<<(BB * NCMAX) / 8, 256>>>(pKex, pScex);
    topk_refine_kernel<<<BB, 128>>>(pScex, pIdxc, pNcand, pIdxf, pCandf);
    gatherperm_f16<<<(BB * HH * LL * DD) / 256, 256>>>(pKex, pVex, pCandf, pKsph, pVspt);

    dim3 agrid(SS / 256, HH, BB);
    attn_mma<<<agrid, 256, ATTN_SMEM>>>(pQh, pKsph, pVspt, wout, pAqh);

    dim3 ggrid(4, 256);
    gemm_f16<0><<<ggrid, 256, GEMM_SMEM>>>(pAqh, pWoh, bo, out);
}

// round 16
// speedup vs baseline: 4.3168x; 1.0713x over previous
#include <cuda_runtime.h>
#include <cuda_fp16.h>
#include <math.h>
#include <stdint.h>

#define BB 4
#define SS 8192
#define EE 1024
#define HH 16
#define DD 64
#define LL 64
#define NCAND 96
#define NCMAX 128
#define MROWS (BB * SS)
#define MSZ   ((size_t)MROWS * EE)

// ===================== scratch ==============================================
__device__ __half g_Qh[MSZ];
__device__ __half g_Aqh[MSZ];         // query fp16 in; reused as fp16 ctx
__device__ __half g_Akh[MSZ];
__device__ __half g_Wqh[EE * EE];
__device__ __half g_Wkh[EE * EE];
__device__ __half g_Woh[EE * EE];
__device__ float g_ssq[MROWS * HH];
__device__ float g_scores[BB * SS];
__device__ int   g_idxc[BB * NCMAX];
__device__ int   g_ncand[BB];
__device__ float g_kex[BB * NCMAX * EE];
__device__ float g_vex[BB * NCMAX * EE];
__device__ float g_scex[BB * NCMAX];
__device__ int   g_idxf[BB * LL];
__device__ int   g_candf[BB * LL];
__device__ __half g_Ksph[BB * HH * LL * DD];   // [b,h,l,d]
__device__ __half g_Vspt[BB * HH * DD * LL];   // [b,h,d,l]

// ===================== small PTX helpers ====================================
__device__ __forceinline__ uint32_t smem_u32(const void* p) {
    uint32_t a;
    asm("{ .reg .u64 t; cvta.to.shared.u64 t, %1; cvt.u32.u64 %0, t; }" : "=r"(a) : "l"(p));
    return a;
}
__device__ __forceinline__ void cp16(uint32_t dst, const void* src) {
    asm volatile("cp.async.cg.shared.global [%0], [%1], 16;" :: "r"(dst), "l"(src));
}
#define CP_COMMIT() asm volatile("cp.async.commit_group;" ::: "memory")
#define CP_WAIT1()  asm volatile("cp.async.wait_group 1;" ::: "memory")
#define CP_WAIT0()  asm volatile("cp.async.wait_group 0;" ::: "memory")
__device__ __forceinline__ void ldm_x4(uint32_t* r, uint32_t addr) {
    asm volatile("ldmatrix.sync.aligned.m8n8.x4.shared.b16 {%0,%1,%2,%3}, [%4];"
                 : "=r"(r[0]), "=r"(r[1]), "=r"(r[2]), "=r"(r[3]) : "r"(addr));
}
#define MMAF16(d, a, b0, b1) \
    asm volatile("mma.sync.aligned.m16n8k16.row.col.f32.f16.f16.f32 " \
        "{%0,%1,%2,%3}, {%4,%5,%6,%7}, {%8,%9}, {%0,%1,%2,%3};" \
        : "+f"((d)[0]), "+f"((d)[1]), "+f"((d)[2]), "+f"((d)[3]) \
        : "r"((a)[0]), "r"((a)[1]), "r"((a)[2]), "r"((a)[3]), \
          "r"(b0), "r"(b1))
__device__ __forceinline__ uint32_t packh2(float a, float b) {
    __half2 h = __floats2half2_rn(a, b);
    return *(uint32_t*)&h;
}

// ===================== fp32 -> fp16 conversions ==============================
__global__ __launch_bounds__(256) void conv2_f16(
    const float* __restrict__ x0, __half* __restrict__ h0,
    const float* __restrict__ x1, __half* __restrict__ h1, int n4)
{
    int i = blockIdx.x * 256 + threadIdx.x;
    if (i >= n4) return;
    const float* x = blockIdx.y ? x1 : x0;
    __half* h = blockIdx.y ? h1 : h0;
    float4 v = ((const float4*)x)[i];
    uint32_t a0 = (uint32_t)__half_as_ushort(__float2half(v.x));
    uint32_t a1 = (uint32_t)__half_as_ushort(__float2half(v.y));
    uint32_t a2 = (uint32_t)__half_as_ushort(__float2half(v.z));
    uint32_t a3 = (uint32_t)__half_as_ushort(__float2half(v.w));
    uint2 hp; hp.x = a0 | (a1 << 16); hp.y = a2 | (a3 << 16);
    ((uint2*)h)[i] = hp;
}

__global__ __launch_bounds__(256) void conv3_f16(
    const float* __restrict__ x0, __half* __restrict__ h0,
    const float* __restrict__ x1, __half* __restrict__ h1,
    const float* __restrict__ x2, __half* __restrict__ h2, int n4)
{
    int i = blockIdx.x * 256 + threadIdx.x;
    if (i >= n4) return;
    const float* x = blockIdx.y == 0 ? x0 : (blockIdx.y == 1 ? x1 : x2);
    __half* h = blockIdx.y == 0 ? h0 : (blockIdx.y == 1 ? h1 : h2);
    float4 v = ((const float4*)x)[i];
    uint32_t a0 = (uint32_t)__half_as_ushort(__float2half(v.x));
    uint32_t a1 = (uint32_t)__half_as_ushort(__float2half(v.y));
    uint32_t a2 = (uint32_t)__half_as_ushort(__float2half(v.z));
    uint32_t a3 = (uint32_t)__half_as_ushort(__float2half(v.w));
    uint2 hp; hp.x = a0 | (a1 << 16); hp.y = a2 | (a3 << 16);
    ((uint2*)h)[i] = hp;
}

// ===================== zero ssq (for atomic accumulation) ====================
__global__ __launch_bounds__(256) void zero_ssq(float* __restrict__ p, int n4)
{
    int i = blockIdx.x * 256 + threadIdx.x;
    if (i < n4) ((float4*)p)[i] = make_float4(0.f, 0.f, 0.f, 0.f);
}

// ===================== fp16 GEMM: BM=128, BN=128, 2 CTAs/SM =================
// 256 thr, warp grid 2(M) x 4(N), warp tile 64x32. 3-stage cp.async, 32KB/stage.
#define GSTAGE 32768u
#define GEMM_SMEM (3 * 32768)

// EPI=0: fp32 C + bias (out GEMM).
__global__ __launch_bounds__(256, 2) void gemm_f16(
    const __half* __restrict__ A, const __half* __restrict__ W,
    const float* __restrict__ bias, float* __restrict__ C)
{
    extern __shared__ __align__(128) char dsm[];
    const uint32_t sbase = smem_u32(dsm);
    const int tid  = threadIdx.x;
    const int lane = tid & 31;
    const int wid  = tid >> 5;
    const int bm = blockIdx.y * 128;
    const int bn = blockIdx.x * 128;
    const int m0 = (wid & 1) * 64;
    const int n0 = (wid >> 1) * 32;
    const int qrow = lane >> 2;
    const int qk   = (lane & 3) * 2;
    const int lrow  = lane & 7;
    const int phase = lane >> 3;
    const int g_c  = tid & 7;
    const int g_r0 = tid >> 3;

    float c[4][4][4];
    #pragma unroll
    for (int mt = 0; mt < 4; mt++)
        #pragma unroll
        for (int nt = 0; nt < 4; nt++)
            #pragma unroll
            for (int q = 0; q < 4; q++) c[mt][nt][q] = 0.f;

    auto load_tile = [&](int kt) {
        if (kt < 16) {
            const uint32_t sA = sbase + (uint32_t)(kt % 3) * GSTAGE;
            const uint32_t sB = sA + 16384u;
            const int kk = kt << 6;
            #pragma unroll
            for (int i = 0; i < 4; i++) {
                int row = g_r0 + i * 32;
                uint32_t off = (uint32_t)(row * 128 + ((g_c ^ (row & 7)) << 4));
                cp16(sA + off, A + (size_t)(bm + row) * 1024 + kk + g_c * 8);
                cp16(sB + off, W + (size_t)(bn + row) * 1024 + kk + g_c * 8);
            }
        }
        CP_COMMIT();
    };

    load_tile(0);
    load_tile(1);

    for (int kt = 0; kt < 16; kt++) {
        CP_WAIT1();
        __syncthreads();
        load_tile(kt + 2);
        const uint32_t aB = sbase + (uint32_t)(kt % 3) * GSTAGE;
        const uint32_t bB = aB + 16384u;
        #pragma unroll
        for (int ks = 0; ks < 4; ks++) {
            const int c0 = ks * 2;
            uint32_t a[4][4];
            #pragma unroll
            for (int mt = 0; mt < 4; mt++) {
                int row = m0 + mt * 16 + (phase & 1) * 8 + lrow;
                int ch  = c0 + (phase >> 1);
                ldm_x4(a[mt], aB + (uint32_t)(row * 128 + ((ch ^ (row & 7)) << 4)));
            }
            uint32_t bf[2][4];
            #pragma unroll
            for (int ng = 0; ng < 2; ng++) {
                int row = n0 + ng * 16 + (phase >> 1) * 8 + lrow;
                int ch  = c0 + (phase & 1);
                ldm_x4(bf[ng], bB + (uint32_t)(row * 128 + ((ch ^ (row & 7)) << 4)));
            }
            #pragma unroll
            for (int nt = 0; nt < 4; nt++) {
                uint32_t b0 = bf[nt >> 1][(nt & 1) * 2];
                uint32_t b1 = bf[nt >> 1][(nt & 1) * 2 + 1];
                #pragma unroll
                for (int mt = 0; mt < 4; mt++)
                    MMAF16(c[mt][nt], a[mt], b0, b1);
            }
        }
        __syncthreads();
    }

    #pragma unroll
    for (int mt = 0; mt < 4; mt++) {
        #pragma unroll
        for (int nt = 0; nt < 4; nt++) {
            int r0  = bm + m0 + mt * 16 + qrow;
            int col = bn + n0 + nt * 8 + qk;
            float2 bv = *(const float2*)(bias + col);
            float2 o0, o1;
            o0.x = c[mt][nt][0] + bv.x; o0.y = c[mt][nt][1] + bv.y;
            o1.x = c[mt][nt][2] + bv.x; o1.y = c[mt][nt][3] + bv.y;
            *(float2*)(C + (size_t)r0 * 1024 + col) = o0;
            *(float2*)(C + (size_t)(r0 + 8) * 1024 + col) = o1;
        }
    }
}

// Merged Q+K GEMM: z=0 -> Q (fp16 out), z=1 -> K (ssq via atomicAdd).
__global__ __launch_bounds__(256, 2) void gemm_qk(
    const __half* __restrict__ A0, const __half* __restrict__ W0,
    const float* __restrict__ b0, __half* __restrict__ C0,
    const __half* __restrict__ A1, const __half* __restrict__ W1,
    const float* __restrict__ b1, float* __restrict__ C1)
{
    extern __shared__ __align__(128) char dsm[];
    const uint32_t sbase = smem_u32(dsm);
    const int z = blockIdx.z;
    const __half* A = z ? A1 : A0;
    const __half* W = z ? W1 : W0;
    const float* bias = z ? b1 : b0;

    const int tid  = threadIdx.x;
    const int lane = tid & 31;
    const int wid  = tid >> 5;
    const int bm = blockIdx.y * 128;
    const int bn = blockIdx.x * 128;
    const int m0 = (wid & 1) * 64;
    const int n0 = (wid >> 1) * 32;
    const int qrow = lane >> 2;
    const int qk   = (lane & 3) * 2;
    const int lrow  = lane & 7;
    const int phase = lane >> 3;
    const int g_c  = tid & 7;
    const int g_r0 = tid >> 3;

    float c[4][4][4];
    #pragma unroll
    for (int mt = 0; mt < 4; mt++)
        #pragma unroll
        for (int nt = 0; nt < 4; nt++)
            #pragma unroll
            for (int q = 0; q < 4; q++) c[mt][nt][q] = 0.f;

    auto load_tile = [&](int kt) {
        if (kt < 16) {
            const uint32_t sA = sbase + (uint32_t)(kt % 3) * GSTAGE;
            const uint32_t sB = sA + 16384u;
            const int kk = kt << 6;
            #pragma unroll
            for (int i = 0; i < 4; i++) {
                int row = g_r0 + i * 32;
                uint32_t off = (uint32_t)(row * 128 + ((g_c ^ (row & 7)) << 4));
                cp16(sA + off, A + (size_t)(bm + row) * 1024 + kk + g_c * 8);
                cp16(sB + off, W + (size_t)(bn + row) * 1024 + kk + g_c * 8);
            }
        }
        CP_COMMIT();
    };

    load_tile(0);
    load_tile(1);

    for (int kt = 0; kt < 16; kt++) {
        CP_WAIT1();
        __syncthreads();
        load_tile(kt + 2);
        const uint32_t aB = sbase + (uint32_t)(kt % 3) * GSTAGE;
        const uint32_t bB = aB + 16384u;
        #pragma unroll
        for (int ks = 0; ks < 4; ks++) {
            const int c0 = ks * 2;
            uint32_t a[4][4];
            #pragma unroll
            for (int mt = 0; mt < 4; mt++) {
                int row = m0 + mt * 16 + (phase & 1) * 8 + lrow;
                int ch  = c0 + (phase >> 1);
                ldm_x4(a[mt], aB + (uint32_t)(row * 128 + ((ch ^ (row & 7)) << 4)));
            }
            uint32_t bf[2][4];
            #pragma unroll
            for (int ng = 0; ng < 2; ng++) {
                int row = n0 + ng * 16 + (phase >> 1) * 8 + lrow;
                int ch  = c0 + (phase & 1);
                ldm_x4(bf[ng], bB + (uint32_t)(row * 128 + ((ch ^ (row & 7)) << 4)));
            }
            #pragma unroll
            for (int nt = 0; nt < 4; nt++) {
                uint32_t p0 = bf[nt >> 1][(nt & 1) * 2];
                uint32_t p1 = bf[nt >> 1][(nt & 1) * 2 + 1];
                #pragma unroll
                for (int mt = 0; mt < 4; mt++)
                    MMAF16(c[mt][nt], a[mt], p0, p1);
            }
        }
        __syncthreads();
    }

    if (z == 0) {
        __half* C = C0;
        #pragma unroll
        for (int mt = 0; mt < 4; mt++) {
            #pragma unroll
            for (int nt = 0; nt < 4; nt++) {
                int r0  = bm + m0 + mt * 16 + qrow;
                int col = bn + n0 + nt * 8 + qk;
                float2 bv = *(const float2*)(bias + col);
                __half2 h0 = __floats2half2_rn(c[mt][nt][0] + bv.x, c[mt][nt][1] + bv.y);
                __half2 h1 = __floats2half2_rn(c[mt][nt][2] + bv.x, c[mt][nt][3] + bv.y);
                *(__half2*)(C + (size_t)r0 * 1024 + col) = h0;
                *(__half2*)(C + (size_t)(r0 + 8) * 1024 + col) = h1;
            }
        }
    } else {
        float* C = C1;
        const int head = (bn + n0) >> 6;   // warp covers half a head -> atomicAdd
        #pragma unroll
        for (int mt = 0; mt < 4; mt++) {
            float s0 = 0.f, s1 = 0.f;
            #pragma unroll
            for (int nt = 0; nt < 4; nt++) {
                int col = bn + n0 + nt * 8 + qk;
                float2 bv = *(const float2*)(bias + col);
                float v0 = c[mt][nt][0] + bv.x, v1 = c[mt][nt][1] + bv.y;
                float v2 = c[mt][nt][2] + bv.x, v3 = c[mt][nt][3] + bv.y;
                s0 += v0 * v0 + v1 * v1;
                s1 += v2 * v2 + v3 * v3;
            }
            s0 += __shfl_xor_sync(0xffffffffu, s0, 1);
            s0 += __shfl_xor_sync(0xffffffffu, s0, 2);
            s1 += __shfl_xor_sync(0xffffffffu, s1, 1);
            s1 += __shfl_xor_sync(0xffffffffu, s1, 2);
            if ((lane & 3) == 0) {
                int r = bm + m0 + mt * 16 + qrow;
                atomicAdd(&C[(size_t)r * HH + head], s0);
                atomicAdd(&C[(size_t)(r + 8) * HH + head], s1);
            }
        }
    }
}

// ===================== scores from ssq ======================================
__global__ __launch_bounds__(256) void scores_ssq(
    const float* __restrict__ ssq, float* __restrict__ scores)
{
    int row = blockIdx.x * 256 + threadIdx.x;
    const float* sp = ssq + (size_t)row * HH;
    float acc = 0.f;
    #pragma unroll
    for (int h = 0; h < HH; h++) acc += sqrtf(sp[h]);
    scores[row] = acc * (1.f / 16.f);
}

// ===================== scores of fp32 rows (candidate rescoring) ============
__global__ __launch_bounds__(256) void scores_kernel(
    const float* __restrict__ Km, float* __restrict__ scores)
{
    int row  = blockIdx.x * 8 + (threadIdx.x >> 5);
    int lane = threadIdx.x & 31;
    const float* kr = Km + (size_t)row * EE;
    float acc = 0.f;
    #pragma unroll
    for (int h = 0; h < HH; h++) {
        float x0 = kr[h * 64 + lane];
        float x1 = kr[h * 64 + 32 + lane];
        float ss = x0 * x0 + x1 * x1;
        #pragma unroll
        for (int o = 16; o > 0; o >>= 1)
            ss += __shfl_xor_sync(0xffffffffu, ss, o);
        acc += sqrtf(ss);
    }
    if (lane == 0) scores[row] = acc * (1.f / 16.f);
}

// ===================== radix-select top-96 superset (<=128) =================
__global__ __launch_bounds__(256) void topk_radix(
    const float* __restrict__ scores, int* __restrict__ idxout,
    int* __restrict__ ncand)
{
    __shared__ int hist[256];
    __shared__ unsigned s_prefix;
    __shared__ int s_remaining;
    __shared__ int s_cnt;
    const int b = blockIdx.x, t = threadIdx.x;
    const float* sp = scores + b * SS;

    if (t == 0) { s_prefix = 0; s_remaining = NCAND; s_cnt = 0; }
    __syncthreads();

    for (int round = 0; round < 4; round++) {
        const int shift = 24 - 8 * round;
        hist[t] = 0;
        __syncthreads();
        const unsigned pfx = s_prefix;
        for (int i = t; i < SS; i += 256) {
            unsigned key = __float_as_uint(sp[i]);
            bool match = (round == 0) || (((key ^ pfx) >> (shift + 8)) == 0);
            if (match) atomicAdd(&hist[(key >> shift) & 255], 1);
        }
        __syncthreads();
        if (t == 0) {
            int rem = s_remaining, cum = 0, bin = 255;
            for (; bin > 0; bin--) {
                cum += hist[bin];
                if (cum >= rem) break;
            }
            if (cum < rem) cum += hist[0];
            s_remaining = rem - (cum - hist[bin]);
            s_prefix = pfx | ((unsigned)bin << shift);
        }
        __syncthreads();
    }
    const unsigned thresh = s_prefix;
    for (int i = t; i < SS; i += 256) {
        unsigned key = __float_as_uint(sp[i]);
        if (key >= thresh) {
            int pos = atomicAdd(&s_cnt, 1);
            if (pos < NCMAX) idxout[b * NCMAX + pos] = i;
        }
    }
    __syncthreads();
    int c = s_cnt < NCMAX ? s_cnt : NCMAX;
    if (t == 0) ncand[b] = c;
    for (int i = c + t; i < NCMAX; i += 256) idxout[b * NCMAX + i] = 0;
}

// ===================== exact fp32 projection (512 thr, K/V via z) ===========
__global__ __launch_bounds__(512) void project_rows2(
    const float* __restrict__ X0, const float* __restrict__ W0,
    const float* __restrict__ b0, float* __restrict__ o0,
    const float* __restrict__ X1, const float* __restrict__ W1,
    const float* __restrict__ b1, float* __restrict__ o1,
    const int* __restrict__ idx)
{
    __shared__ float xs[NCMAX * 32];
    __shared__ float ws[32 * 64];
    const int b = blockIdx.y;
    const int e0 = blockIdx.x * 64;
    const float* X  = blockIdx.z ? X1 : X0;
    const float* Wt = blockIdx.z ? W1 : W0;
    const float* bias = blockIdx.z ? b1 : b0;
    float* outp = blockIdx.z ? o1 : o0;
    const int t = threadIdx.x, tx = t & 15, ty = t >> 4;

    float acc[4][4];
    #pragma unroll
    for (int c = 0; c < 4; c++)
        #pragma unroll
        for (int j = 0; j < 4; j++) acc[c][j] = 0.f;

    for (int kt = 0; kt < EE; kt += 32) {
        __syncthreads();
        for (int u = t; u < NCMAX * 8; u += 512) {
            int cand = u >> 3, c4 = u & 7;
            int s = idx[b * NCMAX + cand];
            float4 v = *(const float4*)(X + ((size_t)(b * SS + s)) * EE + kt + c4 * 4);
            *(float4*)(xs + cand * 32 + c4 * 4) = v;
        }
        {
            int e = t >> 3, c4 = t & 7;
            float4 v = *(const float4*)(Wt + (size_t)(e0 + e) * EE + kt + c4 * 4);
            ws[(c4 * 4 + 0) * 64 + e] = v.x;
            ws[(c4 * 4 + 1) * 64 + e] = v.y;
            ws[(c4 * 4 + 2) * 64 + e] = v.z;
            ws[(c4 * 4 + 3) * 64 + e] = v.w;
        }
        __syncthreads();
        #pragma unroll 8
        for (int k = 0; k < 32; k++) {
            float wv[4];
            #pragma unroll
            for (int j = 0; j < 4; j++) wv[j] = ws[k * 64 + tx * 4 + j];
            #pragma unroll
            for (int c = 0; c < 4; c++) {
                float a = xs[(ty * 4 + c) * 32 + k];
                #pragma unroll
                for (int j = 0; j < 4; j++) acc[c][j] = fmaf(a, wv[j], acc[c][j]);
            }
        }
    }
    #pragma unroll
    for (int c = 0; c < 4; c++) {
        int cand = ty * 4 + c;
        #pragma unroll
        for (int j = 0; j < 4; j++) {
            int e = e0 + tx * 4 + j;
            outp[((size_t)b * NCMAX + cand) * EE + e] = acc[c][j] + bias[e];
        }
    }
}

// ===================== exact top-64 among candidates ========================
__global__ __launch_bounds__(128) void topk_refine_kernel(
    const float* __restrict__ scex, const int* __restrict__ idxc,
    const int* __restrict__ ncand,
    int* __restrict__ idxfin, int* __restrict__ candfin)
{
    __shared__ float sv[NCMAX];
    __shared__ int   si[NCMAX];
    __shared__ float rv[128];
    __shared__ int   rc[128];
    __shared__ int   rs[128];
    const int b = blockIdx.x, t = threadIdx.x;
    const int cnt = ncand[b];
    sv[t] = (t < cnt) ? scex[b * NCMAX + t] : -INFINITY;
    si[t] = (t < cnt) ? idxc[b * NCMAX + t] : 0x7fffffff;
    __syncthreads();
    for (int l = 0; l < LL; l++) {
        rv[t] = sv[t]; rc[t] = t; rs[t] = si[t];
        __syncthreads();
        for (int s = 64; s > 0; s >>= 1) {
            if (t < s) {
                if (rv[t + s] > rv[t] || (rv[t + s] == rv[t] && rs[t + s] < rs[t])) {
                    rv[t] = rv[t + s]; rc[t] = rc[t + s]; rs[t] = rs[t + s];
                }
            }
            __syncthreads();
        }
        if (t == 0) {
            idxfin[b * LL + l] = rs[0];
            candfin[b * LL + l] = rc[0];
            sv[rc[0]] = -INFINITY;
        }
        __syncthreads();
    }
}

// ===================== gather -> fp16 K [b,h,l,d] + V^T [b,h,d,l] ===========
__global__ __launch_bounds__(256) void gatherperm_f16(
    const float* __restrict__ kex, const float* __restrict__ vex,
    const int* __restrict__ candf,
    __half* __restrict__ Kh, __half* __restrict__ Vth)
{
    int i = blockIdx.x * 256 + threadIdx.x;
    int d = i & 63;
    int l = (i >> 6) & 63;
    int h = (i >> 12) & 15;
    int b = i >> 16;
    int cp = candf[b * LL + l];
    size_t src = ((size_t)b * NCMAX + cp) * EE + h * 64 + d;
    Kh[i] = __float2half(kex[src]);
    Vth[(((size_t)(b * HH + h)) << 12) + d * 64 + l] = __float2half(vex[src]);
}

// ===================== tensor-core attention (256 rows / 256 thr) ===========
#define ATTN_SMEM (49152 + 69632)

__global__ __launch_bounds__(256) void attn_mma(
    const __half* __restrict__ Qh, const __half* __restrict__ Kh,
    const __half* __restrict__ Vth, float* __restrict__ w_out,
    __half* __restrict__ ctxh)
{
    extern __shared__ __align__(128) char asmem[];
    const uint32_t sb = smem_u32(asmem);
    const uint32_t sQ = sb;
    const uint32_t sK = sb + 32768u;
    const uint32_t sV = sb + 40960u;
    float*  wsm = (float*)(asmem + 49152);
    __half* csm = (__half*)(asmem + 49152);

    const int b = blockIdx.z, h = blockIdx.y, chunk = blockIdx.x;
    const int t = threadIdx.x;
    const int lane = t & 31, wid = t >> 5;
    const int m0 = wid * 32;
    const int qrow = lane >> 2, qk = (lane & 3) * 2;
    const int lrow = lane & 7, phase = lane >> 3;

    const __half* Qg = Qh + ((size_t)(b * SS + chunk * 256)) * EE + h * 64;
    #pragma unroll
    for (int i = 0; i < 8; i++) {
        int idx = t + i * 256;
        int row = idx >> 3, ch = idx & 7;
        uint32_t off = (uint32_t)(row * 128 + ((ch ^ (row & 7)) << 4));
        cp16(sQ + off, Qg + (size_t)row * EE + ch * 8);
    }
    const __half* Kg = Kh + ((size_t)(b * HH + h) << 12);
    const __half* Vg = Vth + ((size_t)(b * HH + h) << 12);
    #pragma unroll
    for (int i = 0; i < 2; i++) {
        int idx = t + i * 256;
        int row = idx >> 3, ch = idx & 7;
        uint32_t off = (uint32_t)(row * 128 + ((ch ^ (row & 7)) << 4));
        cp16(sK + off, Kg + row * 64 + ch * 8);
        cp16(sV + off, Vg + row * 64 + ch * 8);
    }
    CP_COMMIT();
    CP_WAIT0();
    __syncthreads();

    float c[2][8][4];
    #pragma unroll
    for (int mt = 0; mt < 2; mt++)
        #pragma unroll
        for (int nt = 0; nt < 8; nt++)
            #pragma unroll
            for (int q = 0; q < 4; q++) c[mt][nt][q] = 0.f;

    #pragma unroll
    for (int ks = 0; ks < 4; ks++) {
        uint32_t a[2][4];
        #pragma unroll
        for (int mt = 0; mt < 2; mt++) {
            int row = m0 + mt * 16 + (phase & 1) * 8 + lrow;
            int ch  = ks * 2 + (phase >> 1);
            ldm_x4(a[mt], sQ + (uint32_t)(row * 128 + ((ch ^ (row & 7)) << 4)));
        }
        uint32_t bf[4][4];
        #pragma unroll
        for (int ng = 0; ng < 4; ng++) {
            int row = ng * 16 + (phase >> 1) * 8 + lrow;
            int ch  = ks * 2 + (phase & 1);
            ldm_x4(bf[ng], sK + (uint32_t)(row * 128 + ((ch ^ (row & 7)) << 4)));
        }
        #pragma unroll
        for (int nt = 0; nt < 8; nt++) {
            uint32_t b0 = bf[nt >> 1][(nt & 1) * 2];
            uint32_t b1 = bf[nt >> 1][(nt & 1) * 2 + 1];
            MMAF16(c[0][nt], a[0], b0, b1);
            MMAF16(c[1][nt], a[1], b0, b1);
        }
    }

    float inv[2][2];
    #pragma unroll
    for (int mt = 0; mt < 2; mt++) {
        float mx0 = -INFINITY, mx1 = -INFINITY;
        #pragma unroll
        for (int nt = 0; nt < 8; nt++) {
            #pragma unroll
            for (int q = 0; q < 4; q++) c[mt][nt][q] *= 0.125f;
            mx0 = fmaxf(mx0, fmaxf(c[mt][nt][0], c[mt][nt][1]));
            mx1 = fmaxf(mx1, fmaxf(c[mt][nt][2], c[mt][nt][3]));
        }
        mx0 = fmaxf(mx0, __shfl_xor_sync(0xffffffffu, mx0, 1));
        mx0 = fmaxf(mx0, __shfl_xor_sync(0xffffffffu, mx0, 2));
        mx1 = fmaxf(mx1, __shfl_xor_sync(0xffffffffu, mx1, 1));
        mx1 = fmaxf(mx1, __shfl_xor_sync(0xffffffffu, mx1, 2));
        float s0 = 0.f, s1 = 0.f;
        #pragma unroll
        for (int nt = 0; nt < 8; nt++) {
            c[mt][nt][0] = expf(c[mt][nt][0] - mx0);
            c[mt][nt][1] = expf(c[mt][nt][1] - mx0);
            c[mt][nt][2] = expf(c[mt][nt][2] - mx1);
            c[mt][nt][3] = expf(c[mt][nt][3] - mx1);
            s0 += c[mt][nt][0] + c[mt][nt][1];
            s1 += c[mt][nt][2] + c[mt][nt][3];
        }
        s0 += __shfl_xor_sync(0xffffffffu, s0, 1);
        s0 += __shfl_xor_sync(0xffffffffu, s0, 2);
        s1 += __shfl_xor_sync(0xffffffffu, s1, 1);
        s1 += __shfl_xor_sync(0xffffffffu, s1, 2);
        inv[mt][0] = 1.f / s0;
        inv[mt][1] = 1.f / s1;
    }

    uint32_t wh[2][4][4];
    #pragma unroll
    for (int mt = 0; mt < 2; mt++) {
        int r0 = m0 + mt * 16 + qrow;
        #pragma unroll
        for (int nt = 0; nt < 8; nt++) {
            float w0 = c[mt][nt][0] * inv[mt][0];
            float w1 = c[mt][nt][1] * inv[mt][0];
            float w2 = c[mt][nt][2] * inv[mt][1];
            float w3 = c[mt][nt][3] * inv[mt][1];
            int col = nt * 8 + qk;
            wsm[r0 * 68 + col] = w0;       wsm[r0 * 68 + col + 1] = w1;
            wsm[(r0 + 8) * 68 + col] = w2; wsm[(r0 + 8) * 68 + col + 1] = w3;
            int j = nt >> 1;
            if ((nt & 1) == 0) {
                wh[mt][j][0] = packh2(w0, w1);
                wh[mt][j][1] = packh2(w2, w3);
            } else {
                wh[mt][j][2] = packh2(w0, w1);
                wh[mt][j][3] = packh2(w2, w3);
            }
        }
    }

    float o[2][8][4];
    #pragma unroll
    for (int mt = 0; mt < 2; mt++)
        #pragma unroll
        for (int nt = 0; nt < 8; nt++)
            #pragma unroll
            for (int q = 0; q < 4; q++) o[mt][nt][q] = 0.f;

    #pragma unroll
    for (int j = 0; j < 4; j++) {
        uint32_t bf[4][4];
        #pragma unroll
        for (int ng = 0; ng < 4; ng++) {
            int row = ng * 16 + (phase >> 1) * 8 + lrow;
            int ch  = j * 2 + (phase & 1);
            ldm_x4(bf[ng], sV + (uint32_t)(row * 128 + ((ch ^ (row & 7)) << 4)));
        }
        #pragma unroll
        for (int nt = 0; nt < 8; nt++) {
            uint32_t b0 = bf[nt >> 1][(nt & 1) * 2];
            uint32_t b1 = bf[nt >> 1][(nt & 1) * 2 + 1];
            MMAF16(o[0][nt], wh[0][j], b0, b1);
            MMAF16(o[1][nt], wh[1][j], b0, b1);
        }
    }

    __syncthreads();
    float* wb = w_out + ((size_t)((b * HH + h) * SS + chunk * 256)) * LL;
    #pragma unroll
    for (int i = 0; i < 16; i++) {
        int idx = t + i * 256;
        int row = idx >> 4, c4 = idx & 15;
        *(float4*)(wb + row * 64 + c4 * 4) = *(const float4*)(wsm + row * 68 + c4 * 4);
    }
    __syncthreads();

    #pragma unroll
    for (int mt = 0; mt < 2; mt++) {
        int r0 = m0 + mt * 16 + qrow;
        #pragma unroll
        for (int nt = 0; nt < 8; nt++) {
            int col = nt * 8 + qk;
            *(__half2*)(csm + r0 * 72 + col)       = __floats2half2_rn(o[mt][nt][0], o[mt][nt][1]);
            *(__half2*)(csm + (r0 + 8) * 72 + col) = __floats2half2_rn(o[mt][nt][2], o[mt][nt][3]);
        }
    }
    __syncthreads();
    __half* cb = ctxh + ((size_t)(b * SS + chunk * 256)) * EE + h * 64;
    #pragma unroll
    for (int i = 0; i < 8; i++) {
        int idx = t + i * 256;
        int row = idx >> 3, seg = idx & 7;
        *(uint4*)(cb + (size_t)row * EE + seg * 8) = *(const uint4*)(csm + row * 72 + seg * 8);
    }
}

// ===================== launch ===============================================
extern "C" void kernel_launch(void* const* d_in, const int* in_sizes, int n_in,
                              void* d_out, int out_size)
{
    const float* query = (const float*)d_in[0];
    const float* key   = (const float*)d_in[1];
    const float* value = (const float*)d_in[2];
    const float* Wq = (const float*)d_in[3];
    const float* bq = (const float*)d_in[4];
    const float* Wk = (const float*)d_in[5];
    const float* bk = (const float*)d_in[6];
    const float* Wv = (const float*)d_in[7];
    const float* bv = (const float*)d_in[8];
    const float* Wo = (const float*)d_in[9];
    const float* bo = (const float*)d_in[10];

    float* out  = (float*)d_out;
    float* wout = out + MSZ;

    float *pSsq, *pScores, *pKex, *pVex, *pScex;
    __half *pQh, *pAqh, *pAkh, *pWqh, *pWkh, *pWoh, *pKsph, *pVspt;
    int *pIdxc, *pNcand, *pIdxf, *pCandf;
    cudaGetSymbolAddress((void**)&pQh, g_Qh);
    cudaGetSymbolAddress((void**)&pAqh, g_Aqh);
    cudaGetSymbolAddress((void**)&pAkh, g_Akh);
    cudaGetSymbolAddress((void**)&pWqh, g_Wqh);
    cudaGetSymbolAddress((void**)&pWkh, g_Wkh);
    cudaGetSymbolAddress((void**)&pWoh, g_Woh);
    cudaGetSymbolAddress((void**)&pSsq, g_ssq);
    cudaGetSymbolAddress((void**)&pScores, g_scores);
    cudaGetSymbolAddress((void**)&pIdxc, g_idxc);
    cudaGetSymbolAddress((void**)&pNcand, g_ncand);
    cudaGetSymbolAddress((void**)&pKex, g_kex);
    cudaGetSymbolAddress((void**)&pVex, g_vex);
    cudaGetSymbolAddress((void**)&pScex, g_scex);
    cudaGetSymbolAddress((void**)&pIdxf, g_idxf);
    cudaGetSymbolAddress((void**)&pCandf, g_candf);
    cudaGetSymbolAddress((void**)&pKsph, g_Ksph);
    cudaGetSymbolAddress((void**)&pVspt, g_Vspt);

    cudaFuncSetAttribute((void*)gemm_f16, cudaFuncAttributeMaxDynamicSharedMemorySize, GEMM_SMEM);
    cudaFuncSetAttribute((void*)gemm_qk, cudaFuncAttributeMaxDynamicSharedMemorySize, GEMM_SMEM);
    cudaFuncSetAttribute((void*)attn_mma, cudaFuncAttributeMaxDynamicSharedMemorySize, ATTN_SMEM);

    const int n4m = (int)(MSZ / 4);
    const int n4w = EE * EE / 4;

    dim3 cw(n4w / 256, 3);
    conv3_f16<<<cw, 256>>>(Wq, pWqh, Wk, pWkh, Wo, pWoh, n4w);
    dim3 ca(n4m / 256, 2);
    conv2_f16<<<ca, 256>>>(query, pAqh, key, pAkh, n4m);
    zero_ssq<<<(MROWS * HH / 4) / 256, 256>>>(pSsq, MROWS * HH / 4);

    // Q GEMM (fp16 out) + K GEMM (ssq atomics), merged; BN=128 -> 8 col blocks
    dim3 qkgrid(8, 256, 2);
    gemm_qk<<<qkgrid, 256, GEMM_SMEM>>>(pAqh, pWqh, bq, pQh,
                                        pAkh, pWkh, bk, pSsq);

    scores_ssq<<<MROWS / 256, 256>>>(pSsq, pScores);
    topk_radix<<<BB, 256>>>(pScores, pIdxc, pNcand);

    dim3 pgrid(16, BB, 2);
    project_rows2<<<pgrid, 512>>>(key, Wk, bk, pKex, value, Wv, bv, pVex, pIdxc);
    scores_kernel<<<(BB * NCMAX) / 8, 256>>>(pKex, pScex);
    topk_refine_kernel<<<BB, 128>>>(pScex, pIdxc, pNcand, pIdxf, pCandf);
    gatherperm_f16<<<(BB * HH * LL * DD) / 256, 256>>>(pKex, pVex, pCandf, pKsph, pVspt);

    dim3 agrid(SS / 256, HH, BB);
    attn_mma<<<agrid, 256, ATTN_SMEM>>>(pQh, pKsph, pVspt, wout, pAqh);

    dim3 ggrid(8, 256);
    gemm_f16<<<ggrid, 256, GEMM_SMEM>>>(pAqh, pWoh, bo, out);
}

// round 17
// speedup vs baseline: 4.3413x; 1.0057x over previous
#include <cuda_runtime.h>
#include <cuda_fp16.h>
#include <math.h>
#include <stdint.h>

#define BB 4
#define SS 8192
#define EE 1024
#define HH 16
#define DD 64
#define LL 64
#define NCAND 96
#define NCMAX 128
#define MROWS (BB * SS)
#define MSZ   ((size_t)MROWS * EE)

// ===================== scratch ==============================================
__device__ __half g_Qh[MSZ];
__device__ __half g_Aqh[MSZ];         // query fp16 in; reused as fp16 ctx
__device__ __half g_Akh[MSZ];
__device__ __half g_Wqh[EE * EE];
__device__ __half g_Wkh[EE * EE];
__device__ __half g_Woh[EE * EE];
__device__ __half g_Wvh[EE * EE];
__device__ __half g_Vg16[BB * NCMAX * EE];    // gathered candidate value rows, fp16
__device__ float g_ssq[MROWS * HH];
__device__ float g_scores[BB * SS];
__device__ int   g_idxc[BB * NCMAX];
__device__ int   g_ncand[BB];
__device__ float g_kex[BB * NCMAX * EE];
__device__ float g_vex[BB * NCMAX * EE];
__device__ float g_scex[BB * NCMAX];
__device__ int   g_idxf[BB * LL];
__device__ int   g_candf[BB * LL];
__device__ __half g_Ksph[BB * HH * LL * DD];   // [b,h,l,d]
__device__ __half g_Vspt[BB * HH * DD * LL];   // [b,h,d,l]

// ===================== small PTX helpers ====================================
__device__ __forceinline__ uint32_t smem_u32(const void* p) {
    uint32_t a;
    asm("{ .reg .u64 t; cvta.to.shared.u64 t, %1; cvt.u32.u64 %0, t; }" : "=r"(a) : "l"(p));
    return a;
}
__device__ __forceinline__ void cp16(uint32_t dst, const void* src) {
    asm volatile("cp.async.cg.shared.global [%0], [%1], 16;" :: "r"(dst), "l"(src));
}
#define CP_COMMIT() asm volatile("cp.async.commit_group;" ::: "memory")
#define CP_WAIT1()  asm volatile("cp.async.wait_group 1;" ::: "memory")
#define CP_WAIT0()  asm volatile("cp.async.wait_group 0;" ::: "memory")
__device__ __forceinline__ void ldm_x4(uint32_t* r, uint32_t addr) {
    asm volatile("ldmatrix.sync.aligned.m8n8.x4.shared.b16 {%0,%1,%2,%3}, [%4];"
                 : "=r"(r[0]), "=r"(r[1]), "=r"(r[2]), "=r"(r[3]) : "r"(addr));
}
#define MMAF16(d, a, b0, b1) \
    asm volatile("mma.sync.aligned.m16n8k16.row.col.f32.f16.f16.f32 " \
        "{%0,%1,%2,%3}, {%4,%5,%6,%7}, {%8,%9}, {%0,%1,%2,%3};" \
        : "+f"((d)[0]), "+f"((d)[1]), "+f"((d)[2]), "+f"((d)[3]) \
        : "r"((a)[0]), "r"((a)[1]), "r"((a)[2]), "r"((a)[3]), \
          "r"(b0), "r"(b1))
__device__ __forceinline__ uint32_t packh2(float a, float b) {
    __half2 h = __floats2half2_rn(a, b);
    return *(uint32_t*)&h;
}

// ===================== fp32 -> fp16 conversions ==============================
__global__ __launch_bounds__(256) void conv2_f16(
    const float* __restrict__ x0, __half* __restrict__ h0,
    const float* __restrict__ x1, __half* __restrict__ h1, int n4)
{
    int i = blockIdx.x * 256 + threadIdx.x;
    if (i >= n4) return;
    const float* x = blockIdx.y ? x1 : x0;
    __half* h = blockIdx.y ? h1 : h0;
    float4 v = ((const float4*)x)[i];
    uint32_t a0 = (uint32_t)__half_as_ushort(__float2half(v.x));
    uint32_t a1 = (uint32_t)__half_as_ushort(__float2half(v.y));
    uint32_t a2 = (uint32_t)__half_as_ushort(__float2half(v.z));
    uint32_t a3 = (uint32_t)__half_as_ushort(__float2half(v.w));
    uint2 hp; hp.x = a0 | (a1 << 16); hp.y = a2 | (a3 << 16);
    ((uint2*)h)[i] = hp;
}

__global__ __launch_bounds__(256) void conv4_f16(
    const float* __restrict__ x0, __half* __restrict__ h0,
    const float* __restrict__ x1, __half* __restrict__ h1,
    const float* __restrict__ x2, __half* __restrict__ h2,
    const float* __restrict__ x3, __half* __restrict__ h3, int n4)
{
    int i = blockIdx.x * 256 + threadIdx.x;
    if (i >= n4) return;
    const float* x = blockIdx.y == 0 ? x0 : (blockIdx.y == 1 ? x1 :
                     (blockIdx.y == 2 ? x2 : x3));
    __half* h = blockIdx.y == 0 ? h0 : (blockIdx.y == 1 ? h1 :
                (blockIdx.y == 2 ? h2 : h3));
    float4 v = ((const float4*)x)[i];
    uint32_t a0 = (uint32_t)__half_as_ushort(__float2half(v.x));
    uint32_t a1 = (uint32_t)__half_as_ushort(__float2half(v.y));
    uint32_t a2 = (uint32_t)__half_as_ushort(__float2half(v.z));
    uint32_t a3 = (uint32_t)__half_as_ushort(__float2half(v.w));
    uint2 hp; hp.x = a0 | (a1 << 16); hp.y = a2 | (a3 << 16);
    ((uint2*)h)[i] = hp;
}

// ===================== zero ssq =============================================
__global__ __launch_bounds__(256) void zero_ssq(float* __restrict__ p, int n4)
{
    int i = blockIdx.x * 256 + threadIdx.x;
    if (i < n4) ((float4*)p)[i] = make_float4(0.f, 0.f, 0.f, 0.f);
}

// ===================== gather candidate value rows -> fp16 ==================
__global__ __launch_bounds__(256) void gatherv_f16(
    const float* __restrict__ value, const int* __restrict__ idxc,
    __half* __restrict__ Vg)
{
    int i = blockIdx.x * 256 + threadIdx.x;      // over 512*1024/4 = 131072
    int row = i >> 8;                             // 0..511 (256 float4 per row)
    int c4  = (i & 255) * 4;
    int b = row >> 7, cand = row & 127;
    int s = idxc[b * NCMAX + cand];
    float4 v = *(const float4*)(value + ((size_t)(b * SS + s)) * EE + c4);
    uint32_t a0 = (uint32_t)__half_as_ushort(__float2half(v.x));
    uint32_t a1 = (uint32_t)__half_as_ushort(__float2half(v.y));
    uint32_t a2 = (uint32_t)__half_as_ushort(__float2half(v.z));
    uint32_t a3 = (uint32_t)__half_as_ushort(__float2half(v.w));
    uint2 hp; hp.x = a0 | (a1 << 16); hp.y = a2 | (a3 << 16);
    *(uint2*)(Vg + (size_t)row * EE + c4) = hp;
}

// ===================== fp16 GEMM: BM=128, BN=128, 2 CTAs/SM =================
// 256 thr, warp grid 2(M) x 4(N), warp tile 64x32. 3-stage cp.async, 32KB/stage.
// Single barrier per stage (leading sync after CP_WAIT1 orders WAR + RAW).
#define GSTAGE 32768u
#define GEMM_SMEM (3 * 32768)

__global__ __launch_bounds__(256, 2) void gemm_f16(
    const __half* __restrict__ A, const __half* __restrict__ W,
    const float* __restrict__ bias, float* __restrict__ C)
{
    extern __shared__ __align__(128) char dsm[];
    const uint32_t sbase = smem_u32(dsm);
    const int tid  = threadIdx.x;
    const int lane = tid & 31;
    const int wid  = tid >> 5;
    const int bm = blockIdx.y * 128;
    const int bn = blockIdx.x * 128;
    const int m0 = (wid & 1) * 64;
    const int n0 = (wid >> 1) * 32;
    const int qrow = lane >> 2;
    const int qk   = (lane & 3) * 2;
    const int lrow  = lane & 7;
    const int phase = lane >> 3;
    const int g_c  = tid & 7;
    const int g_r0 = tid >> 3;

    float c[4][4][4];
    #pragma unroll
    for (int mt = 0; mt < 4; mt++)
        #pragma unroll
        for (int nt = 0; nt < 4; nt++)
            #pragma unroll
            for (int q = 0; q < 4; q++) c[mt][nt][q] = 0.f;

    auto load_tile = [&](int kt) {
        if (kt < 16) {
            const uint32_t sA = sbase + (uint32_t)(kt % 3) * GSTAGE;
            const uint32_t sB = sA + 16384u;
            const int kk = kt << 6;
            #pragma unroll
            for (int i = 0; i < 4; i++) {
                int row = g_r0 + i * 32;
                uint32_t off = (uint32_t)(row * 128 + ((g_c ^ (row & 7)) << 4));
                cp16(sA + off, A + (size_t)(bm + row) * 1024 + kk + g_c * 8);
                cp16(sB + off, W + (size_t)(bn + row) * 1024 + kk + g_c * 8);
            }
        }
        CP_COMMIT();
    };

    load_tile(0);
    load_tile(1);

    for (int kt = 0; kt < 16; kt++) {
        CP_WAIT1();
        __syncthreads();
        load_tile(kt + 2);
        const uint32_t aB = sbase + (uint32_t)(kt % 3) * GSTAGE;
        const uint32_t bB = aB + 16384u;
        #pragma unroll
        for (int ks = 0; ks < 4; ks++) {
            const int c0 = ks * 2;
            uint32_t a[4][4];
            #pragma unroll
            for (int mt = 0; mt < 4; mt++) {
                int row = m0 + mt * 16 + (phase & 1) * 8 + lrow;
                int ch  = c0 + (phase >> 1);
                ldm_x4(a[mt], aB + (uint32_t)(row * 128 + ((ch ^ (row & 7)) << 4)));
            }
            uint32_t bf[2][4];
            #pragma unroll
            for (int ng = 0; ng < 2; ng++) {
                int row = n0 + ng * 16 + (phase >> 1) * 8 + lrow;
                int ch  = c0 + (phase & 1);
                ldm_x4(bf[ng], bB + (uint32_t)(row * 128 + ((ch ^ (row & 7)) << 4)));
            }
            #pragma unroll
            for (int nt = 0; nt < 4; nt++) {
                uint32_t b0 = bf[nt >> 1][(nt & 1) * 2];
                uint32_t b1 = bf[nt >> 1][(nt & 1) * 2 + 1];
                #pragma unroll
                for (int mt = 0; mt < 4; mt++)
                    MMAF16(c[mt][nt], a[mt], b0, b1);
            }
        }
    }

    #pragma unroll
    for (int mt = 0; mt < 4; mt++) {
        #pragma unroll
        for (int nt = 0; nt < 4; nt++) {
            int r0  = bm + m0 + mt * 16 + qrow;
            int col = bn + n0 + nt * 8 + qk;
            float2 bv = *(const float2*)(bias + col);
            float2 o0, o1;
            o0.x = c[mt][nt][0] + bv.x; o0.y = c[mt][nt][1] + bv.y;
            o1.x = c[mt][nt][2] + bv.x; o1.y = c[mt][nt][3] + bv.y;
            *(float2*)(C + (size_t)r0 * 1024 + col) = o0;
            *(float2*)(C + (size_t)(r0 + 8) * 1024 + col) = o1;
        }
    }
}

// Merged Q+K GEMM: z=0 -> Q (fp16 out), z=1 -> K (ssq via atomicAdd).
__global__ __launch_bounds__(256, 2) void gemm_qk(
    const __half* __restrict__ A0, const __half* __restrict__ W0,
    const float* __restrict__ b0, __half* __restrict__ C0,
    const __half* __restrict__ A1, const __half* __restrict__ W1,
    const float* __restrict__ b1, float* __restrict__ C1)
{
    extern __shared__ __align__(128) char dsm[];
    const uint32_t sbase = smem_u32(dsm);
    const int z = blockIdx.z;
    const __half* A = z ? A1 : A0;
    const __half* W = z ? W1 : W0;
    const float* bias = z ? b1 : b0;

    const int tid  = threadIdx.x;
    const int lane = tid & 31;
    const int wid  = tid >> 5;
    const int bm = blockIdx.y * 128;
    const int bn = blockIdx.x * 128;
    const int m0 = (wid & 1) * 64;
    const int n0 = (wid >> 1) * 32;
    const int qrow = lane >> 2;
    const int qk   = (lane & 3) * 2;
    const int lrow  = lane & 7;
    const int phase = lane >> 3;
    const int g_c  = tid & 7;
    const int g_r0 = tid >> 3;

    float c[4][4][4];
    #pragma unroll
    for (int mt = 0; mt < 4; mt++)
        #pragma unroll
        for (int nt = 0; nt < 4; nt++)
            #pragma unroll
            for (int q = 0; q < 4; q++) c[mt][nt][q] = 0.f;

    auto load_tile = [&](int kt) {
        if (kt < 16) {
            const uint32_t sA = sbase + (uint32_t)(kt % 3) * GSTAGE;
            const uint32_t sB = sA + 16384u;
            const int kk = kt << 6;
            #pragma unroll
            for (int i = 0; i < 4; i++) {
                int row = g_r0 + i * 32;
                uint32_t off = (uint32_t)(row * 128 + ((g_c ^ (row & 7)) << 4));
                cp16(sA + off, A + (size_t)(bm + row) * 1024 + kk + g_c * 8);
                cp16(sB + off, W + (size_t)(bn + row) * 1024 + kk + g_c * 8);
            }
        }
        CP_COMMIT();
    };

    load_tile(0);
    load_tile(1);

    for (int kt = 0; kt < 16; kt++) {
        CP_WAIT1();
        __syncthreads();
        load_tile(kt + 2);
        const uint32_t aB = sbase + (uint32_t)(kt % 3) * GSTAGE;
        const uint32_t bB = aB + 16384u;
        #pragma unroll
        for (int ks = 0; ks < 4; ks++) {
            const int c0 = ks * 2;
            uint32_t a[4][4];
            #pragma unroll
            for (int mt = 0; mt < 4; mt++) {
                int row = m0 + mt * 16 + (phase & 1) * 8 + lrow;
                int ch  = c0 + (phase >> 1);
                ldm_x4(a[mt], aB + (uint32_t)(row * 128 + ((ch ^ (row & 7)) << 4)));
            }
            uint32_t bf[2][4];
            #pragma unroll
            for (int ng = 0; ng < 2; ng++) {
                int row = n0 + ng * 16 + (phase >> 1) * 8 + lrow;
                int ch  = c0 + (phase & 1);
                ldm_x4(bf[ng], bB + (uint32_t)(row * 128 + ((ch ^ (row & 7)) << 4)));
            }
            #pragma unroll
            for (int nt = 0; nt < 4; nt++) {
                uint32_t p0 = bf[nt >> 1][(nt & 1) * 2];
                uint32_t p1 = bf[nt >> 1][(nt & 1) * 2 + 1];
                #pragma unroll
                for (int mt = 0; mt < 4; mt++)
                    MMAF16(c[mt][nt], a[mt], p0, p1);
            }
        }
    }

    if (z == 0) {
        __half* C = C0;
        #pragma unroll
        for (int mt = 0; mt < 4; mt++) {
            #pragma unroll
            for (int nt = 0; nt < 4; nt++) {
                int r0  = bm + m0 + mt * 16 + qrow;
                int col = bn + n0 + nt * 8 + qk;
                float2 bv = *(const float2*)(bias + col);
                __half2 h0 = __floats2half2_rn(c[mt][nt][0] + bv.x, c[mt][nt][1] + bv.y);
                __half2 h1 = __floats2half2_rn(c[mt][nt][2] + bv.x, c[mt][nt][3] + bv.y);
                *(__half2*)(C + (size_t)r0 * 1024 + col) = h0;
                *(__half2*)(C + (size_t)(r0 + 8) * 1024 + col) = h1;
            }
        }
    } else {
        float* C = C1;
        const int head = (bn + n0) >> 6;
        #pragma unroll
        for (int mt = 0; mt < 4; mt++) {
            float s0 = 0.f, s1 = 0.f;
            #pragma unroll
            for (int nt = 0; nt < 4; nt++) {
                int col = bn + n0 + nt * 8 + qk;
                float2 bv = *(const float2*)(bias + col);
                float v0 = c[mt][nt][0] + bv.x, v1 = c[mt][nt][1] + bv.y;
                float v2 = c[mt][nt][2] + bv.x, v3 = c[mt][nt][3] + bv.y;
                s0 += v0 * v0 + v1 * v1;
                s1 += v2 * v2 + v3 * v3;
            }
            s0 += __shfl_xor_sync(0xffffffffu, s0, 1);
            s0 += __shfl_xor_sync(0xffffffffu, s0, 2);
            s1 += __shfl_xor_sync(0xffffffffu, s1, 1);
            s1 += __shfl_xor_sync(0xffffffffu, s1, 2);
            if ((lane & 3) == 0) {
                int r = bm + m0 + mt * 16 + qrow;
                atomicAdd(&C[(size_t)r * HH + head], s0);
                atomicAdd(&C[(size_t)(r + 8) * HH + head], s1);
            }
        }
    }
}

// ===================== scores from ssq ======================================
__global__ __launch_bounds__(256) void scores_ssq(
    const float* __restrict__ ssq, float* __restrict__ scores)
{
    int row = blockIdx.x * 256 + threadIdx.x;
    const float* sp = ssq + (size_t)row * HH;
    float acc = 0.f;
    #pragma unroll
    for (int h = 0; h < HH; h++) acc += sqrtf(sp[h]);
    scores[row] = acc * (1.f / 16.f);
}

// ===================== scores of fp32 rows (candidate rescoring) ============
__global__ __launch_bounds__(256) void scores_kernel(
    const float* __restrict__ Km, float* __restrict__ scores)
{
    int row  = blockIdx.x * 8 + (threadIdx.x >> 5);
    int lane = threadIdx.x & 31;
    const float* kr = Km + (size_t)row * EE;
    float acc = 0.f;
    #pragma unroll
    for (int h = 0; h < HH; h++) {
        float x0 = kr[h * 64 + lane];
        float x1 = kr[h * 64 + 32 + lane];
        float ss = x0 * x0 + x1 * x1;
        #pragma unroll
        for (int o = 16; o > 0; o >>= 1)
            ss += __shfl_xor_sync(0xffffffffu, ss, o);
        acc += sqrtf(ss);
    }
    if (lane == 0) scores[row] = acc * (1.f / 16.f);
}

// ===================== radix-select top-96 superset (<=128) =================
__global__ __launch_bounds__(256) void topk_radix(
    const float* __restrict__ scores, int* __restrict__ idxout,
    int* __restrict__ ncand)
{
    __shared__ int hist[256];
    __shared__ unsigned s_prefix;
    __shared__ int s_remaining;
    __shared__ int s_cnt;
    const int b = blockIdx.x, t = threadIdx.x;
    const float* sp = scores + b * SS;

    if (t == 0) { s_prefix = 0; s_remaining = NCAND; s_cnt = 0; }
    __syncthreads();

    for (int round = 0; round < 4; round++) {
        const int shift = 24 - 8 * round;
        hist[t] = 0;
        __syncthreads();
        const unsigned pfx = s_prefix;
        for (int i = t; i < SS; i += 256) {
            unsigned key = __float_as_uint(sp[i]);
            bool match = (round == 0) || (((key ^ pfx) >> (shift + 8)) == 0);
            if (match) atomicAdd(&hist[(key >> shift) & 255], 1);
        }
        __syncthreads();
        if (t == 0) {
            int rem = s_remaining, cum = 0, bin = 255;
            for (; bin > 0; bin--) {
                cum += hist[bin];
                if (cum >= rem) break;
            }
            if (cum < rem) cum += hist[0];
            s_remaining = rem - (cum - hist[bin]);
            s_prefix = pfx | ((unsigned)bin << shift);
        }
        __syncthreads();
    }
    const unsigned thresh = s_prefix;
    for (int i = t; i < SS; i += 256) {
        unsigned key = __float_as_uint(sp[i]);
        if (key >= thresh) {
            int pos = atomicAdd(&s_cnt, 1);
            if (pos < NCMAX) idxout[b * NCMAX + pos] = i;
        }
    }
    __syncthreads();
    int c = s_cnt < NCMAX ? s_cnt : NCMAX;
    if (t == 0) ncand[b] = c;
    for (int i = c + t; i < NCMAX; i += 256) idxout[b * NCMAX + i] = 0;
}

// ===================== exact fp32 K projection (512 thr, 32-col blocks) =====
__global__ __launch_bounds__(512) void project_k(
    const float* __restrict__ X, const float* __restrict__ Wt,
    const float* __restrict__ bias, float* __restrict__ outp,
    const int* __restrict__ idx)
{
    __shared__ float xs[NCMAX * 36];   // stride 36 (16B-aligned, bank-spread)
    __shared__ float ws[32 * 32];
    const int b = blockIdx.y;
    const int e0 = blockIdx.x * 32;
    const int t = threadIdx.x, tx = t & 7, ty = t >> 3;   // tx: 8 e-groups, ty: 0..63

    float acc[2][4];
    #pragma unroll
    for (int c = 0; c < 2; c++)
        #pragma unroll
        for (int j = 0; j < 4; j++) acc[c][j] = 0.f;

    for (int kt = 0; kt < EE; kt += 32) {
        __syncthreads();
        for (int u = t; u < NCMAX * 8; u += 512) {
            int cand = u >> 3, c4 = u & 7;
            int s = idx[b * NCMAX + cand];
            float4 v = *(const float4*)(X + ((size_t)(b * SS + s)) * EE + kt + c4 * 4);
            *(float4*)(xs + cand * 36 + c4 * 4) = v;
        }
        if (t < 256) {
            int e = t >> 3, c4 = t & 7;
            float4 v = *(const float4*)(Wt + (size_t)(e0 + e) * EE + kt + c4 * 4);
            ws[(c4 * 4 + 0) * 32 + e] = v.x;
            ws[(c4 * 4 + 1) * 32 + e] = v.y;
            ws[(c4 * 4 + 2) * 32 + e] = v.z;
            ws[(c4 * 4 + 3) * 32 + e] = v.w;
        }
        __syncthreads();
        #pragma unroll 8
        for (int k = 0; k < 32; k++) {
            float wv[4];
            #pragma unroll
            for (int j = 0; j < 4; j++) wv[j] = ws[k * 32 + tx * 4 + j];
            #pragma unroll
            for (int c = 0; c < 2; c++) {
                float a = xs[(ty * 2 + c) * 36 + k];
                #pragma unroll
                for (int j = 0; j < 4; j++) acc[c][j] = fmaf(a, wv[j], acc[c][j]);
            }
        }
    }
    #pragma unroll
    for (int c = 0; c < 2; c++) {
        int cand = ty * 2 + c;
        #pragma unroll
        for (int j = 0; j < 4; j++) {
            int e = e0 + tx * 4 + j;
            outp[((size_t)b * NCMAX + cand) * EE + e] = acc[c][j] + bias[e];
        }
    }
}

// ===================== exact top-64 among candidates ========================
__global__ __launch_bounds__(128) void topk_refine_kernel(
    const float* __restrict__ scex, const int* __restrict__ idxc,
    const int* __restrict__ ncand,
    int* __restrict__ idxfin, int* __restrict__ candfin)
{
    __shared__ float sv[NCMAX];
    __shared__ int   si[NCMAX];
    __shared__ float rv[128];
    __shared__ int   rc[128];
    __shared__ int   rs[128];
    const int b = blockIdx.x, t = threadIdx.x;
    const int cnt = ncand[b];
    sv[t] = (t < cnt) ? scex[b * NCMAX + t] : -INFINITY;
    si[t] = (t < cnt) ? idxc[b * NCMAX + t] : 0x7fffffff;
    __syncthreads();
    for (int l = 0; l < LL; l++) {
        rv[t] = sv[t]; rc[t] = t; rs[t] = si[t];
        __syncthreads();
        for (int s = 64; s > 0; s >>= 1) {
            if (t < s) {
                if (rv[t + s] > rv[t] || (rv[t + s] == rv[t] && rs[t + s] < rs[t])) {
                    rv[t] = rv[t + s]; rc[t] = rc[t + s]; rs[t] = rs[t + s];
                }
            }
            __syncthreads();
        }
        if (t == 0) {
            idxfin[b * LL + l] = rs[0];
            candfin[b * LL + l] = rc[0];
            sv[rc[0]] = -INFINITY;
        }
        __syncthreads();
    }
}

// ===================== gather -> fp16 K [b,h,l,d] + V^T [b,h,d,l] ===========
__global__ __launch_bounds__(256) void gatherperm_f16(
    const float* __restrict__ kex, const float* __restrict__ vex,
    const int* __restrict__ candf,
    __half* __restrict__ Kh, __half* __restrict__ Vth)
{
    int i = blockIdx.x * 256 + threadIdx.x;
    int d = i & 63;
    int l = (i >> 6) & 63;
    int h = (i >> 12) & 15;
    int b = i >> 16;
    int cp = candf[b * LL + l];
    size_t src = ((size_t)b * NCMAX + cp) * EE + h * 64 + d;
    Kh[i] = __float2half(kex[src]);
    Vth[(((size_t)(b * HH + h)) << 12) + d * 64 + l] = __float2half(vex[src]);
}

// ===================== tensor-core attention (256 rows / 256 thr) ===========
#define ATTN_SMEM (49152 + 69632)

__global__ __launch_bounds__(256) void attn_mma(
    const __half* __restrict__ Qh, const __half* __restrict__ Kh,
    const __half* __restrict__ Vth, float* __restrict__ w_out,
    __half* __restrict__ ctxh)
{
    extern __shared__ __align__(128) char asmem[];
    const uint32_t sb = smem_u32(asmem);
    const uint32_t sQ = sb;
    const uint32_t sK = sb + 32768u;
    const uint32_t sV = sb + 40960u;
    float*  wsm = (float*)(asmem + 49152);
    __half* csm = (__half*)(asmem + 49152);

    const int b = blockIdx.z, h = blockIdx.y, chunk = blockIdx.x;
    const int t = threadIdx.x;
    const int lane = t & 31, wid = t >> 5;
    const int m0 = wid * 32;
    const int qrow = lane >> 2, qk = (lane & 3) * 2;
    const int lrow = lane & 7, phase = lane >> 3;

    const __half* Qg = Qh + ((size_t)(b * SS + chunk * 256)) * EE + h * 64;
    #pragma unroll
    for (int i = 0; i < 8; i++) {
        int idx = t + i * 256;
        int row = idx >> 3, ch = idx & 7;
        uint32_t off = (uint32_t)(row * 128 + ((ch ^ (row & 7)) << 4));
        cp16(sQ + off, Qg + (size_t)row * EE + ch * 8);
    }
    const __half* Kg = Kh + ((size_t)(b * HH + h) << 12);
    const __half* Vg = Vth + ((size_t)(b * HH + h) << 12);
    #pragma unroll
    for (int i = 0; i < 2; i++) {
        int idx = t + i * 256;
        int row = idx >> 3, ch = idx & 7;
        uint32_t off = (uint32_t)(row * 128 + ((ch ^ (row & 7)) << 4));
        cp16(sK + off, Kg + row * 64 + ch * 8);
        cp16(sV + off, Vg + row * 64 + ch * 8);
    }
    CP_COMMIT();
    CP_WAIT0();
    __syncthreads();

    float c[2][8][4];
    #pragma unroll
    for (int mt = 0; mt < 2; mt++)
        #pragma unroll
        for (int nt = 0; nt < 8; nt++)
            #pragma unroll
            for (int q = 0; q < 4; q++) c[mt][nt][q] = 0.f;

    #pragma unroll
    for (int ks = 0; ks < 4; ks++) {
        uint32_t a[2][4];
        #pragma unroll
        for (int mt = 0; mt < 2; mt++) {
            int row = m0 + mt * 16 + (phase & 1) * 8 + lrow;
            int ch  = ks * 2 + (phase >> 1);
            ldm_x4(a[mt], sQ + (uint32_t)(row * 128 + ((ch ^ (row & 7)) << 4)));
        }
        uint32_t bf[4][4];
        #pragma unroll
        for (int ng = 0; ng < 4; ng++) {
            int row = ng * 16 + (phase >> 1) * 8 + lrow;
            int ch  = ks * 2 + (phase & 1);
            ldm_x4(bf[ng], sK + (uint32_t)(row * 128 + ((ch ^ (row & 7)) << 4)));
        }
        #pragma unroll
        for (int nt = 0; nt < 8; nt++) {
            uint32_t b0 = bf[nt >> 1][(nt & 1) * 2];
            uint32_t b1 = bf[nt >> 1][(nt & 1) * 2 + 1];
            MMAF16(c[0][nt], a[0], b0, b1);
            MMAF16(c[1][nt], a[1], b0, b1);
        }
    }

    float inv[2][2];
    #pragma unroll
    for (int mt = 0; mt < 2; mt++) {
        float mx0 = -INFINITY, mx1 = -INFINITY;
        #pragma unroll
        for (int nt = 0; nt < 8; nt++) {
            #pragma unroll
            for (int q = 0; q < 4; q++) c[mt][nt][q] *= 0.125f;
            mx0 = fmaxf(mx0, fmaxf(c[mt][nt][0], c[mt][nt][1]));
            mx1 = fmaxf(mx1, fmaxf(c[mt][nt][2], c[mt][nt][3]));
        }
        mx0 = fmaxf(mx0, __shfl_xor_sync(0xffffffffu, mx0, 1));
        mx0 = fmaxf(mx0, __shfl_xor_sync(0xffffffffu, mx0, 2));
        mx1 = fmaxf(mx1, __shfl_xor_sync(0xffffffffu, mx1, 1));
        mx1 = fmaxf(mx1, __shfl_xor_sync(0xffffffffu, mx1, 2));
        float s0 = 0.f, s1 = 0.f;
        #pragma unroll
        for (int nt = 0; nt < 8; nt++) {
            c[mt][nt][0] = expf(c[mt][nt][0] - mx0);
            c[mt][nt][1] = expf(c[mt][nt][1] - mx0);
            c[mt][nt][2] = expf(c[mt][nt][2] - mx1);
            c[mt][nt][3] = expf(c[mt][nt][3] - mx1);
            s0 += c[mt][nt][0] + c[mt][nt][1];
            s1 += c[mt][nt][2] + c[mt][nt][3];
        }
        s0 += __shfl_xor_sync(0xffffffffu, s0, 1);
        s0 += __shfl_xor_sync(0xffffffffu, s0, 2);
        s1 += __shfl_xor_sync(0xffffffffu, s1, 1);
        s1 += __shfl_xor_sync(0xffffffffu, s1, 2);
        inv[mt][0] = 1.f / s0;
        inv[mt][1] = 1.f / s1;
    }

    uint32_t wh[2][4][4];
    #pragma unroll
    for (int mt = 0; mt < 2; mt++) {
        int r0 = m0 + mt * 16 + qrow;
        #pragma unroll
        for (int nt = 0; nt < 8; nt++) {
            float w0 = c[mt][nt][0] * inv[mt][0];
            float w1 = c[mt][nt][1] * inv[mt][0];
            float w2 = c[mt][nt][2] * inv[mt][1];
            float w3 = c[mt][nt][3] * inv[mt][1];
            int col = nt * 8 + qk;
            wsm[r0 * 68 + col] = w0;       wsm[r0 * 68 + col + 1] = w1;
            wsm[(r0 + 8) * 68 + col] = w2; wsm[(r0 + 8) * 68 + col + 1] = w3;
            int j = nt >> 1;
            if ((nt & 1) == 0) {
                wh[mt][j][0] = packh2(w0, w1);
                wh[mt][j][1] = packh2(w2, w3);
            } else {
                wh[mt][j][2] = packh2(w0, w1);
                wh[mt][j][3] = packh2(w2, w3);
            }
        }
    }

    float o[2][8][4];
    #pragma unroll
    for (int mt = 0; mt < 2; mt++)
        #pragma unroll
        for (int nt = 0; nt < 8; nt++)
            #pragma unroll
            for (int q = 0; q < 4; q++) o[mt][nt][q] = 0.f;

    #pragma unroll
    for (int j = 0; j < 4; j++) {
        uint32_t bf[4][4];
        #pragma unroll
        for (int ng = 0; ng < 4; ng++) {
            int row = ng * 16 + (phase >> 1) * 8 + lrow;
            int ch  = j * 2 + (phase & 1);
            ldm_x4(bf[ng], sV + (uint32_t)(row * 128 + ((ch ^ (row & 7)) << 4)));
        }
        #pragma unroll
        for (int nt = 0; nt < 8; nt++) {
            uint32_t b0 = bf[nt >> 1][(nt & 1) * 2];
            uint32_t b1 = bf[nt >> 1][(nt & 1) * 2 + 1];
            MMAF16(o[0][nt], wh[0][j], b0, b1);
            MMAF16(o[1][nt], wh[1][j], b0, b1);
        }
    }

    __syncthreads();
    float* wb = w_out + ((size_t)((b * HH + h) * SS + chunk * 256)) * LL;
    #pragma unroll
    for (int i = 0; i < 16; i++) {
        int idx = t + i * 256;
        int row = idx >> 4, c4 = idx & 15;
        *(float4*)(wb + row * 64 + c4 * 4) = *(const float4*)(wsm + row * 68 + c4 * 4);
    }
    __syncthreads();

    #pragma unroll
    for (int mt = 0; mt < 2; mt++) {
        int r0 = m0 + mt * 16 + qrow;
        #pragma unroll
        for (int nt = 0; nt < 8; nt++) {
            int col = nt * 8 + qk;
            *(__half2*)(csm + r0 * 72 + col)       = __floats2half2_rn(o[mt][nt][0], o[mt][nt][1]);
            *(__half2*)(csm + (r0 + 8) * 72 + col) = __floats2half2_rn(o[mt][nt][2], o[mt][nt][3]);
        }
    }
    __syncthreads();
    __half* cb = ctxh + ((size_t)(b * SS + chunk * 256)) * EE + h * 64;
    #pragma unroll
    for (int i = 0; i < 8; i++) {
        int idx = t + i * 256;
        int row = idx >> 3, seg = idx & 7;
        *(uint4*)(cb + (size_t)row * EE + seg * 8) = *(const uint4*)(csm + row * 72 + seg * 8);
    }
}

// ===================== launch ===============================================
extern "C" void kernel_launch(void* const* d_in, const int* in_sizes, int n_in,
                              void* d_out, int out_size)
{
    const float* query = (const float*)d_in[0];
    const float* key   = (const float*)d_in[1];
    const float* value = (const float*)d_in[2];
    const float* Wq = (const float*)d_in[3];
    const float* bq = (const float*)d_in[4];
    const float* Wk = (const float*)d_in[5];
    const float* bk = (const float*)d_in[6];
    const float* Wv = (const float*)d_in[7];
    const float* bv = (const float*)d_in[8];
    const float* Wo = (const float*)d_in[9];
    const float* bo = (const float*)d_in[10];

    float* out  = (float*)d_out;
    float* wout = out + MSZ;

    float *pSsq, *pScores, *pKex, *pVex, *pScex;
    __half *pQh, *pAqh, *pAkh, *pWqh, *pWkh, *pWoh, *pWvh, *pVg16, *pKsph, *pVspt;
    int *pIdxc, *pNcand, *pIdxf, *pCandf;
    cudaGetSymbolAddress((void**)&pQh, g_Qh);
    cudaGetSymbolAddress((void**)&pAqh, g_Aqh);
    cudaGetSymbolAddress((void**)&pAkh, g_Akh);
    cudaGetSymbolAddress((void**)&pWqh, g_Wqh);
    cudaGetSymbolAddress((void**)&pWkh, g_Wkh);
    cudaGetSymbolAddress((void**)&pWoh, g_Woh);
    cudaGetSymbolAddress((void**)&pWvh, g_Wvh);
    cudaGetSymbolAddress((void**)&pVg16, g_Vg16);
    cudaGetSymbolAddress((void**)&pSsq, g_ssq);
    cudaGetSymbolAddress((void**)&pScores, g_scores);
    cudaGetSymbolAddress((void**)&pIdxc, g_idxc);
    cudaGetSymbolAddress((void**)&pNcand, g_ncand);
    cudaGetSymbolAddress((void**)&pKex, g_kex);
    cudaGetSymbolAddress((void**)&pVex, g_vex);
    cudaGetSymbolAddress((void**)&pScex, g_scex);
    cudaGetSymbolAddress((void**)&pIdxf, g_idxf);
    cudaGetSymbolAddress((void**)&pCandf, g_candf);
    cudaGetSymbolAddress((void**)&pKsph, g_Ksph);
    cudaGetSymbolAddress((void**)&pVspt, g_Vspt);

    cudaFuncSetAttribute((void*)gemm_f16, cudaFuncAttributeMaxDynamicSharedMemorySize, GEMM_SMEM);
    cudaFuncSetAttribute((void*)gemm_qk, cudaFuncAttributeMaxDynamicSharedMemorySize, GEMM_SMEM);
    cudaFuncSetAttribute((void*)attn_mma, cudaFuncAttributeMaxDynamicSharedMemorySize, ATTN_SMEM);

    const int n4m = (int)(MSZ / 4);
    const int n4w = EE * EE / 4;

    dim3 cw(n4w / 256, 4);
    conv4_f16<<<cw, 256>>>(Wq, pWqh, Wk, pWkh, Wo, pWoh, Wv, pWvh, n4w);
    dim3 ca(n4m / 256, 2);
    conv2_f16<<<ca, 256>>>(query, pAqh, key, pAkh, n4m);
    zero_ssq<<<(MROWS * HH / 4) / 256, 256>>>(pSsq, MROWS * HH / 4);

    // Q GEMM (fp16 out) + K GEMM (ssq atomics), merged
    dim3 qkgrid(8, 256, 2);
    gemm_qk<<<qkgrid, 256, GEMM_SMEM>>>(pAqh, pWqh, bq, pQh,
                                        pAkh, pWkh, bk, pSsq);

    scores_ssq<<<MROWS / 256, 256>>>(pSsq, pScores);
    topk_radix<<<BB, 256>>>(pScores, pIdxc, pNcand);

    // V candidate rows: gather fp16 -> HMMA gemm (M=512) -> vex fp32
    gatherv_f16<<<(BB * NCMAX * EE / 4) / 256, 256>>>(value, pIdxc, pVg16);
    dim3 vgrid(8, 4);
    gemm_f16<<<vgrid, 256, GEMM_SMEM>>>(pVg16, pWvh, bv, pVex);

    // exact fp32 K candidate rows (scores must be exact), exact top-64
    dim3 pgrid(32, BB);
    project_k<<<pgrid, 512>>>(key, Wk, bk, pKex, pIdxc);
    scores_kernel<<<(BB * NCMAX) / 8, 256>>>(pKex, pScex);
    topk_refine_kernel<<<BB, 128>>>(pScex, pIdxc, pNcand, pIdxf, pCandf);
    gatherperm_f16<<<(BB * HH * LL * DD) / 256, 256>>>(pKex, pVex, pCandf, pKsph, pVspt);

    dim3 agrid(SS / 256, HH, BB);
    attn_mma<<<agrid, 256, ATTN_SMEM>>>(pQh, pKsph, pVspt, wout, pAqh);

    dim3 ggrid(8, 256);
    gemm_f16<<<ggrid, 256, GEMM_SMEM>>>(pAqh, pWoh, bo, out);
}